// round 9
// baseline (speedup 1.0000x reference)
#include <cuda_runtime.h>
#include <math.h>

// ---------------- problem constants ----------------
#define BB 16
#define TT 8
#define HW 196
#define HID 32
#define IND 16
#define KBIG 6272       // HID*HW
#define K0 588          // CIN*HW
#define K0PAD 640
#define NBU 3136        // IND*HW
#define NTD 9408        // (IND+HID)*HW

// ---------------- device scratch (no allocs allowed) ----------------
__device__ float g_h[3 * 2 * BB * HID * HW];   // hidden, double buffered
__device__ float g_xT[TT * K0PAD * BB];        // transposed+padded input slices
__device__ float g_poolBU[KBIG * BB];
__device__ float g_poolTD[KBIG * BB];
__device__ float g_bu[BB * NBU];
__device__ float g_td[BB * NTD];
__device__ float g_part[8 * BB * NTD];         // GEMM K-split partials
__device__ float g_gp[2 * BB * 64 * HW];       // gate conv ic-split partials
__device__ float g_cp[2 * BB * 32 * HW];       // cand conv ic-split partials
__device__ float g_fc1o[BB * 100];
// transposed weights (k-major), rebuilt every call
__device__ float g_tdw0T[(size_t)KBIG * NTD];
__device__ float g_tdw1T[(size_t)KBIG * NTD];
__device__ float g_buw1T[(size_t)KBIG * NBU];
__device__ float g_buw2T[(size_t)KBIG * NBU];

// ---------------- f32x2 helpers ----------------
__device__ __forceinline__ unsigned long long pack2(float v) {
    unsigned long long r;
    asm("mov.b64 %0, {%1, %1};" : "=l"(r) : "f"(v));
    return r;
}
__device__ __forceinline__ void fma2(unsigned long long& d, unsigned long long a,
                                     unsigned long long b) {
    asm("fma.rn.f32x2 %0, %1, %2, %0;" : "+l"(d) : "l"(a), "l"(b));
}
__device__ __forceinline__ unsigned long long add2(unsigned long long a,
                                                   unsigned long long b) {
    unsigned long long r;
    asm("add.rn.f32x2 %0, %1, %2;" : "=l"(r) : "l"(a), "l"(b));
    return r;
}
__device__ __forceinline__ float sigm(float a) { return 1.f / (1.f + expf(-a)); }

// ---------------- 32x32 tiled transpose: W (Nout x K) -> WT (K x Nout) ----------------
__global__ void trans_k(const float* __restrict__ W, float* __restrict__ WT,
                        int Nout, int K) {
    __shared__ float t[32][33];
    const int kb = blockIdx.x * 32, nb = blockIdx.y * 32;
    const int tx = threadIdx.x, ty = threadIdx.y;   // 32 x 8
#pragma unroll
    for (int i = 0; i < 32; i += 8)
        t[ty + i][tx] = W[(size_t)(nb + ty + i) * K + kb + tx];
    __syncthreads();
#pragma unroll
    for (int i = 0; i < 32; i += 8)
        WT[(size_t)(kb + ty + i) * Nout + nb + tx] = t[tx][ty + i];
}

// ================= gemmT: out[b][n] = sum_k act[k][b] * WT[k][n] =================
// WT k-major (K x Nout). act (K x 16). Thread owns 2 n-columns, all 16 batch.
// Weights: coalesced LDG.64 straight to regs. Acts: broadcast LDS.128 from a
// double-buffered 128-k slab. Writes K-split partials (grid.y = KS).
__global__ void __launch_bounds__(256) gemmT_k(
    const float* __restrict__ act, const float* __restrict__ WT,
    float* __restrict__ part, int Nout, int KS)
{
    __shared__ float sa[2][128 * 16];              // 2 x 8KB
    const int tid = threadIdx.x;
    const int ks = blockIdx.y;
    const int n0raw = blockIdx.x * 512 + tid * 2;
    const bool act_n = n0raw < Nout;
    const int n0 = act_n ? n0raw : (Nout - 2);     // clamp for safe loads
    const int slabs = KBIG >> 7;                   // 49
    const int s0 = slabs * ks / KS, s1 = slabs * (ks + 1) / KS;

    unsigned long long acc[2][8];
#pragma unroll
    for (int n = 0; n < 2; n++)
#pragma unroll
        for (int p = 0; p < 8; p++) acc[n][p] = 0ull;

    // stage first slab
    {
        const float4* src = (const float4*)act + (size_t)s0 * 512;
        float4 v0 = src[tid], v1 = src[tid + 256];
        int f0 = tid, f1 = tid + 256;
        *(float4*)(&sa[0][(f0 >> 2) * 16 + (f0 & 3) * 4]) = v0;
        *(float4*)(&sa[0][(f1 >> 2) * 16 + (f1 & 3) * 4]) = v1;
    }
    for (int s = s0; s < s1; s++) {
        const int buf = (s - s0) & 1;
        __syncthreads();                           // slab 'buf' ready
        float4 p0, p1;
        const bool more = (s + 1 < s1);
        if (more) {
            const float4* src = (const float4*)act + (size_t)(s + 1) * 512;
            p0 = src[tid]; p1 = src[tid + 256];
        }
        const float* wp = WT + (size_t)(s * 128) * Nout + n0;
        const float* ab = sa[buf];
#pragma unroll 4
        for (int k = 0; k < 128; k++) {
            float2 w = *(const float2*)(wp);
            wp += Nout;
            const ulonglong2* ap = (const ulonglong2*)(ab + k * 16);
            ulonglong2 u0 = ap[0], u1 = ap[1], u2 = ap[2], u3 = ap[3];
            unsigned long long av[8] = {u0.x, u0.y, u1.x, u1.y,
                                        u2.x, u2.y, u3.x, u3.y};
            unsigned long long w0 = pack2(w.x), w1 = pack2(w.y);
#pragma unroll
            for (int p = 0; p < 8; p++) fma2(acc[0][p], w0, av[p]);
#pragma unroll
            for (int p = 0; p < 8; p++) fma2(acc[1][p], w1, av[p]);
        }
        if (more) {
            int f0 = tid, f1 = tid + 256;
            *(float4*)(&sa[buf ^ 1][(f0 >> 2) * 16 + (f0 & 3) * 4]) = p0;
            *(float4*)(&sa[buf ^ 1][(f1 >> 2) * 16 + (f1 & 3) * 4]) = p1;
        }
    }
    if (act_n) {
        float* op = part + (size_t)ks * 16 * Nout + n0;
#pragma unroll
        for (int b = 0; b < 16; b++) {
            unsigned long long v0 = acc[0][b >> 1], v1 = acc[1][b >> 1];
            float f0 = (b & 1) ? __uint_as_float((unsigned)(v0 >> 32))
                               : __uint_as_float((unsigned)v0);
            float f1 = (b & 1) ? __uint_as_float((unsigned)(v1 >> 32))
                               : __uint_as_float((unsigned)v1);
            op[(size_t)b * Nout + 0] = f0;
            op[(size_t)b * Nout + 1] = f1;
        }
    }
}

__global__ void reduceN_k(const float* __restrict__ part,
                          const float* __restrict__ bias,
                          float* __restrict__ out, int Nout, int KS) {
    int i = blockIdx.x * 256 + threadIdx.x;
    if (i >= 16 * Nout) return;
    int n = i % Nout;
    float a = bias[n];
    for (int ks = 0; ks < KS; ks++) a += part[(size_t)ks * 16 * Nout + i];
    out[i] = a;
}

// ================= old GEMM (R6 config) — used only for the small bu0 =================
__global__ void __launch_bounds__(128, 4) gemm_k(
    const float* __restrict__ inT, const float* __restrict__ W,
    const float* __restrict__ bias, float* __restrict__ out,
    int K, int Krows, int Nout)
{
    __shared__ float4 smem4[768 * 4];
    char* smb = (char*)smem4;
    const int tid = threadIdx.x, warp = tid >> 5, lane = tid & 31;
    const int row0 = blockIdx.x * 16 + warp * 4;
    const int slabs = Krows >> 7;

    const float* Wr[4];
#pragma unroll
    for (int r = 0; r < 4; r++) Wr[r] = W + (size_t)(row0 + r) * K + 4 * lane;

    unsigned long long acc[4][8];
#pragma unroll
    for (int r = 0; r < 4; r++)
#pragma unroll
        for (int i = 0; i < 8; i++) acc[r][i] = 0ull;

    for (int tb = 0; tb < slabs; tb += 6) {
        const int ns = min(6, slabs - tb);
        __syncthreads();
        for (int f = tid; f < ns * 512; f += 128) {
            int row = f >> 2, q = f & 3;
            float4 v = ((const float4*)inT)[((size_t)(tb * 128 + row)) * 4 + q];
            unsigned off = (unsigned)((row << 6) | (q << 4)) ^ (((row >> 2) & 7) << 4);
            *(float4*)(smb + off) = v;
        }
        __syncthreads();
        const int kbase = tb * 128;
        float4 wc[4], wn[4];
        {
            const bool ok = (kbase + 4 * lane) < K;
#pragma unroll
            for (int r = 0; r < 4; r++)
                wc[r] = ok ? *(const float4*)(Wr[r] + kbase)
                           : make_float4(0.f, 0.f, 0.f, 0.f);
        }
        for (int s = 0; s < ns; s++) {
            const int knext = kbase + (s + 1) * 128;
            if (s + 1 < ns) {
                const bool ok = (knext + 4 * lane) < K;
#pragma unroll
                for (int r = 0; r < 4; r++)
                    wn[r] = ok ? *(const float4*)(Wr[r] + knext)
                               : make_float4(0.f, 0.f, 0.f, 0.f);
            } else {
#pragma unroll
                for (int r = 0; r < 4; r++) wn[r] = make_float4(0.f, 0.f, 0.f, 0.f);
            }
#pragma unroll
            for (int j = 0; j < 4; j++) {
                const int row = s * 128 + 4 * lane + j;
                const unsigned x = ((row >> 2) & 7) << 4;
                const unsigned b0 = (unsigned)(row << 6);
                ulonglong2 u0 = *(const ulonglong2*)(smb + ((b0 | 0u) ^ x));
                ulonglong2 u1 = *(const ulonglong2*)(smb + ((b0 | 16u) ^ x));
                ulonglong2 u2 = *(const ulonglong2*)(smb + ((b0 | 32u) ^ x));
                ulonglong2 u3 = *(const ulonglong2*)(smb + ((b0 | 48u) ^ x));
                unsigned long long av[8] = {u0.x, u0.y, u1.x, u1.y,
                                            u2.x, u2.y, u3.x, u3.y};
#pragma unroll
                for (int r = 0; r < 4; r++) {
                    unsigned long long wj = pack2(((const float*)&wc[r])[j]);
#pragma unroll
                    for (int i = 0; i < 8; i++) fma2(acc[r][i], wj, av[i]);
                }
            }
#pragma unroll
            for (int r = 0; r < 4; r++) wc[r] = wn[r];
        }
    }
#pragma unroll
    for (int off = 16; off; off >>= 1)
#pragma unroll
        for (int r = 0; r < 4; r++)
#pragma unroll
            for (int i = 0; i < 8; i++)
                acc[r][i] = add2(acc[r][i],
                                 __shfl_xor_sync(0xffffffffu, acc[r][i], off));
    if (lane < 16) {
        const int b = lane, jj = b >> 1;
#pragma unroll
        for (int r = 0; r < 4; r++) {
            unsigned long long v = acc[r][jj];
            float f = (b & 1) ? __uint_as_float((unsigned)(v >> 32))
                              : __uint_as_float((unsigned)v);
            int n = row0 + r;
            out[(size_t)b * Nout + n] = f + bias[n];
        }
    }
}

// ================= conv: ic-split partials (R7 fused form) =================
__global__ void __launch_bounds__(224) gate_part_k(
    const float* __restrict__ bu, const float* __restrict__ h,
    const float* __restrict__ td, const float* __restrict__ Wg,
    float* __restrict__ gp, int has_td)
{
    __shared__ float sc[24 * 256];
    __shared__ float sw[24 * 36];
    const int b = blockIdx.x, grp = blockIdx.y, half = blockIdx.z;
    const int ic0 = half * 24;
    const int tid = threadIdx.x;
    for (int i = tid; i < 24 * 256; i += 224) sc[i] = 0.f;
    for (int i = tid; i < 24 * 36; i += 224) {
        int lic = i / 36, rem = i - lic * 36, q = rem >> 2, o = rem & 3;
        sw[i] = Wg[(grp * 4 + o) * 432 + (ic0 + lic) * 9 + q];
    }
    __syncthreads();
    for (int i = tid; i < 24 * 196; i += 224) {
        int lic = i / 196, p = i - lic * 196, y = p / 14, x = p - y * 14;
        int ic = ic0 + lic;
        float v = (ic < IND) ? bu[((size_t)b * IND + ic) * 196 + p]
                             : h[((size_t)b * HID + (ic - IND)) * 196 + p];
        if (has_td) v += td[((size_t)b * 48 + ic) * 196 + p];
        sc[lic * 256 + (y + 1) * 16 + (x + 1)] = v;
    }
    __syncthreads();
    if (tid < 196) {
        const int p = tid, y = p / 14, x = p - y * 14;
        float4 a = make_float4(0.f, 0.f, 0.f, 0.f);
        const float* cbase = sc + y * 16 + x;
        for (int lic = 0; lic < 24; ++lic) {
            float v[9];
            const float* cb = cbase + lic * 256;
#pragma unroll
            for (int dy = 0; dy < 3; dy++)
#pragma unroll
                for (int dx = 0; dx < 3; dx++) v[dy * 3 + dx] = cb[dy * 16 + dx];
            const float4* wq = (const float4*)(sw + lic * 36);
#pragma unroll
            for (int q = 0; q < 9; q++) {
                float4 w = wq[q];
                a.x += w.x * v[q]; a.y += w.y * v[q];
                a.z += w.z * v[q]; a.w += w.w * v[q];
            }
        }
        float* o = gp + (((size_t)half * 16 + b) * 64 + grp * 4) * 196 + p;
        o[0] = a.x; o[196] = a.y; o[392] = a.z; o[588] = a.w;
    }
}

__global__ void __launch_bounds__(224) cand_part_k(
    const float* __restrict__ bu, const float* __restrict__ h,
    const float* __restrict__ gp, const float* __restrict__ bg,
    const float* __restrict__ Wc, float* __restrict__ cp)
{
    __shared__ float sc[24 * 256];
    __shared__ float sw[24 * 36];
    const int b = blockIdx.x, grp = blockIdx.y, half = blockIdx.z;
    const int ic0 = half * 24;
    const int tid = threadIdx.x;
    for (int i = tid; i < 24 * 256; i += 224) sc[i] = 0.f;
    for (int i = tid; i < 24 * 36; i += 224) {
        int lic = i / 36, rem = i - lic * 36, q = rem >> 2, o = rem & 3;
        sw[i] = Wc[(grp * 4 + o) * 432 + (ic0 + lic) * 9 + q];
    }
    __syncthreads();
    for (int i = tid; i < 24 * 196; i += 224) {
        int lic = i / 196, p = i - lic * 196, y = p / 14, x = p - y * 14;
        int ic = ic0 + lic;
        float v;
        if (ic < IND) {
            v = bu[((size_t)b * IND + ic) * 196 + p];
        } else {
            int c = ic - IND;
            size_t gi = ((size_t)b * 64 + c) * 196 + p;
            float r = sigm(gp[gi] + gp[(size_t)16 * 64 * 196 + gi] + bg[c]);
            v = r * h[((size_t)b * HID + c) * 196 + p];
        }
        sc[lic * 256 + (y + 1) * 16 + (x + 1)] = v;
    }
    __syncthreads();
    if (tid < 196) {
        const int p = tid, y = p / 14, x = p - y * 14;
        float4 a = make_float4(0.f, 0.f, 0.f, 0.f);
        const float* cbase = sc + y * 16 + x;
        for (int lic = 0; lic < 24; ++lic) {
            float v[9];
            const float* cb = cbase + lic * 256;
#pragma unroll
            for (int dy = 0; dy < 3; dy++)
#pragma unroll
                for (int dx = 0; dx < 3; dx++) v[dy * 3 + dx] = cb[dy * 16 + dx];
            const float4* wq = (const float4*)(sw + lic * 36);
#pragma unroll
            for (int q = 0; q < 9; q++) {
                float4 w = wq[q];
                a.x += w.x * v[q]; a.y += w.y * v[q];
                a.z += w.z * v[q]; a.w += w.w * v[q];
            }
        }
        float* o = cp + (((size_t)half * 16 + b) * 32 + grp * 4) * 196 + p;
        o[0] = a.x; o[196] = a.y; o[392] = a.z; o[588] = a.w;
    }
}

__global__ void cand_fin_k(const float* __restrict__ cp,
                           const float* __restrict__ bc,
                           const float* __restrict__ gp,
                           const float* __restrict__ bg,
                           const float* __restrict__ h,
                           float* __restrict__ hnew) {
    int i = blockIdx.x * 256 + threadIdx.x;
    if (i >= 16 * 32 * 196) return;
    int p = i % 196;
    int oc = (i / 196) & 31;
    int b = i / (32 * 196);
    float a = cp[i] + cp[(size_t)16 * 32 * 196 + i] + bc[oc];
    size_t gi = ((size_t)b * 64 + 32 + oc) * 196 + p;
    float z = sigm(gp[gi] + gp[(size_t)16 * 64 * 196 + gi] + bg[32 + oc]);
    float ho = h[i];
    hnew[i] = (1.f - z) * ho + z * tanhf(a);
}

// ---------------- maxpool 3x3 s1 p1 + transpose to (K,16) ----------------
__global__ void pool_k(const float* __restrict__ h, float* __restrict__ outT) {
    int idx = blockIdx.x * 256 + threadIdx.x;
    if (idx >= BB * KBIG) return;
    int b = idx & 15, k = idx >> 4;
    int c = k / 196, p = k - c * 196, y = p / 14, x = p - y * 14;
    const float* hp = h + ((size_t)b * HID + c) * 196;
    int y0 = y > 0 ? y - 1 : 0, y1 = y < 13 ? y + 1 : 13;
    int x0 = x > 0 ? x - 1 : 0, x1 = x < 13 ? x + 1 : 13;
    float m = -3.4e38f;
    for (int yy = y0; yy <= y1; ++yy)
        for (int xx = x0; xx <= x1; ++xx)
            m = fmaxf(m, hp[yy * 14 + xx]);
    outT[(size_t)k * 16 + b] = m;
}

__global__ void xT_k(const float* __restrict__ x, float* __restrict__ xT) {
    int idx = blockIdx.x * 256 + threadIdx.x;
    if (idx >= TT * K0PAD * BB) return;
    int b = idx & 15;
    int r = idx >> 4;
    int k = r % K0PAD, t = r / K0PAD;
    float v = 0.f;
    if (k < K0) v = x[((size_t)b * TT + t) * K0 + k];
    xT[idx] = v;
}

__global__ void zero_k(float* p, int n) {
    int i = blockIdx.x * 256 + threadIdx.x;
    if (i < n) p[i] = 0.f;
}

// ---------------- fc tail ----------------
__global__ void __launch_bounds__(256) fc1_k(const float* __restrict__ h2,
                                             const float* __restrict__ w,
                                             const float* __restrict__ bias,
                                             float* __restrict__ out1) {
    __shared__ float red[256];
    int j = blockIdx.x, tid = threadIdx.x;
    float acc[16];
#pragma unroll
    for (int b = 0; b < 16; b++) acc[b] = 0.f;
    for (int k = tid; k < KBIG; k += 256) {
        float wv = w[(size_t)j * KBIG + k];
#pragma unroll
        for (int b = 0; b < 16; b++)
            acc[b] += wv * fmaxf(h2[(size_t)b * KBIG + k], 0.f);
    }
    for (int b = 0; b < 16; b++) {
        red[tid] = acc[b];
        __syncthreads();
        for (int sft = 128; sft; sft >>= 1) {
            if (tid < sft) red[tid] += red[tid + sft];
            __syncthreads();
        }
        if (tid == 0) out1[b * 100 + j] = fmaxf(red[0] + bias[j], 0.f);
        __syncthreads();
    }
}

__global__ void fc2_k(const float* __restrict__ p, const float* __restrict__ w,
                      const float* __restrict__ bias, float* __restrict__ out) {
    int t = threadIdx.x;
    if (t < 160) {
        int b = t / 10, j = t - b * 10;
        float a = bias[j];
        for (int k = 0; k < 100; k++) a += p[b * 100 + k] * w[j * 100 + k];
        out[b * 10 + j] = a;
    }
}

// ---------------- host orchestration ----------------
extern "C" void kernel_launch(void* const* d_in, const int* in_sizes, int n_in,
                              void* d_out, int out_size) {
    const float* x     = (const float*)d_in[0];
    const float* Wg    = (const float*)d_in[1];
    const float* bg    = (const float*)d_in[2];
    const float* Wc    = (const float*)d_in[3];
    const float* bc    = (const float*)d_in[4];
    const float* bu_w0 = (const float*)d_in[5];
    const float* bu_b0 = (const float*)d_in[6];
    const float* bu_w1 = (const float*)d_in[7];
    const float* bu_b1 = (const float*)d_in[8];
    const float* bu_w2 = (const float*)d_in[9];
    const float* bu_b2 = (const float*)d_in[10];
    const float* td_w0 = (const float*)d_in[11];
    const float* td_b0 = (const float*)d_in[12];
    const float* td_w1 = (const float*)d_in[13];
    const float* td_b1 = (const float*)d_in[14];
    const float* fc1_w = (const float*)d_in[15];
    const float* fc1_b = (const float*)d_in[16];
    const float* fc2_w = (const float*)d_in[17];
    const float* fc2_b = (const float*)d_in[18];
    float* out = (float*)d_out;

    float *hbuf, *xT, *pBU, *pTD, *bu, *td, *part, *gp, *cp, *fc1o;
    float *tdw0T, *tdw1T, *buw1T, *buw2T;
    cudaGetSymbolAddress((void**)&hbuf,  g_h);
    cudaGetSymbolAddress((void**)&xT,    g_xT);
    cudaGetSymbolAddress((void**)&pBU,   g_poolBU);
    cudaGetSymbolAddress((void**)&pTD,   g_poolTD);
    cudaGetSymbolAddress((void**)&bu,    g_bu);
    cudaGetSymbolAddress((void**)&td,    g_td);
    cudaGetSymbolAddress((void**)&part,  g_part);
    cudaGetSymbolAddress((void**)&gp,    g_gp);
    cudaGetSymbolAddress((void**)&cp,    g_cp);
    cudaGetSymbolAddress((void**)&fc1o,  g_fc1o);
    cudaGetSymbolAddress((void**)&tdw0T, g_tdw0T);
    cudaGetSymbolAddress((void**)&tdw1T, g_tdw1T);
    cudaGetSymbolAddress((void**)&buw1T, g_buw1T);
    cudaGetSymbolAddress((void**)&buw2T, g_buw2T);

    const int hTot = 3 * 2 * BB * HID * HW;
    zero_k<<<(hTot + 255) / 256, 256>>>(hbuf, hTot);
    xT_k<<<(TT * K0PAD * BB + 255) / 256, 256>>>(x, xT);

    // per-call weight transposes (k-major)
    {
        dim3 tb(32, 8);
        trans_k<<<dim3(KBIG / 32, NTD / 32), tb>>>(td_w0, tdw0T, NTD, KBIG);
        trans_k<<<dim3(KBIG / 32, NTD / 32), tb>>>(td_w1, tdw1T, NTD, KBIG);
        trans_k<<<dim3(KBIG / 32, NBU / 32), tb>>>(bu_w1, buw1T, NBU, KBIG);
        trans_k<<<dim3(KBIG / 32, NBU / 32), tb>>>(bu_w2, buw2T, NBU, KBIG);
    }

    int cur[3] = {0, 0, 0};
    const size_t HSZ = (size_t)BB * HID * HW;
    const float* WgN[3] = {Wg, Wg + 27648, Wg + 2 * 27648};
    const float* bgN[3] = {bg, bg + 64, bg + 128};
    const float* WcN[3] = {Wc, Wc + 13824, Wc + 2 * 13824};
    const float* bcN[3] = {bc, bc + 32, bc + 64};
    const float* buB[3] = {bu_b0, bu_b1, bu_b2};
    const float* buWT[3] = {0, buw1T, buw2T};

    const int KS_TD = 8, KS_BU = 21;
    dim3 gateGrid(16, 16, 2), candGrid(16, 8, 2);
    const int poolBlocks = (BB * KBIG + 255) / 256;
    const int cFinB = (16 * 32 * 196 + 255) / 256;
    const int tdGx = (NTD + 511) / 512, buGx = (NBU + 511) / 512;
    const int tdRed = (16 * NTD + 255) / 256, buRed = (16 * NBU + 255) / 256;
#define HPTR(n, p) (hbuf + ((size_t)(n) * 2 + (p)) * HSZ)

    for (int t = 0; t < TT + 2; t++) {
        // ---- node 0 (runs t < T) ----
        if (t < TT) {
            int hastd = (t >= 2);
            if (hastd) {
                pool_k<<<poolBlocks, 256>>>(HPTR(1, cur[1]), pTD);
                gemmT_k<<<dim3(tdGx, KS_TD), 256>>>(pTD, tdw0T, part, NTD, KS_TD);
                reduceN_k<<<tdRed, 256>>>(part, td_b0, td, NTD, KS_TD);
            }
            gemm_k<<<NBU / 16, 128>>>(xT + (size_t)t * K0PAD * 16, bu_w0, bu_b0,
                                      bu, K0, K0PAD, NBU);
            gate_part_k<<<gateGrid, 224>>>(bu, HPTR(0, cur[0]), td, WgN[0], gp, hastd);
            cand_part_k<<<candGrid, 224>>>(bu, HPTR(0, cur[0]), gp, bgN[0], WcN[0], cp);
            cand_fin_k<<<cFinB, 256>>>(cp, bcN[0], gp, bgN[0], HPTR(0, cur[0]),
                                       HPTR(0, 1 - cur[0]));
            cur[0] ^= 1;
        }
        // ---- nodes 1, 2 (run t >= 1) ----
        if (t >= 1) {
            for (int node = 1; node < 3; node++) {
                pool_k<<<poolBlocks, 256>>>(HPTR(node - 1, cur[node - 1]), pBU);
                gemmT_k<<<dim3(buGx, KS_BU), 256>>>(pBU, buWT[node], part, NBU, KS_BU);
                reduceN_k<<<buRed, 256>>>(part, buB[node], bu, NBU, KS_BU);
                int hastd = (node == 1 && t >= 2);
                if (hastd) {
                    pool_k<<<poolBlocks, 256>>>(HPTR(2, cur[2]), pTD);
                    gemmT_k<<<dim3(tdGx, KS_TD), 256>>>(pTD, tdw1T, part, NTD, KS_TD);
                    reduceN_k<<<tdRed, 256>>>(part, td_b1, td, NTD, KS_TD);
                }
                gate_part_k<<<gateGrid, 224>>>(bu, HPTR(node, cur[node]), td,
                                               WgN[node], gp, hastd);
                cand_part_k<<<candGrid, 224>>>(bu, HPTR(node, cur[node]), gp,
                                               bgN[node], WcN[node], cp);
                cand_fin_k<<<cFinB, 256>>>(cp, bcN[node], gp, bgN[node],
                                           HPTR(node, cur[node]),
                                           HPTR(node, 1 - cur[node]));
                cur[node] ^= 1;
            }
        }
    }
    fc1_k<<<100, 256>>>(HPTR(2, cur[2]), fc1_w, fc1_b, fc1o);
    fc2_k<<<1, 192>>>(fc1o, fc2_w, fc2_b, out);
#undef HPTR
}

// round 10
// speedup vs baseline: 1.5744x; 1.5744x over previous
#include <cuda_runtime.h>
#include <math.h>

// ---------------- problem constants ----------------
#define BB 16
#define TT 8
#define HW 196
#define HID 32
#define IND 16
#define KBIG 6272       // HID*HW
#define K0 588          // CIN*HW
#define K0PAD 640
#define NBU 3136        // IND*HW
#define NTD 9408        // (IND+HID)*HW
#define KS_TD 16
#define KS_BU 42

// ---------------- device scratch (no allocs allowed) ----------------
__device__ float g_h[3 * 2 * BB * HID * HW];   // hidden, double buffered
__device__ float g_xT[TT * K0PAD * BB];        // transposed+padded input slices
__device__ float g_poolBU[KBIG * BB];
__device__ float g_poolTD[KBIG * BB];
__device__ float g_bu[BB * NBU];
__device__ float g_td[BB * NTD];
__device__ float g_part[KS_TD * BB * NTD];     // GEMM K-split partials
__device__ float g_gp[2 * BB * 64 * HW];       // gate conv ic-split partials
__device__ float g_cp[2 * BB * 32 * HW];       // cand conv ic-split partials
__device__ float g_fc1o[BB * 100];
// transposed weights (k-major), rebuilt every call
__device__ float g_tdw0T[(size_t)KBIG * NTD];
__device__ float g_tdw1T[(size_t)KBIG * NTD];
__device__ float g_buw1T[(size_t)KBIG * NBU];
__device__ float g_buw2T[(size_t)KBIG * NBU];

// ---------------- f32x2 helpers ----------------
__device__ __forceinline__ unsigned long long pack2(float v) {
    unsigned long long r;
    asm("mov.b64 %0, {%1, %1};" : "=l"(r) : "f"(v));
    return r;
}
__device__ __forceinline__ void fma2(unsigned long long& d, unsigned long long a,
                                     unsigned long long b) {
    asm("fma.rn.f32x2 %0, %1, %2, %0;" : "+l"(d) : "l"(a), "l"(b));
}
__device__ __forceinline__ unsigned long long add2(unsigned long long a,
                                                   unsigned long long b) {
    unsigned long long r;
    asm("add.rn.f32x2 %0, %1, %2;" : "=l"(r) : "l"(a), "l"(b));
    return r;
}
__device__ __forceinline__ float sigm(float a) { return 1.f / (1.f + expf(-a)); }

// ---------------- 32x32 tiled transpose: W (Nout x K) -> WT (K x Nout) ----------------
__global__ void trans_k(const float* __restrict__ W, float* __restrict__ WT,
                        int Nout, int K) {
    __shared__ float t[32][33];
    const int kb = blockIdx.x * 32, nb = blockIdx.y * 32;
    const int tx = threadIdx.x, ty = threadIdx.y;   // 32 x 8
#pragma unroll
    for (int i = 0; i < 32; i += 8)
        t[ty + i][tx] = W[(size_t)(nb + ty + i) * K + kb + tx];
    __syncthreads();
#pragma unroll
    for (int i = 0; i < 32; i += 8)
        WT[(size_t)(kb + ty + i) * Nout + nb + tx] = t[tx][ty + i];
}

// ================= gemmT v2: part[ks][b][n] = sum_{k in range} act[k][b]*WT[k][n] =================
// Thread owns 2 n-cols; weights stream via 8-deep double-buffered register
// prefetch (8 indep LDG.64 in flight); acts staged once (<=4 slabs, 32KB) and
// read as broadcast LDS.128. grid=(ceil(Nout/512), KS), 2 CTAs/SM.
__global__ void __launch_bounds__(256) gemmT_k(
    const float* __restrict__ act, const float* __restrict__ WT,
    float* __restrict__ part, int Nout, int KS)
{
    __shared__ float sa[4 * 128 * 16];             // 32KB max staging
    const int tid = threadIdx.x;
    const int ks = blockIdx.y;
    const int n0raw = blockIdx.x * 512 + tid * 2;
    const bool act_n = n0raw < Nout;
    const int n0 = act_n ? n0raw : (Nout - 2);
    const int slabs = KBIG >> 7;                   // 49
    const int s0 = slabs * ks / KS, s1 = slabs * (ks + 1) / KS;
    const int ns = s1 - s0;                        // 1..4 slabs
    const int kn = ns * 128;                       // multiple of 128

    // stage this block's K range (coalesced float4)
    {
        const float4* src = (const float4*)act + (size_t)s0 * 512;
        for (int f = tid; f < ns * 512; f += 256) {
            float4 v = src[f];
            *(float4*)(&sa[(f >> 2) * 16 + (f & 3) * 4]) = v;
        }
    }

    unsigned long long acc[2][8];
#pragma unroll
    for (int n = 0; n < 2; n++)
#pragma unroll
        for (int p = 0; p < 8; p++) acc[n][p] = 0ull;

    const float* wp = WT + (size_t)(s0 * 128) * Nout + n0;
    float2 wb[2][8];
#pragma unroll
    for (int u = 0; u < 8; u++)
        wb[0][u] = *(const float2*)(wp + (size_t)u * Nout);

    __syncthreads();                               // acts ready

    for (int k0 = 0; k0 < kn; k0 += 8) {
        const int cur = (k0 >> 3) & 1;
        const float* wpn = wp + (size_t)8 * Nout;
        if (k0 + 8 < kn) {
#pragma unroll
            for (int u = 0; u < 8; u++)
                wb[cur ^ 1][u] = *(const float2*)(wpn + (size_t)u * Nout);
        }
#pragma unroll
        for (int u = 0; u < 8; u++) {
            const ulonglong2* ap = (const ulonglong2*)(sa + (k0 + u) * 16);
            ulonglong2 u0 = ap[0], u1 = ap[1], u2 = ap[2], u3 = ap[3];
            unsigned long long av[8] = {u0.x, u0.y, u1.x, u1.y,
                                        u2.x, u2.y, u3.x, u3.y};
            unsigned long long w0 = pack2(wb[cur][u].x);
            unsigned long long w1 = pack2(wb[cur][u].y);
#pragma unroll
            for (int p = 0; p < 8; p++) fma2(acc[0][p], w0, av[p]);
#pragma unroll
            for (int p = 0; p < 8; p++) fma2(acc[1][p], w1, av[p]);
        }
        wp = wpn;
    }
    if (act_n) {
        float* op = part + (size_t)ks * 16 * Nout + n0;
#pragma unroll
        for (int b = 0; b < 16; b++) {
            unsigned long long v0 = acc[0][b >> 1], v1 = acc[1][b >> 1];
            float f0 = (b & 1) ? __uint_as_float((unsigned)(v0 >> 32))
                               : __uint_as_float((unsigned)v0);
            float f1 = (b & 1) ? __uint_as_float((unsigned)(v1 >> 32))
                               : __uint_as_float((unsigned)v1);
            op[(size_t)b * Nout + 0] = f0;
            op[(size_t)b * Nout + 1] = f1;
        }
    }
}

__global__ void reduceN_k(const float* __restrict__ part,
                          const float* __restrict__ bias,
                          float* __restrict__ out, int Nout, int KS) {
    int i = blockIdx.x * 256 + threadIdx.x;
    if (i >= 16 * Nout) return;
    int n = i % Nout;
    float a = bias[n];
    for (int ks = 0; ks < KS; ks++) a += part[(size_t)ks * 16 * Nout + i];
    out[i] = a;
}

// ================= old GEMM (R6 config) — only for the small bu0 =================
__global__ void __launch_bounds__(128, 4) gemm_k(
    const float* __restrict__ inT, const float* __restrict__ W,
    const float* __restrict__ bias, float* __restrict__ out,
    int K, int Krows, int Nout)
{
    __shared__ float4 smem4[768 * 4];
    char* smb = (char*)smem4;
    const int tid = threadIdx.x, warp = tid >> 5, lane = tid & 31;
    const int row0 = blockIdx.x * 16 + warp * 4;
    const int slabs = Krows >> 7;

    const float* Wr[4];
#pragma unroll
    for (int r = 0; r < 4; r++) Wr[r] = W + (size_t)(row0 + r) * K + 4 * lane;

    unsigned long long acc[4][8];
#pragma unroll
    for (int r = 0; r < 4; r++)
#pragma unroll
        for (int i = 0; i < 8; i++) acc[r][i] = 0ull;

    for (int tb = 0; tb < slabs; tb += 6) {
        const int ns = min(6, slabs - tb);
        __syncthreads();
        for (int f = tid; f < ns * 512; f += 128) {
            int row = f >> 2, q = f & 3;
            float4 v = ((const float4*)inT)[((size_t)(tb * 128 + row)) * 4 + q];
            unsigned off = (unsigned)((row << 6) | (q << 4)) ^ (((row >> 2) & 7) << 4);
            *(float4*)(smb + off) = v;
        }
        __syncthreads();
        const int kbase = tb * 128;
        float4 wc[4], wn[4];
        {
            const bool ok = (kbase + 4 * lane) < K;
#pragma unroll
            for (int r = 0; r < 4; r++)
                wc[r] = ok ? *(const float4*)(Wr[r] + kbase)
                           : make_float4(0.f, 0.f, 0.f, 0.f);
        }
        for (int s = 0; s < ns; s++) {
            const int knext = kbase + (s + 1) * 128;
            if (s + 1 < ns) {
                const bool ok = (knext + 4 * lane) < K;
#pragma unroll
                for (int r = 0; r < 4; r++)
                    wn[r] = ok ? *(const float4*)(Wr[r] + knext)
                               : make_float4(0.f, 0.f, 0.f, 0.f);
            } else {
#pragma unroll
                for (int r = 0; r < 4; r++) wn[r] = make_float4(0.f, 0.f, 0.f, 0.f);
            }
#pragma unroll
            for (int j = 0; j < 4; j++) {
                const int row = s * 128 + 4 * lane + j;
                const unsigned x = ((row >> 2) & 7) << 4;
                const unsigned b0 = (unsigned)(row << 6);
                ulonglong2 u0 = *(const ulonglong2*)(smb + ((b0 | 0u) ^ x));
                ulonglong2 u1 = *(const ulonglong2*)(smb + ((b0 | 16u) ^ x));
                ulonglong2 u2 = *(const ulonglong2*)(smb + ((b0 | 32u) ^ x));
                ulonglong2 u3 = *(const ulonglong2*)(smb + ((b0 | 48u) ^ x));
                unsigned long long av[8] = {u0.x, u0.y, u1.x, u1.y,
                                            u2.x, u2.y, u3.x, u3.y};
#pragma unroll
                for (int r = 0; r < 4; r++) {
                    unsigned long long wj = pack2(((const float*)&wc[r])[j]);
#pragma unroll
                    for (int i = 0; i < 8; i++) fma2(acc[r][i], wj, av[i]);
                }
            }
#pragma unroll
            for (int r = 0; r < 4; r++) wc[r] = wn[r];
        }
    }
#pragma unroll
    for (int off = 16; off; off >>= 1)
#pragma unroll
        for (int r = 0; r < 4; r++)
#pragma unroll
            for (int i = 0; i < 8; i++)
                acc[r][i] = add2(acc[r][i],
                                 __shfl_xor_sync(0xffffffffu, acc[r][i], off));
    if (lane < 16) {
        const int b = lane, jj = b >> 1;
#pragma unroll
        for (int r = 0; r < 4; r++) {
            unsigned long long v = acc[r][jj];
            float f = (b & 1) ? __uint_as_float((unsigned)(v >> 32))
                              : __uint_as_float((unsigned)v);
            int n = row0 + r;
            out[(size_t)b * Nout + n] = f + bias[n];
        }
    }
}

// ================= conv: ic-split partials (fused form) =================
__global__ void __launch_bounds__(224) gate_part_k(
    const float* __restrict__ bu, const float* __restrict__ h,
    const float* __restrict__ td, const float* __restrict__ Wg,
    float* __restrict__ gp, int has_td)
{
    __shared__ float sc[24 * 256];
    __shared__ float sw[24 * 36];
    const int b = blockIdx.x, grp = blockIdx.y, half = blockIdx.z;
    const int ic0 = half * 24;
    const int tid = threadIdx.x;
    for (int i = tid; i < 24 * 256; i += 224) sc[i] = 0.f;
    for (int i = tid; i < 24 * 36; i += 224) {
        int lic = i / 36, rem = i - lic * 36, q = rem >> 2, o = rem & 3;
        sw[i] = Wg[(grp * 4 + o) * 432 + (ic0 + lic) * 9 + q];
    }
    __syncthreads();
    for (int i = tid; i < 24 * 196; i += 224) {
        int lic = i / 196, p = i - lic * 196, y = p / 14, x = p - y * 14;
        int ic = ic0 + lic;
        float v = (ic < IND) ? bu[((size_t)b * IND + ic) * 196 + p]
                             : h[((size_t)b * HID + (ic - IND)) * 196 + p];
        if (has_td) v += td[((size_t)b * 48 + ic) * 196 + p];
        sc[lic * 256 + (y + 1) * 16 + (x + 1)] = v;
    }
    __syncthreads();
    if (tid < 196) {
        const int p = tid, y = p / 14, x = p - y * 14;
        float4 a = make_float4(0.f, 0.f, 0.f, 0.f);
        const float* cbase = sc + y * 16 + x;
        for (int lic = 0; lic < 24; ++lic) {
            float v[9];
            const float* cb = cbase + lic * 256;
#pragma unroll
            for (int dy = 0; dy < 3; dy++)
#pragma unroll
                for (int dx = 0; dx < 3; dx++) v[dy * 3 + dx] = cb[dy * 16 + dx];
            const float4* wq = (const float4*)(sw + lic * 36);
#pragma unroll
            for (int q = 0; q < 9; q++) {
                float4 w = wq[q];
                a.x += w.x * v[q]; a.y += w.y * v[q];
                a.z += w.z * v[q]; a.w += w.w * v[q];
            }
        }
        float* o = gp + (((size_t)half * 16 + b) * 64 + grp * 4) * 196 + p;
        o[0] = a.x; o[196] = a.y; o[392] = a.z; o[588] = a.w;
    }
}

__global__ void __launch_bounds__(224) cand_part_k(
    const float* __restrict__ bu, const float* __restrict__ h,
    const float* __restrict__ gp, const float* __restrict__ bg,
    const float* __restrict__ Wc, float* __restrict__ cp)
{
    __shared__ float sc[24 * 256];
    __shared__ float sw[24 * 36];
    const int b = blockIdx.x, grp = blockIdx.y, half = blockIdx.z;
    const int ic0 = half * 24;
    const int tid = threadIdx.x;
    for (int i = tid; i < 24 * 256; i += 224) sc[i] = 0.f;
    for (int i = tid; i < 24 * 36; i += 224) {
        int lic = i / 36, rem = i - lic * 36, q = rem >> 2, o = rem & 3;
        sw[i] = Wc[(grp * 4 + o) * 432 + (ic0 + lic) * 9 + q];
    }
    __syncthreads();
    for (int i = tid; i < 24 * 196; i += 224) {
        int lic = i / 196, p = i - lic * 196, y = p / 14, x = p - y * 14;
        int ic = ic0 + lic;
        float v;
        if (ic < IND) {
            v = bu[((size_t)b * IND + ic) * 196 + p];
        } else {
            int c = ic - IND;
            size_t gi = ((size_t)b * 64 + c) * 196 + p;
            float r = sigm(gp[gi] + gp[(size_t)16 * 64 * 196 + gi] + bg[c]);
            v = r * h[((size_t)b * HID + c) * 196 + p];
        }
        sc[lic * 256 + (y + 1) * 16 + (x + 1)] = v;
    }
    __syncthreads();
    if (tid < 196) {
        const int p = tid, y = p / 14, x = p - y * 14;
        float4 a = make_float4(0.f, 0.f, 0.f, 0.f);
        const float* cbase = sc + y * 16 + x;
        for (int lic = 0; lic < 24; ++lic) {
            float v[9];
            const float* cb = cbase + lic * 256;
#pragma unroll
            for (int dy = 0; dy < 3; dy++)
#pragma unroll
                for (int dx = 0; dx < 3; dx++) v[dy * 3 + dx] = cb[dy * 16 + dx];
            const float4* wq = (const float4*)(sw + lic * 36);
#pragma unroll
            for (int q = 0; q < 9; q++) {
                float4 w = wq[q];
                a.x += w.x * v[q]; a.y += w.y * v[q];
                a.z += w.z * v[q]; a.w += w.w * v[q];
            }
        }
        float* o = cp + (((size_t)half * 16 + b) * 32 + grp * 4) * 196 + p;
        o[0] = a.x; o[196] = a.y; o[392] = a.z; o[588] = a.w;
    }
}

__global__ void cand_fin_k(const float* __restrict__ cp,
                           const float* __restrict__ bc,
                           const float* __restrict__ gp,
                           const float* __restrict__ bg,
                           const float* __restrict__ h,
                           float* __restrict__ hnew) {
    int i = blockIdx.x * 256 + threadIdx.x;
    if (i >= 16 * 32 * 196) return;
    int p = i % 196;
    int oc = (i / 196) & 31;
    int b = i / (32 * 196);
    float a = cp[i] + cp[(size_t)16 * 32 * 196 + i] + bc[oc];
    size_t gi = ((size_t)b * 64 + 32 + oc) * 196 + p;
    float z = sigm(gp[gi] + gp[(size_t)16 * 64 * 196 + gi] + bg[32 + oc]);
    float ho = h[i];
    hnew[i] = (1.f - z) * ho + z * tanhf(a);
}

// ---------------- maxpool 3x3 s1 p1 + transpose to (K,16) ----------------
__global__ void pool_k(const float* __restrict__ h, float* __restrict__ outT) {
    int idx = blockIdx.x * 256 + threadIdx.x;
    if (idx >= BB * KBIG) return;
    int b = idx & 15, k = idx >> 4;
    int c = k / 196, p = k - c * 196, y = p / 14, x = p - y * 14;
    const float* hp = h + ((size_t)b * HID + c) * 196;
    int y0 = y > 0 ? y - 1 : 0, y1 = y < 13 ? y + 1 : 13;
    int x0 = x > 0 ? x - 1 : 0, x1 = x < 13 ? x + 1 : 13;
    float m = -3.4e38f;
    for (int yy = y0; yy <= y1; ++yy)
        for (int xx = x0; xx <= x1; ++xx)
            m = fmaxf(m, hp[yy * 14 + xx]);
    outT[(size_t)k * 16 + b] = m;
}

__global__ void xT_k(const float* __restrict__ x, float* __restrict__ xT) {
    int idx = blockIdx.x * 256 + threadIdx.x;
    if (idx >= TT * K0PAD * BB) return;
    int b = idx & 15;
    int r = idx >> 4;
    int k = r % K0PAD, t = r / K0PAD;
    float v = 0.f;
    if (k < K0) v = x[((size_t)b * TT + t) * K0 + k];
    xT[idx] = v;
}

__global__ void zero_k(float* p, int n) {
    int i = blockIdx.x * 256 + threadIdx.x;
    if (i < n) p[i] = 0.f;
}

// ---------------- fc tail ----------------
__global__ void __launch_bounds__(256) fc1_k(const float* __restrict__ h2,
                                             const float* __restrict__ w,
                                             const float* __restrict__ bias,
                                             float* __restrict__ out1) {
    __shared__ float red[256];
    int j = blockIdx.x, tid = threadIdx.x;
    float acc[16];
#pragma unroll
    for (int b = 0; b < 16; b++) acc[b] = 0.f;
    for (int k = tid; k < KBIG; k += 256) {
        float wv = w[(size_t)j * KBIG + k];
#pragma unroll
        for (int b = 0; b < 16; b++)
            acc[b] += wv * fmaxf(h2[(size_t)b * KBIG + k], 0.f);
    }
    for (int b = 0; b < 16; b++) {
        red[tid] = acc[b];
        __syncthreads();
        for (int sft = 128; sft; sft >>= 1) {
            if (tid < sft) red[tid] += red[tid + sft];
            __syncthreads();
        }
        if (tid == 0) out1[b * 100 + j] = fmaxf(red[0] + bias[j], 0.f);
        __syncthreads();
    }
}

__global__ void fc2_k(const float* __restrict__ p, const float* __restrict__ w,
                      const float* __restrict__ bias, float* __restrict__ out) {
    int t = threadIdx.x;
    if (t < 160) {
        int b = t / 10, j = t - b * 10;
        float a = bias[j];
        for (int k = 0; k < 100; k++) a += p[b * 100 + k] * w[j * 100 + k];
        out[b * 10 + j] = a;
    }
}

// ---------------- host orchestration ----------------
extern "C" void kernel_launch(void* const* d_in, const int* in_sizes, int n_in,
                              void* d_out, int out_size) {
    const float* x     = (const float*)d_in[0];
    const float* Wg    = (const float*)d_in[1];
    const float* bg    = (const float*)d_in[2];
    const float* Wc    = (const float*)d_in[3];
    const float* bc    = (const float*)d_in[4];
    const float* bu_w0 = (const float*)d_in[5];
    const float* bu_b0 = (const float*)d_in[6];
    const float* bu_w1 = (const float*)d_in[7];
    const float* bu_b1 = (const float*)d_in[8];
    const float* bu_w2 = (const float*)d_in[9];
    const float* bu_b2 = (const float*)d_in[10];
    const float* td_w0 = (const float*)d_in[11];
    const float* td_b0 = (const float*)d_in[12];
    const float* td_w1 = (const float*)d_in[13];
    const float* td_b1 = (const float*)d_in[14];
    const float* fc1_w = (const float*)d_in[15];
    const float* fc1_b = (const float*)d_in[16];
    const float* fc2_w = (const float*)d_in[17];
    const float* fc2_b = (const float*)d_in[18];
    float* out = (float*)d_out;

    float *hbuf, *xT, *pBU, *pTD, *bu, *td, *part, *gp, *cp, *fc1o;
    float *tdw0T, *tdw1T, *buw1T, *buw2T;
    cudaGetSymbolAddress((void**)&hbuf,  g_h);
    cudaGetSymbolAddress((void**)&xT,    g_xT);
    cudaGetSymbolAddress((void**)&pBU,   g_poolBU);
    cudaGetSymbolAddress((void**)&pTD,   g_poolTD);
    cudaGetSymbolAddress((void**)&bu,    g_bu);
    cudaGetSymbolAddress((void**)&td,    g_td);
    cudaGetSymbolAddress((void**)&part,  g_part);
    cudaGetSymbolAddress((void**)&gp,    g_gp);
    cudaGetSymbolAddress((void**)&cp,    g_cp);
    cudaGetSymbolAddress((void**)&fc1o,  g_fc1o);
    cudaGetSymbolAddress((void**)&tdw0T, g_tdw0T);
    cudaGetSymbolAddress((void**)&tdw1T, g_tdw1T);
    cudaGetSymbolAddress((void**)&buw1T, g_buw1T);
    cudaGetSymbolAddress((void**)&buw2T, g_buw2T);

    const int hTot = 3 * 2 * BB * HID * HW;
    zero_k<<<(hTot + 255) / 256, 256>>>(hbuf, hTot);
    xT_k<<<(TT * K0PAD * BB + 255) / 256, 256>>>(x, xT);

    // per-call weight transposes (k-major)
    {
        dim3 tb(32, 8);
        trans_k<<<dim3(KBIG / 32, NTD / 32), tb>>>(td_w0, tdw0T, NTD, KBIG);
        trans_k<<<dim3(KBIG / 32, NTD / 32), tb>>>(td_w1, tdw1T, NTD, KBIG);
        trans_k<<<dim3(KBIG / 32, NBU / 32), tb>>>(bu_w1, buw1T, NBU, KBIG);
        trans_k<<<dim3(KBIG / 32, NBU / 32), tb>>>(bu_w2, buw2T, NBU, KBIG);
    }

    int cur[3] = {0, 0, 0};
    const size_t HSZ = (size_t)BB * HID * HW;
    const float* WgN[3] = {Wg, Wg + 27648, Wg + 2 * 27648};
    const float* bgN[3] = {bg, bg + 64, bg + 128};
    const float* WcN[3] = {Wc, Wc + 13824, Wc + 2 * 13824};
    const float* bcN[3] = {bc, bc + 32, bc + 64};
    const float* buB[3] = {bu_b0, bu_b1, bu_b2};
    const float* buWT[3] = {0, buw1T, buw2T};

    dim3 gateGrid(16, 16, 2), candGrid(16, 8, 2);
    const int poolBlocks = (BB * KBIG + 255) / 256;
    const int cFinB = (16 * 32 * 196 + 255) / 256;
    const int tdGx = (NTD + 511) / 512, buGx = (NBU + 511) / 512;
    const int tdRed = (16 * NTD + 255) / 256, buRed = (16 * NBU + 255) / 256;
#define HPTR(n, p) (hbuf + ((size_t)(n) * 2 + (p)) * HSZ)

    for (int t = 0; t < TT + 2; t++) {
        // ---- node 0 (runs t < T) ----
        if (t < TT) {
            int hastd = (t >= 2);
            if (hastd) {
                pool_k<<<poolBlocks, 256>>>(HPTR(1, cur[1]), pTD);
                gemmT_k<<<dim3(tdGx, KS_TD), 256>>>(pTD, tdw0T, part, NTD, KS_TD);
                reduceN_k<<<tdRed, 256>>>(part, td_b0, td, NTD, KS_TD);
            }
            gemm_k<<<NBU / 16, 128>>>(xT + (size_t)t * K0PAD * 16, bu_w0, bu_b0,
                                      bu, K0, K0PAD, NBU);
            gate_part_k<<<gateGrid, 224>>>(bu, HPTR(0, cur[0]), td, WgN[0], gp, hastd);
            cand_part_k<<<candGrid, 224>>>(bu, HPTR(0, cur[0]), gp, bgN[0], WcN[0], cp);
            cand_fin_k<<<cFinB, 256>>>(cp, bcN[0], gp, bgN[0], HPTR(0, cur[0]),
                                       HPTR(0, 1 - cur[0]));
            cur[0] ^= 1;
        }
        // ---- nodes 1, 2 (run t >= 1) ----
        if (t >= 1) {
            for (int node = 1; node < 3; node++) {
                pool_k<<<poolBlocks, 256>>>(HPTR(node - 1, cur[node - 1]), pBU);
                gemmT_k<<<dim3(buGx, KS_BU), 256>>>(pBU, buWT[node], part, NBU, KS_BU);
                reduceN_k<<<buRed, 256>>>(part, buB[node], bu, NBU, KS_BU);
                int hastd = (node == 1 && t >= 2);
                if (hastd) {
                    pool_k<<<poolBlocks, 256>>>(HPTR(2, cur[2]), pTD);
                    gemmT_k<<<dim3(tdGx, KS_TD), 256>>>(pTD, tdw1T, part, NTD, KS_TD);
                    reduceN_k<<<tdRed, 256>>>(part, td_b1, td, NTD, KS_TD);
                }
                gate_part_k<<<gateGrid, 224>>>(bu, HPTR(node, cur[node]), td,
                                               WgN[node], gp, hastd);
                cand_part_k<<<candGrid, 224>>>(bu, HPTR(node, cur[node]), gp,
                                               bgN[node], WcN[node], cp);
                cand_fin_k<<<cFinB, 256>>>(cp, bcN[node], gp, bgN[node],
                                           HPTR(node, cur[node]),
                                           HPTR(node, 1 - cur[node]));
                cur[node] ^= 1;
            }
        }
    }
    fc1_k<<<100, 256>>>(HPTR(2, cur[2]), fc1_w, fc1_b, fc1o);
    fc2_k<<<1, 192>>>(fc1o, fc2_w, fc2_b, out);
#undef HPTR
}

// round 11
// speedup vs baseline: 1.9202x; 1.2197x over previous
#include <cuda_runtime.h>
#include <math.h>

// ---------------- problem constants ----------------
#define BB 16
#define TT 8
#define HW 196
#define HID 32
#define IND 16
#define KBIG 6272       // HID*HW
#define K0 588          // CIN*HW
#define K0PAD 640
#define NBU 3136        // IND*HW
#define NTD 9408        // (IND+HID)*HW
#define KS_TD 16
#define KS_BU 42
#define GSEG (16 * 64 * 196)
#define CSEG (16 * 32 * 196)

// ---------------- device scratch (no allocs allowed) ----------------
__device__ float g_h[3 * 2 * BB * HID * HW];   // hidden, double buffered
__device__ float g_xT[TT * K0PAD * BB];        // transposed+padded input slices
__device__ float g_poolBU[KBIG * BB];
__device__ float g_poolTD[KBIG * BB];
__device__ float g_bu[BB * NBU];
__device__ float g_td[BB * NTD];
__device__ float g_part[KS_TD * BB * NTD];     // td K-split partials
__device__ float g_partB[KS_BU * BB * NBU];    // bu K-split partials
__device__ float g_gp[4 * BB * 64 * HW];       // gate conv ic-split partials (4)
__device__ float g_cp[4 * BB * 32 * HW];       // cand conv ic-split partials (4)
__device__ float g_fc1o[BB * 100];
// transposed weights (k-major), rebuilt every call
__device__ float g_tdw0T[(size_t)KBIG * NTD];
__device__ float g_tdw1T[(size_t)KBIG * NTD];
__device__ float g_buw1T[(size_t)KBIG * NBU];
__device__ float g_buw2T[(size_t)KBIG * NBU];

// ---------------- f32x2 helpers ----------------
__device__ __forceinline__ unsigned long long pack2(float v) {
    unsigned long long r;
    asm("mov.b64 %0, {%1, %1};" : "=l"(r) : "f"(v));
    return r;
}
__device__ __forceinline__ void fma2(unsigned long long& d, unsigned long long a,
                                     unsigned long long b) {
    asm("fma.rn.f32x2 %0, %1, %2, %0;" : "+l"(d) : "l"(a), "l"(b));
}
__device__ __forceinline__ unsigned long long add2(unsigned long long a,
                                                   unsigned long long b) {
    unsigned long long r;
    asm("add.rn.f32x2 %0, %1, %2;" : "=l"(r) : "l"(a), "l"(b));
    return r;
}
__device__ __forceinline__ float sigm(float a) { return 1.f / (1.f + expf(-a)); }

// ---------------- 32x32 tiled transpose: W (Nout x K) -> WT (K x Nout) ----------------
__global__ void trans_k(const float* __restrict__ W, float* __restrict__ WT,
                        int Nout, int K) {
    __shared__ float t[32][33];
    const int kb = blockIdx.x * 32, nb = blockIdx.y * 32;
    const int tx = threadIdx.x, ty = threadIdx.y;   // 32 x 8
#pragma unroll
    for (int i = 0; i < 32; i += 8)
        t[ty + i][tx] = W[(size_t)(nb + ty + i) * K + kb + tx];
    __syncthreads();
#pragma unroll
    for (int i = 0; i < 32; i += 8)
        WT[(size_t)(kb + ty + i) * Nout + nb + tx] = t[tx][ty + i];
}

// ================= gemmT core (R10-validated) =================
__device__ __forceinline__ void gemmT_core(
    float* sa, const float* __restrict__ act, const float* __restrict__ WT,
    float* __restrict__ part, int Nout, int KS, int ks, int bx)
{
    const int tid = threadIdx.x;
    const int n0raw = bx * 512 + tid * 2;
    const bool act_n = n0raw < Nout;
    const int n0 = act_n ? n0raw : (Nout - 2);
    const int slabs = KBIG >> 7;                   // 49
    const int s0 = slabs * ks / KS, s1 = slabs * (ks + 1) / KS;
    const int ns = s1 - s0;
    const int kn = ns * 128;

    {
        const float4* src = (const float4*)act + (size_t)s0 * 512;
        for (int f = tid; f < ns * 512; f += 256) {
            float4 v = src[f];
            *(float4*)(&sa[(f >> 2) * 16 + (f & 3) * 4]) = v;
        }
    }

    unsigned long long acc[2][8];
#pragma unroll
    for (int n = 0; n < 2; n++)
#pragma unroll
        for (int p = 0; p < 8; p++) acc[n][p] = 0ull;

    const float* wp = WT + (size_t)(s0 * 128) * Nout + n0;
    float2 wb[2][8];
#pragma unroll
    for (int u = 0; u < 8; u++)
        wb[0][u] = *(const float2*)(wp + (size_t)u * Nout);

    __syncthreads();

    for (int k0 = 0; k0 < kn; k0 += 8) {
        const int cur = (k0 >> 3) & 1;
        const float* wpn = wp + (size_t)8 * Nout;
        if (k0 + 8 < kn) {
#pragma unroll
            for (int u = 0; u < 8; u++)
                wb[cur ^ 1][u] = *(const float2*)(wpn + (size_t)u * Nout);
        }
#pragma unroll
        for (int u = 0; u < 8; u++) {
            const ulonglong2* ap = (const ulonglong2*)(sa + (k0 + u) * 16);
            ulonglong2 u0 = ap[0], u1 = ap[1], u2 = ap[2], u3 = ap[3];
            unsigned long long av[8] = {u0.x, u0.y, u1.x, u1.y,
                                        u2.x, u2.y, u3.x, u3.y};
            unsigned long long w0 = pack2(wb[cur][u].x);
            unsigned long long w1 = pack2(wb[cur][u].y);
#pragma unroll
            for (int p = 0; p < 8; p++) fma2(acc[0][p], w0, av[p]);
#pragma unroll
            for (int p = 0; p < 8; p++) fma2(acc[1][p], w1, av[p]);
        }
        wp = wpn;
    }
    if (act_n) {
        float* op = part + (size_t)ks * 16 * Nout + n0;
#pragma unroll
        for (int b = 0; b < 16; b++) {
            unsigned long long v0 = acc[0][b >> 1], v1 = acc[1][b >> 1];
            float f0 = (b & 1) ? __uint_as_float((unsigned)(v0 >> 32))
                               : __uint_as_float((unsigned)v0);
            float f1 = (b & 1) ? __uint_as_float((unsigned)(v1 >> 32))
                               : __uint_as_float((unsigned)v1);
            op[(size_t)b * Nout + 0] = f0;
            op[(size_t)b * Nout + 1] = f1;
        }
    }
}

__global__ void __launch_bounds__(256) gemmT_k(
    const float* __restrict__ act, const float* __restrict__ WT,
    float* __restrict__ part, int Nout, int KS)
{
    __shared__ float sa[4 * 128 * 16];
    gemmT_core(sa, act, WT, part, Nout, KS, blockIdx.y, blockIdx.x);
}

// merged launch: y < KSA -> problem A, else problem B (co-scheduled blocks)
__global__ void __launch_bounds__(256) gemmT2_k(
    const float* __restrict__ actA, const float* __restrict__ WTA,
    float* __restrict__ partA, int NoutA, int KSA,
    const float* __restrict__ actB, const float* __restrict__ WTB,
    float* __restrict__ partB, int NoutB, int KSB)
{
    __shared__ float sa[4 * 128 * 16];
    const int y = blockIdx.y, bx = blockIdx.x;
    if (y < KSA) {
        if (bx * 512 >= NoutA) return;
        gemmT_core(sa, actA, WTA, partA, NoutA, KSA, y, bx);
    } else {
        if (bx * 512 >= NoutB) return;
        gemmT_core(sa, actB, WTB, partB, NoutB, KSB, y - KSA, bx);
    }
}

__global__ void reduceN_k(const float* __restrict__ part,
                          const float* __restrict__ bias,
                          float* __restrict__ out, int Nout, int KS) {
    int i = blockIdx.x * 256 + threadIdx.x;
    if (i >= 16 * Nout) return;
    int n = i % Nout;
    float a = bias[n];
    for (int ks = 0; ks < KS; ks++) a += part[(size_t)ks * 16 * Nout + i];
    out[i] = a;
}

// ================= old GEMM (R6 config) — only for the small bu0 =================
__global__ void __launch_bounds__(128, 4) gemm_k(
    const float* __restrict__ inT, const float* __restrict__ W,
    const float* __restrict__ bias, float* __restrict__ out,
    int K, int Krows, int Nout)
{
    __shared__ float4 smem4[768 * 4];
    char* smb = (char*)smem4;
    const int tid = threadIdx.x, warp = tid >> 5, lane = tid & 31;
    const int row0 = blockIdx.x * 16 + warp * 4;
    const int slabs = Krows >> 7;

    const float* Wr[4];
#pragma unroll
    for (int r = 0; r < 4; r++) Wr[r] = W + (size_t)(row0 + r) * K + 4 * lane;

    unsigned long long acc[4][8];
#pragma unroll
    for (int r = 0; r < 4; r++)
#pragma unroll
        for (int i = 0; i < 8; i++) acc[r][i] = 0ull;

    for (int tb = 0; tb < slabs; tb += 6) {
        const int ns = min(6, slabs - tb);
        __syncthreads();
        for (int f = tid; f < ns * 512; f += 128) {
            int row = f >> 2, q = f & 3;
            float4 v = ((const float4*)inT)[((size_t)(tb * 128 + row)) * 4 + q];
            unsigned off = (unsigned)((row << 6) | (q << 4)) ^ (((row >> 2) & 7) << 4);
            *(float4*)(smb + off) = v;
        }
        __syncthreads();
        const int kbase = tb * 128;
        float4 wc[4], wn[4];
        {
            const bool ok = (kbase + 4 * lane) < K;
#pragma unroll
            for (int r = 0; r < 4; r++)
                wc[r] = ok ? *(const float4*)(Wr[r] + kbase)
                           : make_float4(0.f, 0.f, 0.f, 0.f);
        }
        for (int s = 0; s < ns; s++) {
            const int knext = kbase + (s + 1) * 128;
            if (s + 1 < ns) {
                const bool ok = (knext + 4 * lane) < K;
#pragma unroll
                for (int r = 0; r < 4; r++)
                    wn[r] = ok ? *(const float4*)(Wr[r] + knext)
                               : make_float4(0.f, 0.f, 0.f, 0.f);
            } else {
#pragma unroll
                for (int r = 0; r < 4; r++) wn[r] = make_float4(0.f, 0.f, 0.f, 0.f);
            }
#pragma unroll
            for (int j = 0; j < 4; j++) {
                const int row = s * 128 + 4 * lane + j;
                const unsigned x = ((row >> 2) & 7) << 4;
                const unsigned b0 = (unsigned)(row << 6);
                ulonglong2 u0 = *(const ulonglong2*)(smb + ((b0 | 0u) ^ x));
                ulonglong2 u1 = *(const ulonglong2*)(smb + ((b0 | 16u) ^ x));
                ulonglong2 u2 = *(const ulonglong2*)(smb + ((b0 | 32u) ^ x));
                ulonglong2 u3 = *(const ulonglong2*)(smb + ((b0 | 48u) ^ x));
                unsigned long long av[8] = {u0.x, u0.y, u1.x, u1.y,
                                            u2.x, u2.y, u3.x, u3.y};
#pragma unroll
                for (int r = 0; r < 4; r++) {
                    unsigned long long wj = pack2(((const float*)&wc[r])[j]);
#pragma unroll
                    for (int i = 0; i < 8; i++) fma2(acc[r][i], wj, av[i]);
                }
            }
#pragma unroll
            for (int r = 0; r < 4; r++) wc[r] = wn[r];
        }
    }
#pragma unroll
    for (int off = 16; off; off >>= 1)
#pragma unroll
        for (int r = 0; r < 4; r++)
#pragma unroll
            for (int i = 0; i < 8; i++)
                acc[r][i] = add2(acc[r][i],
                                 __shfl_xor_sync(0xffffffffu, acc[r][i], off));
    if (lane < 16) {
        const int b = lane, jj = b >> 1;
#pragma unroll
        for (int r = 0; r < 4; r++) {
            unsigned long long v = acc[r][jj];
            float f = (b & 1) ? __uint_as_float((unsigned)(v >> 32))
                              : __uint_as_float((unsigned)v);
            int n = row0 + r;
            out[(size_t)b * Nout + n] = f + bias[n];
        }
    }
}

// ================= conv: ic-split x4 partial kernels =================
__global__ void __launch_bounds__(224) gate_part_k(
    const float* __restrict__ bu, const float* __restrict__ h,
    const float* __restrict__ td, const float* __restrict__ Wg,
    float* __restrict__ gp, int has_td)
{
    __shared__ float sc[12 * 256];
    __shared__ float sw[12 * 36];
    const int b = blockIdx.x, grp = blockIdx.y, qtr = blockIdx.z;
    const int ic0 = qtr * 12;
    const int tid = threadIdx.x;
    for (int i = tid; i < 12 * 256; i += 224) sc[i] = 0.f;
    for (int i = tid; i < 12 * 36; i += 224) {
        int lic = i / 36, rem = i - lic * 36, q = rem >> 2, o = rem & 3;
        sw[i] = Wg[(grp * 4 + o) * 432 + (ic0 + lic) * 9 + q];
    }
    __syncthreads();
    for (int i = tid; i < 12 * 196; i += 224) {
        int lic = i / 196, p = i - lic * 196, y = p / 14, x = p - y * 14;
        int ic = ic0 + lic;
        float v = (ic < IND) ? bu[((size_t)b * IND + ic) * 196 + p]
                             : h[((size_t)b * HID + (ic - IND)) * 196 + p];
        if (has_td) v += td[((size_t)b * 48 + ic) * 196 + p];
        sc[lic * 256 + (y + 1) * 16 + (x + 1)] = v;
    }
    __syncthreads();
    if (tid < 196) {
        const int p = tid, y = p / 14, x = p - y * 14;
        float4 a = make_float4(0.f, 0.f, 0.f, 0.f);
        const float* cbase = sc + y * 16 + x;
        for (int lic = 0; lic < 12; ++lic) {
            float v[9];
            const float* cb = cbase + lic * 256;
#pragma unroll
            for (int dy = 0; dy < 3; dy++)
#pragma unroll
                for (int dx = 0; dx < 3; dx++) v[dy * 3 + dx] = cb[dy * 16 + dx];
            const float4* wq = (const float4*)(sw + lic * 36);
#pragma unroll
            for (int q = 0; q < 9; q++) {
                float4 w = wq[q];
                a.x += w.x * v[q]; a.y += w.y * v[q];
                a.z += w.z * v[q]; a.w += w.w * v[q];
            }
        }
        float* o = gp + (size_t)qtr * GSEG + ((size_t)b * 64 + grp * 4) * 196 + p;
        o[0] = a.x; o[196] = a.y; o[392] = a.z; o[588] = a.w;
    }
}

__global__ void __launch_bounds__(224) cand_part_k(
    const float* __restrict__ bu, const float* __restrict__ h,
    const float* __restrict__ gp, const float* __restrict__ bg,
    const float* __restrict__ Wc, float* __restrict__ cp)
{
    __shared__ float sc[12 * 256];
    __shared__ float sw[12 * 36];
    const int b = blockIdx.x, grp = blockIdx.y, qtr = blockIdx.z;
    const int ic0 = qtr * 12;
    const int tid = threadIdx.x;
    for (int i = tid; i < 12 * 256; i += 224) sc[i] = 0.f;
    for (int i = tid; i < 12 * 36; i += 224) {
        int lic = i / 36, rem = i - lic * 36, q = rem >> 2, o = rem & 3;
        sw[i] = Wc[(grp * 4 + o) * 432 + (ic0 + lic) * 9 + q];
    }
    __syncthreads();
    for (int i = tid; i < 12 * 196; i += 224) {
        int lic = i / 196, p = i - lic * 196, y = p / 14, x = p - y * 14;
        int ic = ic0 + lic;
        float v;
        if (ic < IND) {
            v = bu[((size_t)b * IND + ic) * 196 + p];
        } else {
            int c = ic - IND;
            size_t gi = ((size_t)b * 64 + c) * 196 + p;
            float r = sigm(gp[gi] + gp[gi + GSEG] + gp[gi + 2 * (size_t)GSEG] +
                           gp[gi + 3 * (size_t)GSEG] + bg[c]);
            v = r * h[((size_t)b * HID + c) * 196 + p];
        }
        sc[lic * 256 + (y + 1) * 16 + (x + 1)] = v;
    }
    __syncthreads();
    if (tid < 196) {
        const int p = tid, y = p / 14, x = p - y * 14;
        float4 a = make_float4(0.f, 0.f, 0.f, 0.f);
        const float* cbase = sc + y * 16 + x;
        for (int lic = 0; lic < 12; ++lic) {
            float v[9];
            const float* cb = cbase + lic * 256;
#pragma unroll
            for (int dy = 0; dy < 3; dy++)
#pragma unroll
                for (int dx = 0; dx < 3; dx++) v[dy * 3 + dx] = cb[dy * 16 + dx];
            const float4* wq = (const float4*)(sw + lic * 36);
#pragma unroll
            for (int q = 0; q < 9; q++) {
                float4 w = wq[q];
                a.x += w.x * v[q]; a.y += w.y * v[q];
                a.z += w.z * v[q]; a.w += w.w * v[q];
            }
        }
        float* o = cp + (size_t)qtr * CSEG + ((size_t)b * 32 + grp * 4) * 196 + p;
        o[0] = a.x; o[196] = a.y; o[392] = a.z; o[588] = a.w;
    }
}

__global__ void cand_fin_k(const float* __restrict__ cp,
                           const float* __restrict__ bc,
                           const float* __restrict__ gp,
                           const float* __restrict__ bg,
                           const float* __restrict__ h,
                           float* __restrict__ hnew) {
    int i = blockIdx.x * 256 + threadIdx.x;
    if (i >= 16 * 32 * 196) return;
    int p = i % 196;
    int oc = (i / 196) & 31;
    int b = i / (32 * 196);
    float a = cp[i] + cp[i + (size_t)CSEG] + cp[i + 2 * (size_t)CSEG] +
              cp[i + 3 * (size_t)CSEG] + bc[oc];
    size_t gi = ((size_t)b * 64 + 32 + oc) * 196 + p;
    float z = sigm(gp[gi] + gp[gi + (size_t)GSEG] + gp[gi + 2 * (size_t)GSEG] +
                   gp[gi + 3 * (size_t)GSEG] + bg[32 + oc]);
    float ho = h[i];
    hnew[i] = (1.f - z) * ho + z * tanhf(a);
}

// ---------------- maxpool 3x3 s1 p1 + transpose to (K,16) ----------------
__device__ __forceinline__ void pool_one(const float* __restrict__ h,
                                         float* __restrict__ outT, int idx) {
    int b = idx & 15, k = idx >> 4;
    int c = k / 196, p = k - c * 196, y = p / 14, x = p - y * 14;
    const float* hp = h + ((size_t)b * HID + c) * 196;
    int y0 = y > 0 ? y - 1 : 0, y1 = y < 13 ? y + 1 : 13;
    int x0 = x > 0 ? x - 1 : 0, x1 = x < 13 ? x + 1 : 13;
    float m = -3.4e38f;
    for (int yy = y0; yy <= y1; ++yy)
        for (int xx = x0; xx <= x1; ++xx)
            m = fmaxf(m, hp[yy * 14 + xx]);
    outT[(size_t)k * 16 + b] = m;
}
__global__ void pool_k(const float* __restrict__ h, float* __restrict__ outT) {
    int idx = blockIdx.x * 256 + threadIdx.x;
    if (idx >= BB * KBIG) return;
    pool_one(h, outT, idx);
}
// merged: z=0 -> (h0 -> dst0), z=1 -> (h1 -> dst1)
__global__ void pool2_k(const float* __restrict__ h0, float* __restrict__ dst0,
                        const float* __restrict__ h1, float* __restrict__ dst1) {
    int idx = blockIdx.x * 256 + threadIdx.x;
    if (idx >= BB * KBIG) return;
    if (blockIdx.z == 0) pool_one(h0, dst0, idx);
    else                 pool_one(h1, dst1, idx);
}

__global__ void xT_k(const float* __restrict__ x, float* __restrict__ xT) {
    int idx = blockIdx.x * 256 + threadIdx.x;
    if (idx >= TT * K0PAD * BB) return;
    int b = idx & 15;
    int r = idx >> 4;
    int k = r % K0PAD, t = r / K0PAD;
    float v = 0.f;
    if (k < K0) v = x[((size_t)b * TT + t) * K0 + k];
    xT[idx] = v;
}

__global__ void zero_k(float* p, int n) {
    int i = blockIdx.x * 256 + threadIdx.x;
    if (i < n) p[i] = 0.f;
}

// ---------------- fc tail ----------------
__global__ void __launch_bounds__(256) fc1_k(const float* __restrict__ h2,
                                             const float* __restrict__ w,
                                             const float* __restrict__ bias,
                                             float* __restrict__ out1) {
    __shared__ float red[256];
    int j = blockIdx.x, tid = threadIdx.x;
    float acc[16];
#pragma unroll
    for (int b = 0; b < 16; b++) acc[b] = 0.f;
    for (int k = tid; k < KBIG; k += 256) {
        float wv = w[(size_t)j * KBIG + k];
#pragma unroll
        for (int b = 0; b < 16; b++)
            acc[b] += wv * fmaxf(h2[(size_t)b * KBIG + k], 0.f);
    }
    for (int b = 0; b < 16; b++) {
        red[tid] = acc[b];
        __syncthreads();
        for (int sft = 128; sft; sft >>= 1) {
            if (tid < sft) red[tid] += red[tid + sft];
            __syncthreads();
        }
        if (tid == 0) out1[b * 100 + j] = fmaxf(red[0] + bias[j], 0.f);
        __syncthreads();
    }
}

__global__ void fc2_k(const float* __restrict__ p, const float* __restrict__ w,
                      const float* __restrict__ bias, float* __restrict__ out) {
    int t = threadIdx.x;
    if (t < 160) {
        int b = t / 10, j = t - b * 10;
        float a = bias[j];
        for (int k = 0; k < 100; k++) a += p[b * 100 + k] * w[j * 100 + k];
        out[b * 10 + j] = a;
    }
}

// ---------------- host orchestration ----------------
extern "C" void kernel_launch(void* const* d_in, const int* in_sizes, int n_in,
                              void* d_out, int out_size) {
    const float* x     = (const float*)d_in[0];
    const float* Wg    = (const float*)d_in[1];
    const float* bg    = (const float*)d_in[2];
    const float* Wc    = (const float*)d_in[3];
    const float* bc    = (const float*)d_in[4];
    const float* bu_w0 = (const float*)d_in[5];
    const float* bu_b0 = (const float*)d_in[6];
    const float* bu_w1 = (const float*)d_in[7];
    const float* bu_b1 = (const float*)d_in[8];
    const float* bu_w2 = (const float*)d_in[9];
    const float* bu_b2 = (const float*)d_in[10];
    const float* td_w0 = (const float*)d_in[11];
    const float* td_b0 = (const float*)d_in[12];
    const float* td_w1 = (const float*)d_in[13];
    const float* td_b1 = (const float*)d_in[14];
    const float* fc1_w = (const float*)d_in[15];
    const float* fc1_b = (const float*)d_in[16];
    const float* fc2_w = (const float*)d_in[17];
    const float* fc2_b = (const float*)d_in[18];
    float* out = (float*)d_out;

    float *hbuf, *xT, *pBU, *pTD, *bu, *td, *part, *partB, *gp, *cp, *fc1o;
    float *tdw0T, *tdw1T, *buw1T, *buw2T;
    cudaGetSymbolAddress((void**)&hbuf,  g_h);
    cudaGetSymbolAddress((void**)&xT,    g_xT);
    cudaGetSymbolAddress((void**)&pBU,   g_poolBU);
    cudaGetSymbolAddress((void**)&pTD,   g_poolTD);
    cudaGetSymbolAddress((void**)&bu,    g_bu);
    cudaGetSymbolAddress((void**)&td,    g_td);
    cudaGetSymbolAddress((void**)&part,  g_part);
    cudaGetSymbolAddress((void**)&partB, g_partB);
    cudaGetSymbolAddress((void**)&gp,    g_gp);
    cudaGetSymbolAddress((void**)&cp,    g_cp);
    cudaGetSymbolAddress((void**)&fc1o,  g_fc1o);
    cudaGetSymbolAddress((void**)&tdw0T, g_tdw0T);
    cudaGetSymbolAddress((void**)&tdw1T, g_tdw1T);
    cudaGetSymbolAddress((void**)&buw1T, g_buw1T);
    cudaGetSymbolAddress((void**)&buw2T, g_buw2T);

    const int hTot = 3 * 2 * BB * HID * HW;
    zero_k<<<(hTot + 255) / 256, 256>>>(hbuf, hTot);
    xT_k<<<(TT * K0PAD * BB + 255) / 256, 256>>>(x, xT);

    {
        dim3 tb(32, 8);
        trans_k<<<dim3(KBIG / 32, NTD / 32), tb>>>(td_w0, tdw0T, NTD, KBIG);
        trans_k<<<dim3(KBIG / 32, NTD / 32), tb>>>(td_w1, tdw1T, NTD, KBIG);
        trans_k<<<dim3(KBIG / 32, NBU / 32), tb>>>(bu_w1, buw1T, NBU, KBIG);
        trans_k<<<dim3(KBIG / 32, NBU / 32), tb>>>(bu_w2, buw2T, NBU, KBIG);
    }

    int cur[3] = {0, 0, 0};
    const size_t HSZ = (size_t)BB * HID * HW;
    const float* WgN[3] = {Wg, Wg + 27648, Wg + 2 * 27648};
    const float* bgN[3] = {bg, bg + 64, bg + 128};
    const float* WcN[3] = {Wc, Wc + 13824, Wc + 2 * 13824};
    const float* bcN[3] = {bc, bc + 32, bc + 64};
    const float* buB[3] = {bu_b0, bu_b1, bu_b2};
    const float* buWT[3] = {0, buw1T, buw2T};

    dim3 gateGrid(16, 16, 4), candGrid(16, 8, 4);
    const int poolBlocks = (BB * KBIG + 255) / 256;
    const int cFinB = (16 * 32 * 196 + 255) / 256;
    const int tdGx = (NTD + 511) / 512, buGx = (NBU + 511) / 512;
    const int tdRed = (16 * NTD + 255) / 256, buRed = (16 * NBU + 255) / 256;
#define HPTR(n, p) (hbuf + ((size_t)(n) * 2 + (p)) * HSZ)

    for (int t = 0; t < TT + 2; t++) {
        // ---- node 0 (runs t < T) ----
        if (t < TT) {
            int hastd = (t >= 2);
            if (hastd) {
                pool_k<<<poolBlocks, 256>>>(HPTR(1, cur[1]), pTD);
                gemmT_k<<<dim3(tdGx, KS_TD), 256>>>(pTD, tdw0T, part, NTD, KS_TD);
                reduceN_k<<<tdRed, 256>>>(part, td_b0, td, NTD, KS_TD);
            }
            gemm_k<<<NBU / 16, 128>>>(xT + (size_t)t * K0PAD * 16, bu_w0, bu_b0,
                                      bu, K0, K0PAD, NBU);
            gate_part_k<<<gateGrid, 224>>>(bu, HPTR(0, cur[0]), td, WgN[0], gp, hastd);
            cand_part_k<<<candGrid, 224>>>(bu, HPTR(0, cur[0]), gp, bgN[0], WcN[0], cp);
            cand_fin_k<<<cFinB, 256>>>(cp, bcN[0], gp, bgN[0], HPTR(0, cur[0]),
                                       HPTR(0, 1 - cur[0]));
            cur[0] ^= 1;
        }
        // ---- nodes 1, 2 (run t >= 1) ----
        if (t >= 1) {
            // node 1
            {
                int hastd = (t >= 2);
                if (hastd) {
                    // merged pools: bu pool (h0 post-update) + td pool (h2 pre-update)
                    pool2_k<<<dim3(poolBlocks, 1, 2), 256>>>(
                        HPTR(0, cur[0]), pBU, HPTR(2, cur[2]), pTD);
                    // merged GEMMs: bu (KS_BU) + td1 (KS_TD) co-scheduled
                    gemmT2_k<<<dim3(tdGx, KS_BU + KS_TD), 256>>>(
                        pBU, buWT[1], partB, NBU, KS_BU,
                        pTD, tdw1T, part, NTD, KS_TD);
                    reduceN_k<<<buRed, 256>>>(partB, buB[1], bu, NBU, KS_BU);
                    reduceN_k<<<tdRed, 256>>>(part, td_b1, td, NTD, KS_TD);
                } else {
                    pool_k<<<poolBlocks, 256>>>(HPTR(0, cur[0]), pBU);
                    gemmT_k<<<dim3(buGx, KS_BU), 256>>>(pBU, buWT[1], partB,
                                                        NBU, KS_BU);
                    reduceN_k<<<buRed, 256>>>(partB, buB[1], bu, NBU, KS_BU);
                }
                gate_part_k<<<gateGrid, 224>>>(bu, HPTR(1, cur[1]), td,
                                               WgN[1], gp, hastd);
                cand_part_k<<<candGrid, 224>>>(bu, HPTR(1, cur[1]), gp,
                                               bgN[1], WcN[1], cp);
                cand_fin_k<<<cFinB, 256>>>(cp, bcN[1], gp, bgN[1],
                                           HPTR(1, cur[1]), HPTR(1, 1 - cur[1]));
                cur[1] ^= 1;
            }
            // node 2 (no td)
            {
                pool_k<<<poolBlocks, 256>>>(HPTR(1, cur[1]), pBU);
                gemmT_k<<<dim3(buGx, KS_BU), 256>>>(pBU, buWT[2], partB, NBU, KS_BU);
                reduceN_k<<<buRed, 256>>>(partB, buB[2], bu, NBU, KS_BU);
                gate_part_k<<<gateGrid, 224>>>(bu, HPTR(2, cur[2]), td,
                                               WgN[2], gp, 0);
                cand_part_k<<<candGrid, 224>>>(bu, HPTR(2, cur[2]), gp,
                                               bgN[2], WcN[2], cp);
                cand_fin_k<<<cFinB, 256>>>(cp, bcN[2], gp, bgN[2],
                                           HPTR(2, cur[2]), HPTR(2, 1 - cur[2]));
                cur[2] ^= 1;
            }
        }
    }
    fc1_k<<<100, 256>>>(HPTR(2, cur[2]), fc1_w, fc1_b, fc1o);
    fc2_k<<<1, 192>>>(fc1o, fc2_w, fc2_b, out);
#undef HPTR
}

// round 12
// speedup vs baseline: 2.1221x; 1.1051x over previous
#include <cuda_runtime.h>
#include <math.h>

// ---------------- problem constants ----------------
#define BB 16
#define TT 8
#define HW 196
#define HID 32
#define IND 16
#define KBIG 6272       // HID*HW
#define K0 588          // CIN*HW
#define K0PAD 640
#define NBU 3136        // IND*HW
#define NTD 9408        // (IND+HID)*HW
#define KS_TD 24
#define KS_BU 49
#define GSEG (16 * 64 * 196)
#define CSEG (16 * 32 * 196)

// ---------------- device scratch (no allocs allowed) ----------------
__device__ float g_h[3 * 2 * BB * HID * HW];   // hidden, double buffered
__device__ float g_xT[TT * K0PAD * BB];        // transposed+padded input slices
__device__ float g_poolBU[KBIG * BB];
__device__ float g_poolTD[KBIG * BB];
__device__ float g_bu[BB * NBU];
__device__ float g_td[BB * NTD];
__device__ float g_part[KS_TD * BB * NTD];     // td K-split partials
__device__ float g_partB[KS_BU * BB * NBU];    // bu K-split partials
__device__ float g_gp[4 * BB * 64 * HW];       // gate conv ic-split partials (4)
__device__ float g_cp[4 * BB * 32 * HW];       // cand conv ic-split partials (4)
__device__ float g_fc1o[BB * 100];
// transposed weights (k-major), rebuilt every call
__device__ float g_tdw0T[(size_t)KBIG * NTD];
__device__ float g_tdw1T[(size_t)KBIG * NTD];
__device__ float g_buw1T[(size_t)KBIG * NBU];
__device__ float g_buw2T[(size_t)KBIG * NBU];

// ---------------- f32x2 helpers ----------------
__device__ __forceinline__ unsigned long long pack2(float v) {
    unsigned long long r;
    asm("mov.b64 %0, {%1, %1};" : "=l"(r) : "f"(v));
    return r;
}
__device__ __forceinline__ void fma2(unsigned long long& d, unsigned long long a,
                                     unsigned long long b) {
    asm("fma.rn.f32x2 %0, %1, %2, %0;" : "+l"(d) : "l"(a), "l"(b));
}
__device__ __forceinline__ unsigned long long add2(unsigned long long a,
                                                   unsigned long long b) {
    unsigned long long r;
    asm("add.rn.f32x2 %0, %1, %2;" : "=l"(r) : "l"(a), "l"(b));
    return r;
}
__device__ __forceinline__ float sigm(float a) { return 1.f / (1.f + expf(-a)); }

// ---------------- merged 32x32 tiled transpose: 2 same-shape matrices ----------------
__global__ void trans2_k(const float* __restrict__ Wa, float* __restrict__ WTa,
                         const float* __restrict__ Wb, float* __restrict__ WTb,
                         int Nout) {
    __shared__ float t[32][33];
    const float* W  = blockIdx.z ? Wb  : Wa;
    float*       WT = blockIdx.z ? WTb : WTa;
    const int kb = blockIdx.x * 32, nb = blockIdx.y * 32;
    const int tx = threadIdx.x, ty = threadIdx.y;   // 32 x 8
#pragma unroll
    for (int i = 0; i < 32; i += 8)
        t[ty + i][tx] = W[(size_t)(nb + ty + i) * KBIG + kb + tx];
    __syncthreads();
#pragma unroll
    for (int i = 0; i < 32; i += 8)
        WT[(size_t)(kb + ty + i) * Nout + nb + tx] = t[tx][ty + i];
}

// ================= gemmT core (R10-validated) =================
__device__ __forceinline__ void gemmT_core(
    float* sa, const float* __restrict__ act, const float* __restrict__ WT,
    float* __restrict__ part, int Nout, int KS, int ks, int bx)
{
    const int tid = threadIdx.x;
    const int n0raw = bx * 512 + tid * 2;
    const bool act_n = n0raw < Nout;
    const int n0 = act_n ? n0raw : (Nout - 2);
    const int slabs = KBIG >> 7;                   // 49
    const int s0 = slabs * ks / KS, s1 = slabs * (ks + 1) / KS;
    const int ns = s1 - s0;                        // 1..3 slabs
    const int kn = ns * 128;

    {
        const float4* src = (const float4*)act + (size_t)s0 * 512;
        for (int f = tid; f < ns * 512; f += 256) {
            float4 v = src[f];
            *(float4*)(&sa[(f >> 2) * 16 + (f & 3) * 4]) = v;
        }
    }

    unsigned long long acc[2][8];
#pragma unroll
    for (int n = 0; n < 2; n++)
#pragma unroll
        for (int p = 0; p < 8; p++) acc[n][p] = 0ull;

    const float* wp = WT + (size_t)(s0 * 128) * Nout + n0;
    float2 wb[2][8];
#pragma unroll
    for (int u = 0; u < 8; u++)
        wb[0][u] = *(const float2*)(wp + (size_t)u * Nout);

    __syncthreads();

    for (int k0 = 0; k0 < kn; k0 += 8) {
        const int cur = (k0 >> 3) & 1;
        const float* wpn = wp + (size_t)8 * Nout;
        if (k0 + 8 < kn) {
#pragma unroll
            for (int u = 0; u < 8; u++)
                wb[cur ^ 1][u] = *(const float2*)(wpn + (size_t)u * Nout);
        }
#pragma unroll
        for (int u = 0; u < 8; u++) {
            const ulonglong2* ap = (const ulonglong2*)(sa + (k0 + u) * 16);
            ulonglong2 u0 = ap[0], u1 = ap[1], u2 = ap[2], u3 = ap[3];
            unsigned long long av[8] = {u0.x, u0.y, u1.x, u1.y,
                                        u2.x, u2.y, u3.x, u3.y};
            unsigned long long w0 = pack2(wb[cur][u].x);
            unsigned long long w1 = pack2(wb[cur][u].y);
#pragma unroll
            for (int p = 0; p < 8; p++) fma2(acc[0][p], w0, av[p]);
#pragma unroll
            for (int p = 0; p < 8; p++) fma2(acc[1][p], w1, av[p]);
        }
        wp = wpn;
    }
    if (act_n) {
        float* op = part + (size_t)ks * 16 * Nout + n0;
#pragma unroll
        for (int b = 0; b < 16; b++) {
            unsigned long long v0 = acc[0][b >> 1], v1 = acc[1][b >> 1];
            float f0 = (b & 1) ? __uint_as_float((unsigned)(v0 >> 32))
                               : __uint_as_float((unsigned)v0);
            float f1 = (b & 1) ? __uint_as_float((unsigned)(v1 >> 32))
                               : __uint_as_float((unsigned)v1);
            op[(size_t)b * Nout + 0] = f0;
            op[(size_t)b * Nout + 1] = f1;
        }
    }
}

__global__ void __launch_bounds__(256) gemmT_k(
    const float* __restrict__ act, const float* __restrict__ WT,
    float* __restrict__ part, int Nout, int KS)
{
    __shared__ float sa[3 * 128 * 16];
    gemmT_core(sa, act, WT, part, Nout, KS, blockIdx.y, blockIdx.x);
}

// merged launch: y < KSA -> problem A, else problem B (co-scheduled blocks)
__global__ void __launch_bounds__(256) gemmT2_k(
    const float* __restrict__ actA, const float* __restrict__ WTA,
    float* __restrict__ partA, int NoutA, int KSA,
    const float* __restrict__ actB, const float* __restrict__ WTB,
    float* __restrict__ partB, int NoutB, int KSB)
{
    __shared__ float sa[3 * 128 * 16];
    const int y = blockIdx.y, bx = blockIdx.x;
    if (y < KSA) {
        if (bx * 512 >= NoutA) return;
        gemmT_core(sa, actA, WTA, partA, NoutA, KSA, y, bx);
    } else {
        if (bx * 512 >= NoutB) return;
        gemmT_core(sa, actB, WTB, partB, NoutB, KSB, y - KSA, bx);
    }
}

__global__ void reduceN_k(const float* __restrict__ part,
                          const float* __restrict__ bias,
                          float* __restrict__ out, int Nout, int KS) {
    int i = blockIdx.x * 256 + threadIdx.x;
    if (i >= 16 * Nout) return;
    int n = i % Nout;
    float a = bias[n];
    for (int ks = 0; ks < KS; ks++) a += part[(size_t)ks * 16 * Nout + i];
    out[i] = a;
}

// merged reduce: bu partials then td partials in one launch
__global__ void reduce2_k(const float* __restrict__ pB,
                          const float* __restrict__ bB, float* __restrict__ oB,
                          const float* __restrict__ pT,
                          const float* __restrict__ bT, float* __restrict__ oT) {
    int i = blockIdx.x * 256 + threadIdx.x;
    if (i < 16 * NBU) {
        int n = i % NBU;
        float a = bB[n];
        for (int ks = 0; ks < KS_BU; ks++) a += pB[(size_t)ks * 16 * NBU + i];
        oB[i] = a;
    } else {
        int j = i - 16 * NBU;
        if (j >= 16 * NTD) return;
        int n = j % NTD;
        float a = bT[n];
        for (int ks = 0; ks < KS_TD; ks++) a += pT[(size_t)ks * 16 * NTD + j];
        oT[j] = a;
    }
}

// ================= old GEMM (R6 config) — only for the small bu0 =================
__global__ void __launch_bounds__(128, 4) gemm_k(
    const float* __restrict__ inT, const float* __restrict__ W,
    const float* __restrict__ bias, float* __restrict__ out,
    int K, int Krows, int Nout)
{
    __shared__ float4 smem4[768 * 4];
    char* smb = (char*)smem4;
    const int tid = threadIdx.x, warp = tid >> 5, lane = tid & 31;
    const int row0 = blockIdx.x * 16 + warp * 4;
    const int slabs = Krows >> 7;

    const float* Wr[4];
#pragma unroll
    for (int r = 0; r < 4; r++) Wr[r] = W + (size_t)(row0 + r) * K + 4 * lane;

    unsigned long long acc[4][8];
#pragma unroll
    for (int r = 0; r < 4; r++)
#pragma unroll
        for (int i = 0; i < 8; i++) acc[r][i] = 0ull;

    for (int tb = 0; tb < slabs; tb += 6) {
        const int ns = min(6, slabs - tb);
        __syncthreads();
        for (int f = tid; f < ns * 512; f += 128) {
            int row = f >> 2, q = f & 3;
            float4 v = ((const float4*)inT)[((size_t)(tb * 128 + row)) * 4 + q];
            unsigned off = (unsigned)((row << 6) | (q << 4)) ^ (((row >> 2) & 7) << 4);
            *(float4*)(smb + off) = v;
        }
        __syncthreads();
        const int kbase = tb * 128;
        float4 wc[4], wn[4];
        {
            const bool ok = (kbase + 4 * lane) < K;
#pragma unroll
            for (int r = 0; r < 4; r++)
                wc[r] = ok ? *(const float4*)(Wr[r] + kbase)
                           : make_float4(0.f, 0.f, 0.f, 0.f);
        }
        for (int s = 0; s < ns; s++) {
            const int knext = kbase + (s + 1) * 128;
            if (s + 1 < ns) {
                const bool ok = (knext + 4 * lane) < K;
#pragma unroll
                for (int r = 0; r < 4; r++)
                    wn[r] = ok ? *(const float4*)(Wr[r] + knext)
                               : make_float4(0.f, 0.f, 0.f, 0.f);
            } else {
#pragma unroll
                for (int r = 0; r < 4; r++) wn[r] = make_float4(0.f, 0.f, 0.f, 0.f);
            }
#pragma unroll
            for (int j = 0; j < 4; j++) {
                const int row = s * 128 + 4 * lane + j;
                const unsigned x = ((row >> 2) & 7) << 4;
                const unsigned b0 = (unsigned)(row << 6);
                ulonglong2 u0 = *(const ulonglong2*)(smb + ((b0 | 0u) ^ x));
                ulonglong2 u1 = *(const ulonglong2*)(smb + ((b0 | 16u) ^ x));
                ulonglong2 u2 = *(const ulonglong2*)(smb + ((b0 | 32u) ^ x));
                ulonglong2 u3 = *(const ulonglong2*)(smb + ((b0 | 48u) ^ x));
                unsigned long long av[8] = {u0.x, u0.y, u1.x, u1.y,
                                            u2.x, u2.y, u3.x, u3.y};
#pragma unroll
                for (int r = 0; r < 4; r++) {
                    unsigned long long wj = pack2(((const float*)&wc[r])[j]);
#pragma unroll
                    for (int i = 0; i < 8; i++) fma2(acc[r][i], wj, av[i]);
                }
            }
#pragma unroll
            for (int r = 0; r < 4; r++) wc[r] = wn[r];
        }
    }
#pragma unroll
    for (int off = 16; off; off >>= 1)
#pragma unroll
        for (int r = 0; r < 4; r++)
#pragma unroll
            for (int i = 0; i < 8; i++)
                acc[r][i] = add2(acc[r][i],
                                 __shfl_xor_sync(0xffffffffu, acc[r][i], off));
    if (lane < 16) {
        const int b = lane, jj = b >> 1;
#pragma unroll
        for (int r = 0; r < 4; r++) {
            unsigned long long v = acc[r][jj];
            float f = (b & 1) ? __uint_as_float((unsigned)(v >> 32))
                              : __uint_as_float((unsigned)v);
            int n = row0 + r;
            out[(size_t)b * Nout + n] = f + bias[n];
        }
    }
}

// ================= conv: ic-split x4 partial kernels =================
__global__ void __launch_bounds__(224) gate_part_k(
    const float* __restrict__ bu, const float* __restrict__ h,
    const float* __restrict__ td, const float* __restrict__ Wg,
    float* __restrict__ gp, int has_td)
{
    __shared__ float sc[12 * 256];
    __shared__ float sw[12 * 36];
    const int b = blockIdx.x, grp = blockIdx.y, qtr = blockIdx.z;
    const int ic0 = qtr * 12;
    const int tid = threadIdx.x;
    for (int i = tid; i < 12 * 256; i += 224) sc[i] = 0.f;
    for (int i = tid; i < 12 * 36; i += 224) {
        int lic = i / 36, rem = i - lic * 36, q = rem >> 2, o = rem & 3;
        sw[i] = Wg[(grp * 4 + o) * 432 + (ic0 + lic) * 9 + q];
    }
    __syncthreads();
    for (int i = tid; i < 12 * 196; i += 224) {
        int lic = i / 196, p = i - lic * 196, y = p / 14, x = p - y * 14;
        int ic = ic0 + lic;
        float v = (ic < IND) ? bu[((size_t)b * IND + ic) * 196 + p]
                             : h[((size_t)b * HID + (ic - IND)) * 196 + p];
        if (has_td) v += td[((size_t)b * 48 + ic) * 196 + p];
        sc[lic * 256 + (y + 1) * 16 + (x + 1)] = v;
    }
    __syncthreads();
    if (tid < 196) {
        const int p = tid, y = p / 14, x = p - y * 14;
        float4 a = make_float4(0.f, 0.f, 0.f, 0.f);
        const float* cbase = sc + y * 16 + x;
        for (int lic = 0; lic < 12; ++lic) {
            float v[9];
            const float* cb = cbase + lic * 256;
#pragma unroll
            for (int dy = 0; dy < 3; dy++)
#pragma unroll
                for (int dx = 0; dx < 3; dx++) v[dy * 3 + dx] = cb[dy * 16 + dx];
            const float4* wq = (const float4*)(sw + lic * 36);
#pragma unroll
            for (int q = 0; q < 9; q++) {
                float4 w = wq[q];
                a.x += w.x * v[q]; a.y += w.y * v[q];
                a.z += w.z * v[q]; a.w += w.w * v[q];
            }
        }
        float* o = gp + (size_t)qtr * GSEG + ((size_t)b * 64 + grp * 4) * 196 + p;
        o[0] = a.x; o[196] = a.y; o[392] = a.z; o[588] = a.w;
    }
}

__global__ void __launch_bounds__(224) cand_part_k(
    const float* __restrict__ bu, const float* __restrict__ h,
    const float* __restrict__ gp, const float* __restrict__ bg,
    const float* __restrict__ Wc, float* __restrict__ cp)
{
    __shared__ float sc[12 * 256];
    __shared__ float sw[12 * 36];
    const int b = blockIdx.x, grp = blockIdx.y, qtr = blockIdx.z;
    const int ic0 = qtr * 12;
    const int tid = threadIdx.x;
    for (int i = tid; i < 12 * 256; i += 224) sc[i] = 0.f;
    for (int i = tid; i < 12 * 36; i += 224) {
        int lic = i / 36, rem = i - lic * 36, q = rem >> 2, o = rem & 3;
        sw[i] = Wc[(grp * 4 + o) * 432 + (ic0 + lic) * 9 + q];
    }
    __syncthreads();
    for (int i = tid; i < 12 * 196; i += 224) {
        int lic = i / 196, p = i - lic * 196, y = p / 14, x = p - y * 14;
        int ic = ic0 + lic;
        float v;
        if (ic < IND) {
            v = bu[((size_t)b * IND + ic) * 196 + p];
        } else {
            int c = ic - IND;
            size_t gi = ((size_t)b * 64 + c) * 196 + p;
            float r = sigm(gp[gi] + gp[gi + GSEG] + gp[gi + 2 * (size_t)GSEG] +
                           gp[gi + 3 * (size_t)GSEG] + bg[c]);
            v = r * h[((size_t)b * HID + c) * 196 + p];
        }
        sc[lic * 256 + (y + 1) * 16 + (x + 1)] = v;
    }
    __syncthreads();
    if (tid < 196) {
        const int p = tid, y = p / 14, x = p - y * 14;
        float4 a = make_float4(0.f, 0.f, 0.f, 0.f);
        const float* cbase = sc + y * 16 + x;
        for (int lic = 0; lic < 12; ++lic) {
            float v[9];
            const float* cb = cbase + lic * 256;
#pragma unroll
            for (int dy = 0; dy < 3; dy++)
#pragma unroll
                for (int dx = 0; dx < 3; dx++) v[dy * 3 + dx] = cb[dy * 16 + dx];
            const float4* wq = (const float4*)(sw + lic * 36);
#pragma unroll
            for (int q = 0; q < 9; q++) {
                float4 w = wq[q];
                a.x += w.x * v[q]; a.y += w.y * v[q];
                a.z += w.z * v[q]; a.w += w.w * v[q];
            }
        }
        float* o = cp + (size_t)qtr * CSEG + ((size_t)b * 32 + grp * 4) * 196 + p;
        o[0] = a.x; o[196] = a.y; o[392] = a.z; o[588] = a.w;
    }
}

__global__ void cand_fin_k(const float* __restrict__ cp,
                           const float* __restrict__ bc,
                           const float* __restrict__ gp,
                           const float* __restrict__ bg,
                           const float* __restrict__ h,
                           float* __restrict__ hnew) {
    int i = blockIdx.x * 256 + threadIdx.x;
    if (i >= 16 * 32 * 196) return;
    int p = i % 196;
    int oc = (i / 196) & 31;
    int b = i / (32 * 196);
    float a = cp[i] + cp[i + (size_t)CSEG] + cp[i + 2 * (size_t)CSEG] +
              cp[i + 3 * (size_t)CSEG] + bc[oc];
    size_t gi = ((size_t)b * 64 + 32 + oc) * 196 + p;
    float z = sigm(gp[gi] + gp[gi + (size_t)GSEG] + gp[gi + 2 * (size_t)GSEG] +
                   gp[gi + 3 * (size_t)GSEG] + bg[32 + oc]);
    float ho = h[i];
    hnew[i] = (1.f - z) * ho + z * tanhf(a);
}

// ---------------- maxpool 3x3 s1 p1 + transpose to (K,16) ----------------
__device__ __forceinline__ void pool_one(const float* __restrict__ h,
                                         float* __restrict__ outT, int idx) {
    int b = idx & 15, k = idx >> 4;
    int c = k / 196, p = k - c * 196, y = p / 14, x = p - y * 14;
    const float* hp = h + ((size_t)b * HID + c) * 196;
    int y0 = y > 0 ? y - 1 : 0, y1 = y < 13 ? y + 1 : 13;
    int x0 = x > 0 ? x - 1 : 0, x1 = x < 13 ? x + 1 : 13;
    float m = -3.4e38f;
    for (int yy = y0; yy <= y1; ++yy)
        for (int xx = x0; xx <= x1; ++xx)
            m = fmaxf(m, hp[yy * 14 + xx]);
    outT[(size_t)k * 16 + b] = m;
}
__global__ void pool_k(const float* __restrict__ h, float* __restrict__ outT) {
    int idx = blockIdx.x * 256 + threadIdx.x;
    if (idx >= BB * KBIG) return;
    pool_one(h, outT, idx);
}
__global__ void pool2_k(const float* __restrict__ h0, float* __restrict__ dst0,
                        const float* __restrict__ h1, float* __restrict__ dst1) {
    int idx = blockIdx.x * 256 + threadIdx.x;
    if (idx >= BB * KBIG) return;
    if (blockIdx.z == 0) pool_one(h0, dst0, idx);
    else                 pool_one(h1, dst1, idx);
}

__global__ void xT_k(const float* __restrict__ x, float* __restrict__ xT) {
    int idx = blockIdx.x * 256 + threadIdx.x;
    if (idx >= TT * K0PAD * BB) return;
    int b = idx & 15;
    int r = idx >> 4;
    int k = r % K0PAD, t = r / K0PAD;
    float v = 0.f;
    if (k < K0) v = x[((size_t)b * TT + t) * K0 + k];
    xT[idx] = v;
}

__global__ void zero_k(float* p, int n) {
    int i = blockIdx.x * 256 + threadIdx.x;
    if (i < n) p[i] = 0.f;
}

// ---------------- fc tail ----------------
__global__ void __launch_bounds__(256) fc1_k(const float* __restrict__ h2,
                                             const float* __restrict__ w,
                                             const float* __restrict__ bias,
                                             float* __restrict__ out1) {
    __shared__ float red[256];
    int j = blockIdx.x, tid = threadIdx.x;
    float acc[16];
#pragma unroll
    for (int b = 0; b < 16; b++) acc[b] = 0.f;
    for (int k = tid; k < KBIG; k += 256) {
        float wv = w[(size_t)j * KBIG + k];
#pragma unroll
        for (int b = 0; b < 16; b++)
            acc[b] += wv * fmaxf(h2[(size_t)b * KBIG + k], 0.f);
    }
    for (int b = 0; b < 16; b++) {
        red[tid] = acc[b];
        __syncthreads();
        for (int sft = 128; sft; sft >>= 1) {
            if (tid < sft) red[tid] += red[tid + sft];
            __syncthreads();
        }
        if (tid == 0) out1[b * 100 + j] = fmaxf(red[0] + bias[j], 0.f);
        __syncthreads();
    }
}

__global__ void fc2_k(const float* __restrict__ p, const float* __restrict__ w,
                      const float* __restrict__ bias, float* __restrict__ out) {
    int t = threadIdx.x;
    if (t < 160) {
        int b = t / 10, j = t - b * 10;
        float a = bias[j];
        for (int k = 0; k < 100; k++) a += p[b * 100 + k] * w[j * 100 + k];
        out[b * 10 + j] = a;
    }
}

// ---------------- host orchestration ----------------
extern "C" void kernel_launch(void* const* d_in, const int* in_sizes, int n_in,
                              void* d_out, int out_size) {
    const float* x     = (const float*)d_in[0];
    const float* Wg    = (const float*)d_in[1];
    const float* bg    = (const float*)d_in[2];
    const float* Wc    = (const float*)d_in[3];
    const float* bc    = (const float*)d_in[4];
    const float* bu_w0 = (const float*)d_in[5];
    const float* bu_b0 = (const float*)d_in[6];
    const float* bu_w1 = (const float*)d_in[7];
    const float* bu_b1 = (const float*)d_in[8];
    const float* bu_w2 = (const float*)d_in[9];
    const float* bu_b2 = (const float*)d_in[10];
    const float* td_w0 = (const float*)d_in[11];
    const float* td_b0 = (const float*)d_in[12];
    const float* td_w1 = (const float*)d_in[13];
    const float* td_b1 = (const float*)d_in[14];
    const float* fc1_w = (const float*)d_in[15];
    const float* fc1_b = (const float*)d_in[16];
    const float* fc2_w = (const float*)d_in[17];
    const float* fc2_b = (const float*)d_in[18];
    float* out = (float*)d_out;

    float *hbuf, *xT, *pBU, *pTD, *bu, *td, *part, *partB, *gp, *cp, *fc1o;
    float *tdw0T, *tdw1T, *buw1T, *buw2T;
    cudaGetSymbolAddress((void**)&hbuf,  g_h);
    cudaGetSymbolAddress((void**)&xT,    g_xT);
    cudaGetSymbolAddress((void**)&pBU,   g_poolBU);
    cudaGetSymbolAddress((void**)&pTD,   g_poolTD);
    cudaGetSymbolAddress((void**)&bu,    g_bu);
    cudaGetSymbolAddress((void**)&td,    g_td);
    cudaGetSymbolAddress((void**)&part,  g_part);
    cudaGetSymbolAddress((void**)&partB, g_partB);
    cudaGetSymbolAddress((void**)&gp,    g_gp);
    cudaGetSymbolAddress((void**)&cp,    g_cp);
    cudaGetSymbolAddress((void**)&fc1o,  g_fc1o);
    cudaGetSymbolAddress((void**)&tdw0T, g_tdw0T);
    cudaGetSymbolAddress((void**)&tdw1T, g_tdw1T);
    cudaGetSymbolAddress((void**)&buw1T, g_buw1T);
    cudaGetSymbolAddress((void**)&buw2T, g_buw2T);

    const int hTot = 3 * 2 * BB * HID * HW;
    zero_k<<<(hTot + 255) / 256, 256>>>(hbuf, hTot);
    xT_k<<<(TT * K0PAD * BB + 255) / 256, 256>>>(x, xT);

    {
        dim3 tb(32, 8);
        trans2_k<<<dim3(KBIG / 32, NTD / 32, 2), tb>>>(td_w0, tdw0T,
                                                       td_w1, tdw1T, NTD);
        trans2_k<<<dim3(KBIG / 32, NBU / 32, 2), tb>>>(bu_w1, buw1T,
                                                       bu_w2, buw2T, NBU);
    }

    int cur[3] = {0, 0, 0};
    const size_t HSZ = (size_t)BB * HID * HW;
    const float* WgN[3] = {Wg, Wg + 27648, Wg + 2 * 27648};
    const float* bgN[3] = {bg, bg + 64, bg + 128};
    const float* WcN[3] = {Wc, Wc + 13824, Wc + 2 * 13824};
    const float* bcN[3] = {bc, bc + 32, bc + 64};
    const float* buB[3] = {bu_b0, bu_b1, bu_b2};
    const float* buWT[3] = {0, buw1T, buw2T};

    dim3 gateGrid(16, 16, 4), candGrid(16, 8, 4);
    const int poolBlocks = (BB * KBIG + 255) / 256;
    const int cFinB = (16 * 32 * 196 + 255) / 256;
    const int tdGx = (NTD + 511) / 512, buGx = (NBU + 511) / 512;
    const int tdRed = (16 * NTD + 255) / 256, buRed = (16 * NBU + 255) / 256;
    const int r2B = (16 * (NBU + NTD) + 255) / 256;
#define HPTR(n, p) (hbuf + ((size_t)(n) * 2 + (p)) * HSZ)

    for (int t = 0; t < TT + 2; t++) {
        // ---- node 0 (runs t < T) ----
        if (t < TT) {
            int hastd = (t >= 2);
            if (hastd) {
                pool_k<<<poolBlocks, 256>>>(HPTR(1, cur[1]), pTD);
                gemmT_k<<<dim3(tdGx, KS_TD), 256>>>(pTD, tdw0T, part, NTD, KS_TD);
                reduceN_k<<<tdRed, 256>>>(part, td_b0, td, NTD, KS_TD);
            }
            gemm_k<<<NBU / 16, 128>>>(xT + (size_t)t * K0PAD * 16, bu_w0, bu_b0,
                                      bu, K0, K0PAD, NBU);
            gate_part_k<<<gateGrid, 224>>>(bu, HPTR(0, cur[0]), td, WgN[0], gp, hastd);
            cand_part_k<<<candGrid, 224>>>(bu, HPTR(0, cur[0]), gp, bgN[0], WcN[0], cp);
            cand_fin_k<<<cFinB, 256>>>(cp, bcN[0], gp, bgN[0], HPTR(0, cur[0]),
                                       HPTR(0, 1 - cur[0]));
            cur[0] ^= 1;
        }
        // ---- nodes 1, 2 (run t >= 1) ----
        if (t >= 1) {
            // node 1
            {
                int hastd = (t >= 2);
                if (hastd) {
                    pool2_k<<<dim3(poolBlocks, 1, 2), 256>>>(
                        HPTR(0, cur[0]), pBU, HPTR(2, cur[2]), pTD);
                    gemmT2_k<<<dim3(tdGx, KS_BU + KS_TD), 256>>>(
                        pBU, buWT[1], partB, NBU, KS_BU,
                        pTD, tdw1T, part, NTD, KS_TD);
                    reduce2_k<<<r2B, 256>>>(partB, buB[1], bu, part, td_b1, td);
                } else {
                    pool_k<<<poolBlocks, 256>>>(HPTR(0, cur[0]), pBU);
                    gemmT_k<<<dim3(buGx, KS_BU), 256>>>(pBU, buWT[1], partB,
                                                        NBU, KS_BU);
                    reduceN_k<<<buRed, 256>>>(partB, buB[1], bu, NBU, KS_BU);
                }
                gate_part_k<<<gateGrid, 224>>>(bu, HPTR(1, cur[1]), td,
                                               WgN[1], gp, hastd);
                cand_part_k<<<candGrid, 224>>>(bu, HPTR(1, cur[1]), gp,
                                               bgN[1], WcN[1], cp);
                cand_fin_k<<<cFinB, 256>>>(cp, bcN[1], gp, bgN[1],
                                           HPTR(1, cur[1]), HPTR(1, 1 - cur[1]));
                cur[1] ^= 1;
            }
            // node 2 (no td)
            {
                pool_k<<<poolBlocks, 256>>>(HPTR(1, cur[1]), pBU);
                gemmT_k<<<dim3(buGx, KS_BU), 256>>>(pBU, buWT[2], partB, NBU, KS_BU);
                reduceN_k<<<buRed, 256>>>(partB, buB[2], bu, NBU, KS_BU);
                gate_part_k<<<gateGrid, 224>>>(bu, HPTR(2, cur[2]), td,
                                               WgN[2], gp, 0);
                cand_part_k<<<candGrid, 224>>>(bu, HPTR(2, cur[2]), gp,
                                               bgN[2], WcN[2], cp);
                cand_fin_k<<<cFinB, 256>>>(cp, bcN[2], gp, bgN[2],
                                           HPTR(2, cur[2]), HPTR(2, 1 - cur[2]));
                cur[2] ^= 1;
            }
        }
    }
    fc1_k<<<100, 256>>>(HPTR(2, cur[2]), fc1_w, fc1_b, fc1o);
    fc2_k<<<1, 192>>>(fc1o, fc2_w, fc2_b, out);
#undef HPTR
}

// round 13
// speedup vs baseline: 2.1808x; 1.0277x over previous
#include <cuda_runtime.h>
#include <math.h>

// ---------------- problem constants ----------------
#define BB 16
#define TT 8
#define HW 196
#define HID 32
#define IND 16
#define KBIG 6272       // HID*HW
#define K0 588          // CIN*HW
#define K0PAD 640
#define NBU 3136        // IND*HW
#define NTD 9408        // (IND+HID)*HW
#define KS_TD 24
#define KS_BU 49
#define KS_B0 5
#define GSEG (16 * 64 * 196)
#define CSEG (16 * 32 * 196)

// ---------------- device scratch (no allocs allowed) ----------------
__device__ float g_h[3 * 2 * BB * HID * HW];   // hidden, double buffered
__device__ float g_xT[TT * K0PAD * BB];        // transposed+padded input slices
__device__ float g_poolBU[KBIG * BB];
__device__ float g_poolTD[KBIG * BB];
__device__ float g_bu[BB * NBU];
__device__ float g_td[BB * NTD];
__device__ float g_part[KS_TD * BB * NTD];     // td K-split partials
__device__ float g_partB[KS_BU * BB * NBU];    // bu K-split partials
__device__ float g_gp[4 * BB * 64 * HW];       // gate conv ic-split partials (4)
__device__ float g_cp[4 * BB * 32 * HW];       // cand conv ic-split partials (4)
__device__ float g_fc1o[BB * 100];
// transposed weights (k-major), rebuilt every call
__device__ float g_tdw0T[(size_t)KBIG * NTD];
__device__ float g_tdw1T[(size_t)KBIG * NTD];
__device__ float g_buw1T[(size_t)KBIG * NBU];
__device__ float g_buw2T[(size_t)KBIG * NBU];
__device__ float g_buw0T[(size_t)K0PAD * NBU];

// ---------------- f32x2 helpers ----------------
__device__ __forceinline__ unsigned long long pack2(float v) {
    unsigned long long r;
    asm("mov.b64 %0, {%1, %1};" : "=l"(r) : "f"(v));
    return r;
}
__device__ __forceinline__ void fma2(unsigned long long& d, unsigned long long a,
                                     unsigned long long b) {
    asm("fma.rn.f32x2 %0, %1, %2, %0;" : "+l"(d) : "l"(a), "l"(b));
}
__device__ __forceinline__ float sigm(float a) { return 1.f / (1.f + expf(-a)); }

// ---------------- merged 32x32 tiled transpose: 2 same-shape matrices ----------------
__global__ void trans2_k(const float* __restrict__ Wa, float* __restrict__ WTa,
                         const float* __restrict__ Wb, float* __restrict__ WTb,
                         int Nout) {
    __shared__ float t[32][33];
    const float* W  = blockIdx.z ? Wb  : Wa;
    float*       WT = blockIdx.z ? WTb : WTa;
    const int kb = blockIdx.x * 32, nb = blockIdx.y * 32;
    const int tx = threadIdx.x, ty = threadIdx.y;   // 32 x 8
#pragma unroll
    for (int i = 0; i < 32; i += 8)
        t[ty + i][tx] = W[(size_t)(nb + ty + i) * KBIG + kb + tx];
    __syncthreads();
#pragma unroll
    for (int i = 0; i < 32; i += 8)
        WT[(size_t)(kb + ty + i) * Nout + nb + tx] = t[tx][ty + i];
}

// padded transpose: W (Nout x K0) -> WT (K0PAD x Nout), rows >= K0 zeroed
__global__ void trans_pad_k(const float* __restrict__ W, float* __restrict__ WT,
                            int Nout) {
    __shared__ float t[32][33];
    const int kb = blockIdx.x * 32, nb = blockIdx.y * 32;
    const int tx = threadIdx.x, ty = threadIdx.y;   // 32 x 8
#pragma unroll
    for (int i = 0; i < 32; i += 8) {
        int k = kb + tx;
        t[ty + i][tx] = (k < K0) ? W[(size_t)(nb + ty + i) * K0 + k] : 0.f;
    }
    __syncthreads();
#pragma unroll
    for (int i = 0; i < 32; i += 8) {
        int k = kb + ty + i;
        if (k < K0PAD) WT[(size_t)k * Nout + nb + tx] = t[tx][ty + i];
    }
}

// ================= gemmT core (Kpad-parameterized) =================
__device__ __forceinline__ void gemmT_core(
    float* sa, const float* __restrict__ act, const float* __restrict__ WT,
    float* __restrict__ part, int Nout, int KS, int ks, int bx, int Kpad)
{
    const int tid = threadIdx.x;
    const int n0raw = bx * 512 + tid * 2;
    const bool act_n = n0raw < Nout;
    const int n0 = act_n ? n0raw : (Nout - 2);
    const int slabs = Kpad >> 7;
    const int s0 = slabs * ks / KS, s1 = slabs * (ks + 1) / KS;
    const int ns = s1 - s0;                        // 1..3 slabs
    const int kn = ns * 128;

    {
        const float4* src = (const float4*)act + (size_t)s0 * 512;
        for (int f = tid; f < ns * 512; f += 256) {
            float4 v = src[f];
            *(float4*)(&sa[(f >> 2) * 16 + (f & 3) * 4]) = v;
        }
    }

    unsigned long long acc[2][8];
#pragma unroll
    for (int n = 0; n < 2; n++)
#pragma unroll
        for (int p = 0; p < 8; p++) acc[n][p] = 0ull;

    const float* wp = WT + (size_t)(s0 * 128) * Nout + n0;
    float2 wb[2][8];
#pragma unroll
    for (int u = 0; u < 8; u++)
        wb[0][u] = *(const float2*)(wp + (size_t)u * Nout);

    __syncthreads();

    for (int k0 = 0; k0 < kn; k0 += 8) {
        const int cur = (k0 >> 3) & 1;
        const float* wpn = wp + (size_t)8 * Nout;
        if (k0 + 8 < kn) {
#pragma unroll
            for (int u = 0; u < 8; u++)
                wb[cur ^ 1][u] = *(const float2*)(wpn + (size_t)u * Nout);
        }
#pragma unroll
        for (int u = 0; u < 8; u++) {
            const ulonglong2* ap = (const ulonglong2*)(sa + (k0 + u) * 16);
            ulonglong2 u0 = ap[0], u1 = ap[1], u2 = ap[2], u3 = ap[3];
            unsigned long long av[8] = {u0.x, u0.y, u1.x, u1.y,
                                        u2.x, u2.y, u3.x, u3.y};
            unsigned long long w0 = pack2(wb[cur][u].x);
            unsigned long long w1 = pack2(wb[cur][u].y);
#pragma unroll
            for (int p = 0; p < 8; p++) fma2(acc[0][p], w0, av[p]);
#pragma unroll
            for (int p = 0; p < 8; p++) fma2(acc[1][p], w1, av[p]);
        }
        wp = wpn;
    }
    if (act_n) {
        float* op = part + (size_t)ks * 16 * Nout + n0;
#pragma unroll
        for (int b = 0; b < 16; b++) {
            unsigned long long v0 = acc[0][b >> 1], v1 = acc[1][b >> 1];
            float f0 = (b & 1) ? __uint_as_float((unsigned)(v0 >> 32))
                               : __uint_as_float((unsigned)v0);
            float f1 = (b & 1) ? __uint_as_float((unsigned)(v1 >> 32))
                               : __uint_as_float((unsigned)v1);
            op[(size_t)b * Nout + 0] = f0;
            op[(size_t)b * Nout + 1] = f1;
        }
    }
}

__global__ void __launch_bounds__(256) gemmT_k(
    const float* __restrict__ act, const float* __restrict__ WT,
    float* __restrict__ part, int Nout, int KS, int Kpad)
{
    __shared__ float sa[3 * 128 * 16];
    gemmT_core(sa, act, WT, part, Nout, KS, blockIdx.y, blockIdx.x, Kpad);
}

// merged launch: y < KSA -> problem A, else problem B (co-scheduled blocks)
__global__ void __launch_bounds__(256) gemmT2_k(
    const float* __restrict__ actA, const float* __restrict__ WTA,
    float* __restrict__ partA, int NoutA, int KSA, int KpadA,
    const float* __restrict__ actB, const float* __restrict__ WTB,
    float* __restrict__ partB, int NoutB, int KSB, int KpadB)
{
    __shared__ float sa[3 * 128 * 16];
    const int y = blockIdx.y, bx = blockIdx.x;
    if (y < KSA) {
        if (bx * 512 >= NoutA) return;
        gemmT_core(sa, actA, WTA, partA, NoutA, KSA, y, bx, KpadA);
    } else {
        if (bx * 512 >= NoutB) return;
        gemmT_core(sa, actB, WTB, partB, NoutB, KSB, y - KSA, bx, KpadB);
    }
}

__global__ void reduceN_k(const float* __restrict__ part,
                          const float* __restrict__ bias,
                          float* __restrict__ out, int Nout, int KS) {
    int i = blockIdx.x * 256 + threadIdx.x;
    if (i >= 16 * Nout) return;
    int n = i % Nout;
    float a = bias[n];
    for (int ks = 0; ks < KS; ks++) a += part[(size_t)ks * 16 * Nout + i];
    out[i] = a;
}

// merged reduce: problem A (first 16*NA threads) then problem B
__global__ void reduce2_k(const float* __restrict__ pA,
                          const float* __restrict__ bA, float* __restrict__ oA,
                          int NA, int KSA,
                          const float* __restrict__ pB,
                          const float* __restrict__ bB, float* __restrict__ oB,
                          int NB, int KSB) {
    int i = blockIdx.x * 256 + threadIdx.x;
    if (i < 16 * NA) {
        int n = i % NA;
        float a = bA[n];
        for (int ks = 0; ks < KSA; ks++) a += pA[(size_t)ks * 16 * NA + i];
        oA[i] = a;
    } else {
        int j = i - 16 * NA;
        if (j >= 16 * NB) return;
        int n = j % NB;
        float a = bB[n];
        for (int ks = 0; ks < KSB; ks++) a += pB[(size_t)ks * 16 * NB + j];
        oB[j] = a;
    }
}

// ================= conv: ic-split x4 partial kernels =================
__global__ void __launch_bounds__(224) gate_part_k(
    const float* __restrict__ bu, const float* __restrict__ h,
    const float* __restrict__ td, const float* __restrict__ Wg,
    float* __restrict__ gp, int has_td)
{
    __shared__ float sc[12 * 256];
    __shared__ float sw[12 * 36];
    const int b = blockIdx.x, grp = blockIdx.y, qtr = blockIdx.z;
    const int ic0 = qtr * 12;
    const int tid = threadIdx.x;
    for (int i = tid; i < 12 * 256; i += 224) sc[i] = 0.f;
    for (int i = tid; i < 12 * 36; i += 224) {
        int lic = i / 36, rem = i - lic * 36, q = rem >> 2, o = rem & 3;
        sw[i] = Wg[(grp * 4 + o) * 432 + (ic0 + lic) * 9 + q];
    }
    __syncthreads();
    for (int i = tid; i < 12 * 196; i += 224) {
        int lic = i / 196, p = i - lic * 196, y = p / 14, x = p - y * 14;
        int ic = ic0 + lic;
        float v = (ic < IND) ? bu[((size_t)b * IND + ic) * 196 + p]
                             : h[((size_t)b * HID + (ic - IND)) * 196 + p];
        if (has_td) v += td[((size_t)b * 48 + ic) * 196 + p];
        sc[lic * 256 + (y + 1) * 16 + (x + 1)] = v;
    }
    __syncthreads();
    if (tid < 196) {
        const int p = tid, y = p / 14, x = p - y * 14;
        float4 a = make_float4(0.f, 0.f, 0.f, 0.f);
        const float* cbase = sc + y * 16 + x;
        for (int lic = 0; lic < 12; ++lic) {
            float v[9];
            const float* cb = cbase + lic * 256;
#pragma unroll
            for (int dy = 0; dy < 3; dy++)
#pragma unroll
                for (int dx = 0; dx < 3; dx++) v[dy * 3 + dx] = cb[dy * 16 + dx];
            const float4* wq = (const float4*)(sw + lic * 36);
#pragma unroll
            for (int q = 0; q < 9; q++) {
                float4 w = wq[q];
                a.x += w.x * v[q]; a.y += w.y * v[q];
                a.z += w.z * v[q]; a.w += w.w * v[q];
            }
        }
        float* o = gp + (size_t)qtr * GSEG + ((size_t)b * 64 + grp * 4) * 196 + p;
        o[0] = a.x; o[196] = a.y; o[392] = a.z; o[588] = a.w;
    }
}

__global__ void __launch_bounds__(224) cand_part_k(
    const float* __restrict__ bu, const float* __restrict__ h,
    const float* __restrict__ gp, const float* __restrict__ bg,
    const float* __restrict__ Wc, float* __restrict__ cp)
{
    __shared__ float sc[12 * 256];
    __shared__ float sw[12 * 36];
    const int b = blockIdx.x, grp = blockIdx.y, qtr = blockIdx.z;
    const int ic0 = qtr * 12;
    const int tid = threadIdx.x;
    for (int i = tid; i < 12 * 256; i += 224) sc[i] = 0.f;
    for (int i = tid; i < 12 * 36; i += 224) {
        int lic = i / 36, rem = i - lic * 36, q = rem >> 2, o = rem & 3;
        sw[i] = Wc[(grp * 4 + o) * 432 + (ic0 + lic) * 9 + q];
    }
    __syncthreads();
    for (int i = tid; i < 12 * 196; i += 224) {
        int lic = i / 196, p = i - lic * 196, y = p / 14, x = p - y * 14;
        int ic = ic0 + lic;
        float v;
        if (ic < IND) {
            v = bu[((size_t)b * IND + ic) * 196 + p];
        } else {
            int c = ic - IND;
            size_t gi = ((size_t)b * 64 + c) * 196 + p;
            float r = sigm(gp[gi] + gp[gi + GSEG] + gp[gi + 2 * (size_t)GSEG] +
                           gp[gi + 3 * (size_t)GSEG] + bg[c]);
            v = r * h[((size_t)b * HID + c) * 196 + p];
        }
        sc[lic * 256 + (y + 1) * 16 + (x + 1)] = v;
    }
    __syncthreads();
    if (tid < 196) {
        const int p = tid, y = p / 14, x = p - y * 14;
        float4 a = make_float4(0.f, 0.f, 0.f, 0.f);
        const float* cbase = sc + y * 16 + x;
        for (int lic = 0; lic < 12; ++lic) {
            float v[9];
            const float* cb = cbase + lic * 256;
#pragma unroll
            for (int dy = 0; dy < 3; dy++)
#pragma unroll
                for (int dx = 0; dx < 3; dx++) v[dy * 3 + dx] = cb[dy * 16 + dx];
            const float4* wq = (const float4*)(sw + lic * 36);
#pragma unroll
            for (int q = 0; q < 9; q++) {
                float4 w = wq[q];
                a.x += w.x * v[q]; a.y += w.y * v[q];
                a.z += w.z * v[q]; a.w += w.w * v[q];
            }
        }
        float* o = cp + (size_t)qtr * CSEG + ((size_t)b * 32 + grp * 4) * 196 + p;
        o[0] = a.x; o[196] = a.y; o[392] = a.z; o[588] = a.w;
    }
}

__global__ void cand_fin_k(const float* __restrict__ cp,
                           const float* __restrict__ bc,
                           const float* __restrict__ gp,
                           const float* __restrict__ bg,
                           const float* __restrict__ h,
                           float* __restrict__ hnew) {
    int i = blockIdx.x * 256 + threadIdx.x;
    if (i >= 16 * 32 * 196) return;
    int p = i % 196;
    int oc = (i / 196) & 31;
    int b = i / (32 * 196);
    float a = cp[i] + cp[i + (size_t)CSEG] + cp[i + 2 * (size_t)CSEG] +
              cp[i + 3 * (size_t)CSEG] + bc[oc];
    size_t gi = ((size_t)b * 64 + 32 + oc) * 196 + p;
    float z = sigm(gp[gi] + gp[gi + (size_t)GSEG] + gp[gi + 2 * (size_t)GSEG] +
                   gp[gi + 3 * (size_t)GSEG] + bg[32 + oc]);
    float ho = h[i];
    hnew[i] = (1.f - z) * ho + z * tanhf(a);
}

// ---------------- maxpool 3x3 s1 p1 + transpose to (K,16) ----------------
__device__ __forceinline__ void pool_one(const float* __restrict__ h,
                                         float* __restrict__ outT, int idx) {
    int b = idx & 15, k = idx >> 4;
    int c = k / 196, p = k - c * 196, y = p / 14, x = p - y * 14;
    const float* hp = h + ((size_t)b * HID + c) * 196;
    int y0 = y > 0 ? y - 1 : 0, y1 = y < 13 ? y + 1 : 13;
    int x0 = x > 0 ? x - 1 : 0, x1 = x < 13 ? x + 1 : 13;
    float m = -3.4e38f;
    for (int yy = y0; yy <= y1; ++yy)
        for (int xx = x0; xx <= x1; ++xx)
            m = fmaxf(m, hp[yy * 14 + xx]);
    outT[(size_t)k * 16 + b] = m;
}
__global__ void pool_k(const float* __restrict__ h, float* __restrict__ outT) {
    int idx = blockIdx.x * 256 + threadIdx.x;
    if (idx >= BB * KBIG) return;
    pool_one(h, outT, idx);
}
__global__ void pool2_k(const float* __restrict__ h0, float* __restrict__ dst0,
                        const float* __restrict__ h1, float* __restrict__ dst1) {
    int idx = blockIdx.x * 256 + threadIdx.x;
    if (idx >= BB * KBIG) return;
    if (blockIdx.z == 0) pool_one(h0, dst0, idx);
    else                 pool_one(h1, dst1, idx);
}

__global__ void xT_k(const float* __restrict__ x, float* __restrict__ xT) {
    int idx = blockIdx.x * 256 + threadIdx.x;
    if (idx >= TT * K0PAD * BB) return;
    int b = idx & 15;
    int r = idx >> 4;
    int k = r % K0PAD, t = r / K0PAD;
    float v = 0.f;
    if (k < K0) v = x[((size_t)b * TT + t) * K0 + k];
    xT[idx] = v;
}

__global__ void zero_k(float* p, int n) {
    int i = blockIdx.x * 256 + threadIdx.x;
    if (i < n) p[i] = 0.f;
}

// ---------------- fc tail ----------------
__global__ void __launch_bounds__(256) fc1_k(const float* __restrict__ h2,
                                             const float* __restrict__ w,
                                             const float* __restrict__ bias,
                                             float* __restrict__ out1) {
    __shared__ float red[256];
    int j = blockIdx.x, tid = threadIdx.x;
    float acc[16];
#pragma unroll
    for (int b = 0; b < 16; b++) acc[b] = 0.f;
    for (int k = tid; k < KBIG; k += 256) {
        float wv = w[(size_t)j * KBIG + k];
#pragma unroll
        for (int b = 0; b < 16; b++)
            acc[b] += wv * fmaxf(h2[(size_t)b * KBIG + k], 0.f);
    }
    for (int b = 0; b < 16; b++) {
        red[tid] = acc[b];
        __syncthreads();
        for (int sft = 128; sft; sft >>= 1) {
            if (tid < sft) red[tid] += red[tid + sft];
            __syncthreads();
        }
        if (tid == 0) out1[b * 100 + j] = fmaxf(red[0] + bias[j], 0.f);
        __syncthreads();
    }
}

__global__ void fc2_k(const float* __restrict__ p, const float* __restrict__ w,
                      const float* __restrict__ bias, float* __restrict__ out) {
    int t = threadIdx.x;
    if (t < 160) {
        int b = t / 10, j = t - b * 10;
        float a = bias[j];
        for (int k = 0; k < 100; k++) a += p[b * 100 + k] * w[j * 100 + k];
        out[b * 10 + j] = a;
    }
}

// ---------------- host orchestration ----------------
extern "C" void kernel_launch(void* const* d_in, const int* in_sizes, int n_in,
                              void* d_out, int out_size) {
    const float* x     = (const float*)d_in[0];
    const float* Wg    = (const float*)d_in[1];
    const float* bg    = (const float*)d_in[2];
    const float* Wc    = (const float*)d_in[3];
    const float* bc    = (const float*)d_in[4];
    const float* bu_w0 = (const float*)d_in[5];
    const float* bu_b0 = (const float*)d_in[6];
    const float* bu_w1 = (const float*)d_in[7];
    const float* bu_b1 = (const float*)d_in[8];
    const float* bu_w2 = (const float*)d_in[9];
    const float* bu_b2 = (const float*)d_in[10];
    const float* td_w0 = (const float*)d_in[11];
    const float* td_b0 = (const float*)d_in[12];
    const float* td_w1 = (const float*)d_in[13];
    const float* td_b1 = (const float*)d_in[14];
    const float* fc1_w = (const float*)d_in[15];
    const float* fc1_b = (const float*)d_in[16];
    const float* fc2_w = (const float*)d_in[17];
    const float* fc2_b = (const float*)d_in[18];
    float* out = (float*)d_out;

    float *hbuf, *xT, *pBU, *pTD, *bu, *td, *part, *partB, *gp, *cp, *fc1o;
    float *tdw0T, *tdw1T, *buw1T, *buw2T, *buw0T;
    cudaGetSymbolAddress((void**)&hbuf,  g_h);
    cudaGetSymbolAddress((void**)&xT,    g_xT);
    cudaGetSymbolAddress((void**)&pBU,   g_poolBU);
    cudaGetSymbolAddress((void**)&pTD,   g_poolTD);
    cudaGetSymbolAddress((void**)&bu,    g_bu);
    cudaGetSymbolAddress((void**)&td,    g_td);
    cudaGetSymbolAddress((void**)&part,  g_part);
    cudaGetSymbolAddress((void**)&partB, g_partB);
    cudaGetSymbolAddress((void**)&gp,    g_gp);
    cudaGetSymbolAddress((void**)&cp,    g_cp);
    cudaGetSymbolAddress((void**)&fc1o,  g_fc1o);
    cudaGetSymbolAddress((void**)&tdw0T, g_tdw0T);
    cudaGetSymbolAddress((void**)&tdw1T, g_tdw1T);
    cudaGetSymbolAddress((void**)&buw1T, g_buw1T);
    cudaGetSymbolAddress((void**)&buw2T, g_buw2T);
    cudaGetSymbolAddress((void**)&buw0T, g_buw0T);

    const int hTot = 3 * 2 * BB * HID * HW;
    zero_k<<<(hTot + 255) / 256, 256>>>(hbuf, hTot);
    xT_k<<<(TT * K0PAD * BB + 255) / 256, 256>>>(x, xT);

    {
        dim3 tb(32, 8);
        trans2_k<<<dim3(KBIG / 32, NTD / 32, 2), tb>>>(td_w0, tdw0T,
                                                       td_w1, tdw1T, NTD);
        trans2_k<<<dim3(KBIG / 32, NBU / 32, 2), tb>>>(bu_w1, buw1T,
                                                       bu_w2, buw2T, NBU);
        trans_pad_k<<<dim3(K0PAD / 32, NBU / 32), tb>>>(bu_w0, buw0T, NBU);
    }

    int cur[3] = {0, 0, 0};
    const size_t HSZ = (size_t)BB * HID * HW;
    const float* WgN[3] = {Wg, Wg + 27648, Wg + 2 * 27648};
    const float* bgN[3] = {bg, bg + 64, bg + 128};
    const float* WcN[3] = {Wc, Wc + 13824, Wc + 2 * 13824};
    const float* bcN[3] = {bc, bc + 32, bc + 64};
    const float* buB[3] = {bu_b0, bu_b1, bu_b2};
    const float* buWT[3] = {buw0T, buw1T, buw2T};

    dim3 gateGrid(16, 16, 4), candGrid(16, 8, 4);
    const int poolBlocks = (BB * KBIG + 255) / 256;
    const int cFinB = (16 * 32 * 196 + 255) / 256;
    const int tdGx = (NTD + 511) / 512, buGx = (NBU + 511) / 512;
    const int buRed = (16 * NBU + 255) / 256;
    const int tdRed = (16 * NTD + 255) / 256;
    const int r2B = (16 * (NBU + NTD) + 255) / 256;
#define HPTR(n, p) (hbuf + ((size_t)(n) * 2 + (p)) * HSZ)

    for (int t = 0; t < TT + 2; t++) {
        // ---- node 0 (runs t < T) ----
        if (t < TT) {
            int hastd = (t >= 2);
            const float* x0 = xT + (size_t)t * K0PAD * 16;
            if (hastd) {
                pool_k<<<poolBlocks, 256>>>(HPTR(1, cur[1]), pTD);
                // merged: td0 (KS_TD) + bu0 (KS_B0, Kpad=640) co-scheduled
                gemmT2_k<<<dim3(tdGx, KS_TD + KS_B0), 256>>>(
                    pTD, tdw0T, part, NTD, KS_TD, KBIG,
                    x0, buWT[0], partB, NBU, KS_B0, K0PAD);
                reduce2_k<<<r2B, 256>>>(partB, buB[0], bu, NBU, KS_B0,
                                        part, td_b0, td, NTD, KS_TD);
            } else {
                gemmT_k<<<dim3(buGx, KS_B0), 256>>>(x0, buWT[0], partB,
                                                    NBU, KS_B0, K0PAD);
                reduceN_k<<<buRed, 256>>>(partB, buB[0], bu, NBU, KS_B0);
            }
            gate_part_k<<<gateGrid, 224>>>(bu, HPTR(0, cur[0]), td, WgN[0], gp, hastd);
            cand_part_k<<<candGrid, 224>>>(bu, HPTR(0, cur[0]), gp, bgN[0], WcN[0], cp);
            cand_fin_k<<<cFinB, 256>>>(cp, bcN[0], gp, bgN[0], HPTR(0, cur[0]),
                                       HPTR(0, 1 - cur[0]));
            cur[0] ^= 1;
        }
        // ---- nodes 1, 2 (run t >= 1) ----
        if (t >= 1) {
            // node 1
            {
                int hastd = (t >= 2);
                if (hastd) {
                    pool2_k<<<dim3(poolBlocks, 1, 2), 256>>>(
                        HPTR(0, cur[0]), pBU, HPTR(2, cur[2]), pTD);
                    gemmT2_k<<<dim3(tdGx, KS_BU + KS_TD), 256>>>(
                        pBU, buWT[1], partB, NBU, KS_BU, KBIG,
                        pTD, tdw1T, part, NTD, KS_TD, KBIG);
                    reduce2_k<<<r2B, 256>>>(partB, buB[1], bu, NBU, KS_BU,
                                            part, td_b1, td, NTD, KS_TD);
                } else {
                    pool_k<<<poolBlocks, 256>>>(HPTR(0, cur[0]), pBU);
                    gemmT_k<<<dim3(buGx, KS_BU), 256>>>(pBU, buWT[1], partB,
                                                        NBU, KS_BU, KBIG);
                    reduceN_k<<<buRed, 256>>>(partB, buB[1], bu, NBU, KS_BU);
                }
                gate_part_k<<<gateGrid, 224>>>(bu, HPTR(1, cur[1]), td,
                                               WgN[1], gp, hastd);
                cand_part_k<<<candGrid, 224>>>(bu, HPTR(1, cur[1]), gp,
                                               bgN[1], WcN[1], cp);
                cand_fin_k<<<cFinB, 256>>>(cp, bcN[1], gp, bgN[1],
                                           HPTR(1, cur[1]), HPTR(1, 1 - cur[1]));
                cur[1] ^= 1;
            }
            // node 2 (no td)
            {
                pool_k<<<poolBlocks, 256>>>(HPTR(1, cur[1]), pBU);
                gemmT_k<<<dim3(buGx, KS_BU), 256>>>(pBU, buWT[2], partB,
                                                    NBU, KS_BU, KBIG);
                reduceN_k<<<buRed, 256>>>(partB, buB[2], bu, NBU, KS_BU);
                gate_part_k<<<gateGrid, 224>>>(bu, HPTR(2, cur[2]), td,
                                               WgN[2], gp, 0);
                cand_part_k<<<candGrid, 224>>>(bu, HPTR(2, cur[2]), gp,
                                               bgN[2], WcN[2], cp);
                cand_fin_k<<<cFinB, 256>>>(cp, bcN[2], gp, bgN[2],
                                           HPTR(2, cur[2]), HPTR(2, 1 - cur[2]));
                cur[2] ^= 1;
            }
        }
    }
    fc1_k<<<100, 256>>>(HPTR(2, cur[2]), fc1_w, fc1_b, fc1o);
    fc2_k<<<1, 192>>>(fc1o, fc2_w, fc2_b, out);
#undef HPTR
}

// round 14
// speedup vs baseline: 2.2756x; 1.0435x over previous
#include <cuda_runtime.h>
#include <math.h>

// ---------------- problem constants ----------------
#define BB 16
#define TT 8
#define HW 196
#define HID 32
#define IND 16
#define KBIG 6272       // HID*HW
#define K0 588          // CIN*HW
#define K0PAD 640
#define NBU 3136        // IND*HW
#define NTD 9408        // (IND+HID)*HW
#define KS_TD 24
#define KS_BU 49
#define KS_B0 5
#define GSEG (16 * 64 * 196)
#define CSEG (16 * 32 * 196)

// ---------------- device scratch (no allocs allowed) ----------------
__device__ float g_h[3 * 2 * BB * HID * HW];   // hidden, double buffered
__device__ float g_xT[TT * K0PAD * BB];        // transposed+padded input slices
__device__ float g_poolBU[KBIG * BB];
__device__ float g_poolTD[KBIG * BB];          // shared pool in PAIR phase
__device__ float g_bu[BB * NBU];               // node1/node2 bu
__device__ float g_bu0[BB * NBU];              // node0 bu (pair)
__device__ float g_td[BB * NTD];
__device__ float g_part[KS_TD * BB * NTD];     // td K-split partials
__device__ float g_partB[KS_BU * BB * NBU];    // bu K-split partials
__device__ float g_partB0[KS_B0 * BB * NBU];   // bu0 K-split partials
__device__ float g_gp[4 * GSEG];               // gate partials (node1/2)
__device__ float g_cp[4 * CSEG];
__device__ float g_gp0[4 * GSEG];              // gate partials (node0 in pair)
__device__ float g_cp0[4 * CSEG];
__device__ float g_fc1o[BB * 100];
// transposed weights (k-major), rebuilt every call
__device__ float g_tdw0T[(size_t)KBIG * NTD];
__device__ float g_tdw1T[(size_t)KBIG * NTD];
__device__ float g_buw1T[(size_t)KBIG * NBU];
__device__ float g_buw2T[(size_t)KBIG * NBU];
__device__ float g_buw0T[(size_t)K0PAD * NBU];

// ---------------- f32x2 helpers ----------------
__device__ __forceinline__ unsigned long long pack2(float v) {
    unsigned long long r;
    asm("mov.b64 %0, {%1, %1};" : "=l"(r) : "f"(v));
    return r;
}
__device__ __forceinline__ void fma2(unsigned long long& d, unsigned long long a,
                                     unsigned long long b) {
    asm("fma.rn.f32x2 %0, %1, %2, %0;" : "+l"(d) : "l"(a), "l"(b));
}
__device__ __forceinline__ float sigm(float a) { return 1.f / (1.f + expf(-a)); }

// ---------------- transposes ----------------
__global__ void trans2_k(const float* __restrict__ Wa, float* __restrict__ WTa,
                         const float* __restrict__ Wb, float* __restrict__ WTb,
                         int Nout) {
    __shared__ float t[32][33];
    const float* W  = blockIdx.z ? Wb  : Wa;
    float*       WT = blockIdx.z ? WTb : WTa;
    const int kb = blockIdx.x * 32, nb = blockIdx.y * 32;
    const int tx = threadIdx.x, ty = threadIdx.y;   // 32 x 8
#pragma unroll
    for (int i = 0; i < 32; i += 8)
        t[ty + i][tx] = W[(size_t)(nb + ty + i) * KBIG + kb + tx];
    __syncthreads();
#pragma unroll
    for (int i = 0; i < 32; i += 8)
        WT[(size_t)(kb + ty + i) * Nout + nb + tx] = t[tx][ty + i];
}

__global__ void trans_pad_k(const float* __restrict__ W, float* __restrict__ WT,
                            int Nout) {
    __shared__ float t[32][33];
    const int kb = blockIdx.x * 32, nb = blockIdx.y * 32;
    const int tx = threadIdx.x, ty = threadIdx.y;
#pragma unroll
    for (int i = 0; i < 32; i += 8) {
        int k = kb + tx;
        t[ty + i][tx] = (k < K0) ? W[(size_t)(nb + ty + i) * K0 + k] : 0.f;
    }
    __syncthreads();
#pragma unroll
    for (int i = 0; i < 32; i += 8) {
        int k = kb + ty + i;
        if (k < K0PAD) WT[(size_t)k * Nout + nb + tx] = t[tx][ty + i];
    }
}

// ================= gemmT core =================
__device__ __forceinline__ void gemmT_core(
    float* sa, const float* __restrict__ act, const float* __restrict__ WT,
    float* __restrict__ part, int Nout, int KS, int ks, int bx, int Kpad)
{
    const int tid = threadIdx.x;
    const int n0raw = bx * 512 + tid * 2;
    const bool act_n = n0raw < Nout;
    const int n0 = act_n ? n0raw : (Nout - 2);
    const int slabs = Kpad >> 7;
    const int s0 = slabs * ks / KS, s1 = slabs * (ks + 1) / KS;
    const int ns = s1 - s0;
    const int kn = ns * 128;

    {
        const float4* src = (const float4*)act + (size_t)s0 * 512;
        for (int f = tid; f < ns * 512; f += 256) {
            float4 v = src[f];
            *(float4*)(&sa[(f >> 2) * 16 + (f & 3) * 4]) = v;
        }
    }

    unsigned long long acc[2][8];
#pragma unroll
    for (int n = 0; n < 2; n++)
#pragma unroll
        for (int p = 0; p < 8; p++) acc[n][p] = 0ull;

    const float* wp = WT + (size_t)(s0 * 128) * Nout + n0;
    float2 wb[2][8];
#pragma unroll
    for (int u = 0; u < 8; u++)
        wb[0][u] = *(const float2*)(wp + (size_t)u * Nout);

    __syncthreads();

    for (int k0 = 0; k0 < kn; k0 += 8) {
        const int cur = (k0 >> 3) & 1;
        const float* wpn = wp + (size_t)8 * Nout;
        if (k0 + 8 < kn) {
#pragma unroll
            for (int u = 0; u < 8; u++)
                wb[cur ^ 1][u] = *(const float2*)(wpn + (size_t)u * Nout);
        }
#pragma unroll
        for (int u = 0; u < 8; u++) {
            const ulonglong2* ap = (const ulonglong2*)(sa + (k0 + u) * 16);
            ulonglong2 u0 = ap[0], u1 = ap[1], u2 = ap[2], u3 = ap[3];
            unsigned long long av[8] = {u0.x, u0.y, u1.x, u1.y,
                                        u2.x, u2.y, u3.x, u3.y};
            unsigned long long w0 = pack2(wb[cur][u].x);
            unsigned long long w1 = pack2(wb[cur][u].y);
#pragma unroll
            for (int p = 0; p < 8; p++) fma2(acc[0][p], w0, av[p]);
#pragma unroll
            for (int p = 0; p < 8; p++) fma2(acc[1][p], w1, av[p]);
        }
        wp = wpn;
    }
    if (act_n) {
        float* op = part + (size_t)ks * 16 * Nout + n0;
#pragma unroll
        for (int b = 0; b < 16; b++) {
            unsigned long long v0 = acc[0][b >> 1], v1 = acc[1][b >> 1];
            float f0 = (b & 1) ? __uint_as_float((unsigned)(v0 >> 32))
                               : __uint_as_float((unsigned)v0);
            float f1 = (b & 1) ? __uint_as_float((unsigned)(v1 >> 32))
                               : __uint_as_float((unsigned)v1);
            op[(size_t)b * Nout + 0] = f0;
            op[(size_t)b * Nout + 1] = f1;
        }
    }
}

__global__ void __launch_bounds__(256) gemmT_k(
    const float* __restrict__ act, const float* __restrict__ WT,
    float* __restrict__ part, int Nout, int KS, int Kpad)
{
    __shared__ float sa[3 * 128 * 16];
    gemmT_core(sa, act, WT, part, Nout, KS, blockIdx.y, blockIdx.x, Kpad);
}

__global__ void __launch_bounds__(256) gemmT2_k(
    const float* __restrict__ actA, const float* __restrict__ WTA,
    float* __restrict__ partA, int NoutA, int KSA, int KpadA,
    const float* __restrict__ actB, const float* __restrict__ WTB,
    float* __restrict__ partB, int NoutB, int KSB, int KpadB)
{
    __shared__ float sa[3 * 128 * 16];
    const int y = blockIdx.y, bx = blockIdx.x;
    if (y < KSA) {
        if (bx * 512 >= NoutA) return;
        gemmT_core(sa, actA, WTA, partA, NoutA, KSA, y, bx, KpadA);
    } else {
        if (bx * 512 >= NoutB) return;
        gemmT_core(sa, actB, WTB, partB, NoutB, KSB, y - KSA, bx, KpadB);
    }
}

__global__ void __launch_bounds__(256) gemmT3_k(
    const float* __restrict__ actA, const float* __restrict__ WTA,
    float* __restrict__ partA, int NoutA, int KSA, int KpadA,
    const float* __restrict__ actB, const float* __restrict__ WTB,
    float* __restrict__ partB, int NoutB, int KSB, int KpadB,
    const float* __restrict__ actC, const float* __restrict__ WTC,
    float* __restrict__ partC, int NoutC, int KSC, int KpadC)
{
    __shared__ float sa[3 * 128 * 16];
    const int y = blockIdx.y, bx = blockIdx.x;
    if (y < KSA) {
        if (bx * 512 >= NoutA) return;
        gemmT_core(sa, actA, WTA, partA, NoutA, KSA, y, bx, KpadA);
    } else if (y < KSA + KSB) {
        if (bx * 512 >= NoutB) return;
        gemmT_core(sa, actB, WTB, partB, NoutB, KSB, y - KSA, bx, KpadB);
    } else {
        if (bx * 512 >= NoutC) return;
        gemmT_core(sa, actC, WTC, partC, NoutC, KSC, y - KSA - KSB, bx, KpadC);
    }
}

// ---------------- reduces ----------------
__device__ __forceinline__ void red_one(const float* __restrict__ p,
                                        const float* __restrict__ bias,
                                        float* __restrict__ o, int N, int KS,
                                        int i) {
    int n = i % N;
    float a = bias[n];
    for (int ks = 0; ks < KS; ks++) a += p[(size_t)ks * 16 * N + i];
    o[i] = a;
}
__global__ void reduceN_k(const float* __restrict__ part,
                          const float* __restrict__ bias,
                          float* __restrict__ out, int Nout, int KS) {
    int i = blockIdx.x * 256 + threadIdx.x;
    if (i >= 16 * Nout) return;
    red_one(part, bias, out, Nout, KS, i);
}
__global__ void reduce2_k(const float* __restrict__ pA,
                          const float* __restrict__ bA, float* __restrict__ oA,
                          int NA, int KSA,
                          const float* __restrict__ pB,
                          const float* __restrict__ bB, float* __restrict__ oB,
                          int NB, int KSB) {
    int i = blockIdx.x * 256 + threadIdx.x;
    if (i < 16 * NA) { red_one(pA, bA, oA, NA, KSA, i); return; }
    int j = i - 16 * NA;
    if (j < 16 * NB) red_one(pB, bB, oB, NB, KSB, j);
}
__global__ void reduce3_k(const float* __restrict__ pA,
                          const float* __restrict__ bA, float* __restrict__ oA,
                          int NA, int KSA,
                          const float* __restrict__ pB,
                          const float* __restrict__ bB, float* __restrict__ oB,
                          int NB, int KSB,
                          const float* __restrict__ pC,
                          const float* __restrict__ bC, float* __restrict__ oC,
                          int NC, int KSC) {
    int i = blockIdx.x * 256 + threadIdx.x;
    if (i < 16 * NA) { red_one(pA, bA, oA, NA, KSA, i); return; }
    int j = i - 16 * NA;
    if (j < 16 * NB) { red_one(pB, bB, oB, NB, KSB, j); return; }
    int k = j - 16 * NB;
    if (k < 16 * NC) red_one(pC, bC, oC, NC, KSC, k);
}

// ================= conv bodies (ic-split x4) =================
__device__ __forceinline__ void gate_body(
    float* sc, float* sw,
    const float* __restrict__ bu, const float* __restrict__ h,
    const float* __restrict__ td, const float* __restrict__ Wg,
    float* __restrict__ gp, int has_td, int b, int grp, int qtr)
{
    const int ic0 = qtr * 12;
    const int tid = threadIdx.x;
    for (int i = tid; i < 12 * 256; i += 224) sc[i] = 0.f;
    for (int i = tid; i < 12 * 36; i += 224) {
        int lic = i / 36, rem = i - lic * 36, q = rem >> 2, o = rem & 3;
        sw[i] = Wg[(grp * 4 + o) * 432 + (ic0 + lic) * 9 + q];
    }
    __syncthreads();
    for (int i = tid; i < 12 * 196; i += 224) {
        int lic = i / 196, p = i - lic * 196, y = p / 14, x = p - y * 14;
        int ic = ic0 + lic;
        float v = (ic < IND) ? bu[((size_t)b * IND + ic) * 196 + p]
                             : h[((size_t)b * HID + (ic - IND)) * 196 + p];
        if (has_td) v += td[((size_t)b * 48 + ic) * 196 + p];
        sc[lic * 256 + (y + 1) * 16 + (x + 1)] = v;
    }
    __syncthreads();
    if (tid < 196) {
        const int p = tid, y = p / 14, x = p - y * 14;
        float4 a = make_float4(0.f, 0.f, 0.f, 0.f);
        const float* cbase = sc + y * 16 + x;
        for (int lic = 0; lic < 12; ++lic) {
            float v[9];
            const float* cb = cbase + lic * 256;
#pragma unroll
            for (int dy = 0; dy < 3; dy++)
#pragma unroll
                for (int dx = 0; dx < 3; dx++) v[dy * 3 + dx] = cb[dy * 16 + dx];
            const float4* wq = (const float4*)(sw + lic * 36);
#pragma unroll
            for (int q = 0; q < 9; q++) {
                float4 w = wq[q];
                a.x += w.x * v[q]; a.y += w.y * v[q];
                a.z += w.z * v[q]; a.w += w.w * v[q];
            }
        }
        float* o = gp + (size_t)qtr * GSEG + ((size_t)b * 64 + grp * 4) * 196 + p;
        o[0] = a.x; o[196] = a.y; o[392] = a.z; o[588] = a.w;
    }
}

__device__ __forceinline__ void cand_body(
    float* sc, float* sw,
    const float* __restrict__ bu, const float* __restrict__ h,
    const float* __restrict__ gp, const float* __restrict__ bg,
    const float* __restrict__ Wc, float* __restrict__ cp,
    int b, int grp, int qtr)
{
    const int ic0 = qtr * 12;
    const int tid = threadIdx.x;
    for (int i = tid; i < 12 * 256; i += 224) sc[i] = 0.f;
    for (int i = tid; i < 12 * 36; i += 224) {
        int lic = i / 36, rem = i - lic * 36, q = rem >> 2, o = rem & 3;
        sw[i] = Wc[(grp * 4 + o) * 432 + (ic0 + lic) * 9 + q];
    }
    __syncthreads();
    for (int i = tid; i < 12 * 196; i += 224) {
        int lic = i / 196, p = i - lic * 196, y = p / 14, x = p - y * 14;
        int ic = ic0 + lic;
        float v;
        if (ic < IND) {
            v = bu[((size_t)b * IND + ic) * 196 + p];
        } else {
            int c = ic - IND;
            size_t gi = ((size_t)b * 64 + c) * 196 + p;
            float r = sigm(gp[gi] + gp[gi + GSEG] + gp[gi + 2 * (size_t)GSEG] +
                           gp[gi + 3 * (size_t)GSEG] + bg[c]);
            v = r * h[((size_t)b * HID + c) * 196 + p];
        }
        sc[lic * 256 + (y + 1) * 16 + (x + 1)] = v;
    }
    __syncthreads();
    if (tid < 196) {
        const int p = tid, y = p / 14, x = p - y * 14;
        float4 a = make_float4(0.f, 0.f, 0.f, 0.f);
        const float* cbase = sc + y * 16 + x;
        for (int lic = 0; lic < 12; ++lic) {
            float v[9];
            const float* cb = cbase + lic * 256;
#pragma unroll
            for (int dy = 0; dy < 3; dy++)
#pragma unroll
                for (int dx = 0; dx < 3; dx++) v[dy * 3 + dx] = cb[dy * 16 + dx];
            const float4* wq = (const float4*)(sw + lic * 36);
#pragma unroll
            for (int q = 0; q < 9; q++) {
                float4 w = wq[q];
                a.x += w.x * v[q]; a.y += w.y * v[q];
                a.z += w.z * v[q]; a.w += w.w * v[q];
            }
        }
        float* o = cp + (size_t)qtr * CSEG + ((size_t)b * 32 + grp * 4) * 196 + p;
        o[0] = a.x; o[196] = a.y; o[392] = a.z; o[588] = a.w;
    }
}

__device__ __forceinline__ void fin_one(
    int i, const float* __restrict__ cp, const float* __restrict__ bc,
    const float* __restrict__ gp, const float* __restrict__ bg,
    const float* __restrict__ h, float* __restrict__ hnew)
{
    int p = i % 196;
    int oc = (i / 196) & 31;
    int b = i / (32 * 196);
    float a = cp[i] + cp[i + (size_t)CSEG] + cp[i + 2 * (size_t)CSEG] +
              cp[i + 3 * (size_t)CSEG] + bc[oc];
    size_t gi = ((size_t)b * 64 + 32 + oc) * 196 + p;
    float z = sigm(gp[gi] + gp[gi + (size_t)GSEG] + gp[gi + 2 * (size_t)GSEG] +
                   gp[gi + 3 * (size_t)GSEG] + bg[32 + oc]);
    float ho = h[i];
    hnew[i] = (1.f - z) * ho + z * tanhf(a);
}

// single-node conv kernels
__global__ void __launch_bounds__(224) gate_part_k(
    const float* __restrict__ bu, const float* __restrict__ h,
    const float* __restrict__ td, const float* __restrict__ Wg,
    float* __restrict__ gp, int has_td)
{
    __shared__ float sc[12 * 256];
    __shared__ float sw[12 * 36];
    gate_body(sc, sw, bu, h, td, Wg, gp, has_td,
              blockIdx.x, blockIdx.y, blockIdx.z);
}
__global__ void __launch_bounds__(224) cand_part_k(
    const float* __restrict__ bu, const float* __restrict__ h,
    const float* __restrict__ gp, const float* __restrict__ bg,
    const float* __restrict__ Wc, float* __restrict__ cp)
{
    __shared__ float sc[12 * 256];
    __shared__ float sw[12 * 36];
    cand_body(sc, sw, bu, h, gp, bg, Wc, cp, blockIdx.x, blockIdx.y, blockIdx.z);
}
__global__ void cand_fin_k(const float* __restrict__ cp,
                           const float* __restrict__ bc,
                           const float* __restrict__ gp,
                           const float* __restrict__ bg,
                           const float* __restrict__ h,
                           float* __restrict__ hnew) {
    int i = blockIdx.x * 256 + threadIdx.x;
    if (i >= CSEG) return;
    fin_one(i, cp, bc, gp, bg, h, hnew);
}

// merged two-node conv kernels (PAIR: A=node2 no-td, B=node0 with td)
__global__ void __launch_bounds__(224) gate_part2_k(
    const float* __restrict__ buA, const float* __restrict__ hA,
    const float* __restrict__ WgA, float* __restrict__ gpA,
    const float* __restrict__ buB, const float* __restrict__ hB,
    const float* __restrict__ tdB, const float* __restrict__ WgB,
    float* __restrict__ gpB)
{
    __shared__ float sc[12 * 256];
    __shared__ float sw[12 * 36];
    const int z = blockIdx.z;
    if (z < 4)
        gate_body(sc, sw, buA, hA, tdB, WgA, gpA, 0, blockIdx.x, blockIdx.y, z);
    else
        gate_body(sc, sw, buB, hB, tdB, WgB, gpB, 1, blockIdx.x, blockIdx.y, z - 4);
}
__global__ void __launch_bounds__(224) cand_part2_k(
    const float* __restrict__ buA, const float* __restrict__ hA,
    const float* __restrict__ gpA, const float* __restrict__ bgA,
    const float* __restrict__ WcA, float* __restrict__ cpA,
    const float* __restrict__ buB, const float* __restrict__ hB,
    const float* __restrict__ gpB, const float* __restrict__ bgB,
    const float* __restrict__ WcB, float* __restrict__ cpB)
{
    __shared__ float sc[12 * 256];
    __shared__ float sw[12 * 36];
    const int z = blockIdx.z;
    if (z < 4)
        cand_body(sc, sw, buA, hA, gpA, bgA, WcA, cpA, blockIdx.x, blockIdx.y, z);
    else
        cand_body(sc, sw, buB, hB, gpB, bgB, WcB, cpB, blockIdx.x, blockIdx.y, z - 4);
}
__global__ void cand_fin2_k(
    const float* __restrict__ cpA, const float* __restrict__ bcA,
    const float* __restrict__ gpA, const float* __restrict__ bgA,
    const float* __restrict__ hA, float* __restrict__ hnA,
    const float* __restrict__ cpB, const float* __restrict__ bcB,
    const float* __restrict__ gpB, const float* __restrict__ bgB,
    const float* __restrict__ hB, float* __restrict__ hnB)
{
    int i = blockIdx.x * 256 + threadIdx.x;
    if (i < CSEG) { fin_one(i, cpA, bcA, gpA, bgA, hA, hnA); return; }
    int j = i - CSEG;
    if (j < CSEG) fin_one(j, cpB, bcB, gpB, bgB, hB, hnB);
}

// ---------------- maxpool 3x3 s1 p1 + transpose to (K,16) ----------------
__device__ __forceinline__ void pool_one(const float* __restrict__ h,
                                         float* __restrict__ outT, int idx) {
    int b = idx & 15, k = idx >> 4;
    int c = k / 196, p = k - c * 196, y = p / 14, x = p - y * 14;
    const float* hp = h + ((size_t)b * HID + c) * 196;
    int y0 = y > 0 ? y - 1 : 0, y1 = y < 13 ? y + 1 : 13;
    int x0 = x > 0 ? x - 1 : 0, x1 = x < 13 ? x + 1 : 13;
    float m = -3.4e38f;
    for (int yy = y0; yy <= y1; ++yy)
        for (int xx = x0; xx <= x1; ++xx)
            m = fmaxf(m, hp[yy * 14 + xx]);
    outT[(size_t)k * 16 + b] = m;
}
__global__ void pool_k(const float* __restrict__ h, float* __restrict__ outT) {
    int idx = blockIdx.x * 256 + threadIdx.x;
    if (idx >= BB * KBIG) return;
    pool_one(h, outT, idx);
}
__global__ void pool2_k(const float* __restrict__ h0, float* __restrict__ dst0,
                        const float* __restrict__ h1, float* __restrict__ dst1) {
    int idx = blockIdx.x * 256 + threadIdx.x;
    if (idx >= BB * KBIG) return;
    if (blockIdx.z == 0) pool_one(h0, dst0, idx);
    else                 pool_one(h1, dst1, idx);
}

__global__ void xT_k(const float* __restrict__ x, float* __restrict__ xT) {
    int idx = blockIdx.x * 256 + threadIdx.x;
    if (idx >= TT * K0PAD * BB) return;
    int b = idx & 15;
    int r = idx >> 4;
    int k = r % K0PAD, t = r / K0PAD;
    float v = 0.f;
    if (k < K0) v = x[((size_t)b * TT + t) * K0 + k];
    xT[idx] = v;
}

__global__ void zero_k(float* p, int n) {
    int i = blockIdx.x * 256 + threadIdx.x;
    if (i < n) p[i] = 0.f;
}

// ---------------- fc tail ----------------
__global__ void __launch_bounds__(256) fc1_k(const float* __restrict__ h2,
                                             const float* __restrict__ w,
                                             const float* __restrict__ bias,
                                             float* __restrict__ out1) {
    __shared__ float red[256];
    int j = blockIdx.x, tid = threadIdx.x;
    float acc[16];
#pragma unroll
    for (int b = 0; b < 16; b++) acc[b] = 0.f;
    for (int k = tid; k < KBIG; k += 256) {
        float wv = w[(size_t)j * KBIG + k];
#pragma unroll
        for (int b = 0; b < 16; b++)
            acc[b] += wv * fmaxf(h2[(size_t)b * KBIG + k], 0.f);
    }
    for (int b = 0; b < 16; b++) {
        red[tid] = acc[b];
        __syncthreads();
        for (int sft = 128; sft; sft >>= 1) {
            if (tid < sft) red[tid] += red[tid + sft];
            __syncthreads();
        }
        if (tid == 0) out1[b * 100 + j] = fmaxf(red[0] + bias[j], 0.f);
        __syncthreads();
    }
}

__global__ void fc2_k(const float* __restrict__ p, const float* __restrict__ w,
                      const float* __restrict__ bias, float* __restrict__ out) {
    int t = threadIdx.x;
    if (t < 160) {
        int b = t / 10, j = t - b * 10;
        float a = bias[j];
        for (int k = 0; k < 100; k++) a += p[b * 100 + k] * w[j * 100 + k];
        out[b * 10 + j] = a;
    }
}

// ---------------- host orchestration ----------------
extern "C" void kernel_launch(void* const* d_in, const int* in_sizes, int n_in,
                              void* d_out, int out_size) {
    const float* x     = (const float*)d_in[0];
    const float* Wg    = (const float*)d_in[1];
    const float* bg    = (const float*)d_in[2];
    const float* Wc    = (const float*)d_in[3];
    const float* bc    = (const float*)d_in[4];
    const float* bu_w0 = (const float*)d_in[5];
    const float* bu_b0 = (const float*)d_in[6];
    const float* bu_w1 = (const float*)d_in[7];
    const float* bu_b1 = (const float*)d_in[8];
    const float* bu_w2 = (const float*)d_in[9];
    const float* bu_b2 = (const float*)d_in[10];
    const float* td_w0 = (const float*)d_in[11];
    const float* td_b0 = (const float*)d_in[12];
    const float* td_w1 = (const float*)d_in[13];
    const float* td_b1 = (const float*)d_in[14];
    const float* fc1_w = (const float*)d_in[15];
    const float* fc1_b = (const float*)d_in[16];
    const float* fc2_w = (const float*)d_in[17];
    const float* fc2_b = (const float*)d_in[18];
    float* out = (float*)d_out;

    float *hbuf, *xT, *pBU, *pTD, *bu, *bu0, *td, *part, *partB, *partB0;
    float *gp, *cp, *gp0, *cp0, *fc1o;
    float *tdw0T, *tdw1T, *buw1T, *buw2T, *buw0T;
    cudaGetSymbolAddress((void**)&hbuf,   g_h);
    cudaGetSymbolAddress((void**)&xT,     g_xT);
    cudaGetSymbolAddress((void**)&pBU,    g_poolBU);
    cudaGetSymbolAddress((void**)&pTD,    g_poolTD);
    cudaGetSymbolAddress((void**)&bu,     g_bu);
    cudaGetSymbolAddress((void**)&bu0,    g_bu0);
    cudaGetSymbolAddress((void**)&td,     g_td);
    cudaGetSymbolAddress((void**)&part,   g_part);
    cudaGetSymbolAddress((void**)&partB,  g_partB);
    cudaGetSymbolAddress((void**)&partB0, g_partB0);
    cudaGetSymbolAddress((void**)&gp,     g_gp);
    cudaGetSymbolAddress((void**)&cp,     g_cp);
    cudaGetSymbolAddress((void**)&gp0,    g_gp0);
    cudaGetSymbolAddress((void**)&cp0,    g_cp0);
    cudaGetSymbolAddress((void**)&fc1o,   g_fc1o);
    cudaGetSymbolAddress((void**)&tdw0T,  g_tdw0T);
    cudaGetSymbolAddress((void**)&tdw1T,  g_tdw1T);
    cudaGetSymbolAddress((void**)&buw1T,  g_buw1T);
    cudaGetSymbolAddress((void**)&buw2T,  g_buw2T);
    cudaGetSymbolAddress((void**)&buw0T,  g_buw0T);

    const int hTot = 3 * 2 * BB * HID * HW;
    zero_k<<<(hTot + 255) / 256, 256>>>(hbuf, hTot);
    xT_k<<<(TT * K0PAD * BB + 255) / 256, 256>>>(x, xT);

    {
        dim3 tb(32, 8);
        trans2_k<<<dim3(KBIG / 32, NTD / 32, 2), tb>>>(td_w0, tdw0T,
                                                       td_w1, tdw1T, NTD);
        trans2_k<<<dim3(KBIG / 32, NBU / 32, 2), tb>>>(bu_w1, buw1T,
                                                       bu_w2, buw2T, NBU);
        trans_pad_k<<<dim3(K0PAD / 32, NBU / 32), tb>>>(bu_w0, buw0T, NBU);
    }

    int cur[3] = {0, 0, 0};
    const size_t HSZ = (size_t)BB * HID * HW;
    const float* WgN[3] = {Wg, Wg + 27648, Wg + 2 * 27648};
    const float* bgN[3] = {bg, bg + 64, bg + 128};
    const float* WcN[3] = {Wc, Wc + 13824, Wc + 2 * 13824};
    const float* bcN[3] = {bc, bc + 32, bc + 64};
    const float* buB[3] = {bu_b0, bu_b1, bu_b2};
    const float* buWT[3] = {buw0T, buw1T, buw2T};

    dim3 gateGrid(16, 16, 4), candGrid(16, 8, 4);
    dim3 gate2Grid(16, 16, 8), cand2Grid(16, 8, 8);
    const int poolBlocks = (BB * KBIG + 255) / 256;
    const int cFinB = (CSEG + 255) / 256;
    const int cFin2B = (2 * CSEG + 255) / 256;
    const int tdGx = (NTD + 511) / 512, buGx = (NBU + 511) / 512;
    const int buRed = (16 * NBU + 255) / 256;
    const int r2B = (16 * (NBU + NTD) + 255) / 256;
    const int r3B = (16 * (NBU + NTD + NBU) + 255) / 256;
#define HPTR(n, p) (hbuf + ((size_t)(n) * 2 + (p)) * HSZ)

    // helper lambdas via macros --------------------------------------------
#define NODE0_NOTD(tt)                                                         \
    do {                                                                       \
        const float* x0 = xT + (size_t)(tt) * K0PAD * 16;                      \
        gemmT_k<<<dim3(buGx, KS_B0), 256>>>(x0, buWT[0], partB0,               \
                                            NBU, KS_B0, K0PAD);                \
        reduceN_k<<<buRed, 256>>>(partB0, buB[0], bu0, NBU, KS_B0);            \
        gate_part_k<<<gateGrid, 224>>>(bu0, HPTR(0, cur[0]), td, WgN[0],       \
                                       gp0, 0);                                \
        cand_part_k<<<candGrid, 224>>>(bu0, HPTR(0, cur[0]), gp0, bgN[0],      \
                                       WcN[0], cp0);                           \
        cand_fin_k<<<cFinB, 256>>>(cp0, bcN[0], gp0, bgN[0], HPTR(0, cur[0]),  \
                                   HPTR(0, 1 - cur[0]));                       \
        cur[0] ^= 1;                                                           \
    } while (0)

#define NODE1(tt)                                                              \
    do {                                                                       \
        int hastd = ((tt) >= 2);                                               \
        if (hastd) {                                                           \
            pool2_k<<<dim3(poolBlocks, 1, 2), 256>>>(                          \
                HPTR(0, cur[0]), pBU, HPTR(2, cur[2]), pTD);                   \
            gemmT2_k<<<dim3(tdGx, KS_BU + KS_TD), 256>>>(                      \
                pBU, buWT[1], partB, NBU, KS_BU, KBIG,                         \
                pTD, tdw1T, part, NTD, KS_TD, KBIG);                           \
            reduce2_k<<<r2B, 256>>>(partB, buB[1], bu, NBU, KS_BU,             \
                                    part, td_b1, td, NTD, KS_TD);              \
        } else {                                                               \
            pool_k<<<poolBlocks, 256>>>(HPTR(0, cur[0]), pBU);                 \
            gemmT_k<<<dim3(buGx, KS_BU), 256>>>(pBU, buWT[1], partB,           \
                                                NBU, KS_BU, KBIG);             \
            reduceN_k<<<buRed, 256>>>(partB, buB[1], bu, NBU, KS_BU);          \
        }                                                                      \
        gate_part_k<<<gateGrid, 224>>>(bu, HPTR(1, cur[1]), td, WgN[1],        \
                                       gp, hastd);                             \
        cand_part_k<<<candGrid, 224>>>(bu, HPTR(1, cur[1]), gp, bgN[1],        \
                                       WcN[1], cp);                            \
        cand_fin_k<<<cFinB, 256>>>(cp, bcN[1], gp, bgN[1], HPTR(1, cur[1]),    \
                                   HPTR(1, 1 - cur[1]));                       \
        cur[1] ^= 1;                                                           \
    } while (0)

#define NODE2()                                                                \
    do {                                                                       \
        pool_k<<<poolBlocks, 256>>>(HPTR(1, cur[1]), pBU);                     \
        gemmT_k<<<dim3(buGx, KS_BU), 256>>>(pBU, buWT[2], partB,               \
                                            NBU, KS_BU, KBIG);                 \
        reduceN_k<<<buRed, 256>>>(partB, buB[2], bu, NBU, KS_BU);              \
        gate_part_k<<<gateGrid, 224>>>(bu, HPTR(2, cur[2]), td, WgN[2],        \
                                       gp, 0);                                 \
        cand_part_k<<<candGrid, 224>>>(bu, HPTR(2, cur[2]), gp, bgN[2],        \
                                       WcN[2], cp);                            \
        cand_fin_k<<<cFinB, 256>>>(cp, bcN[2], gp, bgN[2], HPTR(2, cur[2]),    \
                                   HPTR(2, 1 - cur[2]));                       \
        cur[2] ^= 1;                                                           \
    } while (0)

    // ---- prologue: node0(0), node0(1), node1(1) ----
    NODE0_NOTD(0);
    NODE0_NOTD(1);
    NODE1(1);

    // ---- main loop: PAIR{node2(t), node0(t+1)} ; node1(t+1)  for t=1..6 ----
    for (int t = 1; t <= 6; t++) {
        // shared pool of h1 (post node1(t)) serves node2 bu AND node0 td
        pool_k<<<poolBlocks, 256>>>(HPTR(1, cur[1]), pTD);
        const float* x0 = xT + (size_t)(t + 1) * K0PAD * 16;
        gemmT3_k<<<dim3(tdGx, KS_BU + KS_TD + KS_B0), 256>>>(
            pTD, buWT[2], partB, NBU, KS_BU, KBIG,     // node2 bu
            pTD, tdw0T, part, NTD, KS_TD, KBIG,        // node0 td
            x0, buWT[0], partB0, NBU, KS_B0, K0PAD);   // node0 bu
        reduce3_k<<<r3B, 256>>>(partB, buB[2], bu, NBU, KS_BU,
                                part, td_b0, td, NTD, KS_TD,
                                partB0, buB[0], bu0, NBU, KS_B0);
        gate_part2_k<<<gate2Grid, 224>>>(bu, HPTR(2, cur[2]), WgN[2], gp,
                                         bu0, HPTR(0, cur[0]), td, WgN[0], gp0);
        cand_part2_k<<<cand2Grid, 224>>>(bu, HPTR(2, cur[2]), gp, bgN[2],
                                         WcN[2], cp,
                                         bu0, HPTR(0, cur[0]), gp0, bgN[0],
                                         WcN[0], cp0);
        cand_fin2_k<<<cFin2B, 256>>>(cp, bcN[2], gp, bgN[2],
                                     HPTR(2, cur[2]), HPTR(2, 1 - cur[2]),
                                     cp0, bcN[0], gp0, bgN[0],
                                     HPTR(0, cur[0]), HPTR(0, 1 - cur[0]));
        cur[2] ^= 1;
        cur[0] ^= 1;
        NODE1(t + 1);
    }

    // ---- epilogue: node2(7), node1(8), node2(8), node1(9), node2(9) ----
    NODE2();
    NODE1(8);
    NODE2();
    NODE1(9);
    NODE2();

    fc1_k<<<100, 256>>>(HPTR(2, cur[2]), fc1_w, fc1_b, fc1o);
    fc2_k<<<1, 192>>>(fc1o, fc2_w, fc2_b, out);
#undef NODE0_NOTD
#undef NODE1
#undef NODE2
#undef HPTR
}

// round 15
// speedup vs baseline: 2.3642x; 1.0389x over previous
#include <cuda_runtime.h>
#include <math.h>

// ---------------- problem constants ----------------
#define BB 16
#define TT 8
#define HW 196
#define HID 32
#define IND 16
#define KBIG 6272       // HID*HW
#define K0 588          // CIN*HW
#define K0PAD 640
#define NBU 3136        // IND*HW
#define NTD 9408        // (IND+HID)*HW
#define KS_TD 24
#define KS_BU 49
#define KS_B0 5
#define GSEG (16 * 64 * 196)
#define CSEG (16 * 32 * 196)

// ---------------- device scratch (no allocs allowed) ----------------
__device__ float g_h[3 * 2 * BB * HID * HW];   // hidden, double buffered
__device__ float g_xT[TT * K0PAD * BB];        // transposed+padded input slices
__device__ float g_pH0[KBIG * BB];             // pool(h0) -> node1 bu
__device__ float g_pH1[KBIG * BB];             // pool(h1) -> node2 bu / node0 td
__device__ float g_pH2[KBIG * BB];             // pool(h2) -> node1 td
__device__ float g_bu[BB * NBU];               // node1/node2 bu
__device__ float g_bu0all[TT * BB * NBU];      // all node0 bu, precomputed
__device__ float g_td[BB * NTD];
__device__ float g_part[KS_TD * BB * NTD];     // td K-split partials
__device__ float g_partB[KS_BU * BB * NBU];    // bu K-split partials
__device__ float g_partB0[TT * KS_B0 * BB * NBU]; // bu0 partials (all t)
__device__ float g_gp[4 * GSEG];               // gate partials (node1/2)
__device__ float g_cp[4 * CSEG];
__device__ float g_gp0[4 * GSEG];              // gate partials (node0 in pair)
__device__ float g_cp0[4 * CSEG];
__device__ float g_fc1o[BB * 100];
// transposed weights (k-major), rebuilt every call
__device__ float g_tdw0T[(size_t)KBIG * NTD];
__device__ float g_tdw1T[(size_t)KBIG * NTD];
__device__ float g_buw1T[(size_t)KBIG * NBU];
__device__ float g_buw2T[(size_t)KBIG * NBU];
__device__ float g_buw0T[(size_t)K0PAD * NBU];

// ---------------- f32x2 helpers ----------------
__device__ __forceinline__ unsigned long long pack2(float v) {
    unsigned long long r;
    asm("mov.b64 %0, {%1, %1};" : "=l"(r) : "f"(v));
    return r;
}
__device__ __forceinline__ void fma2(unsigned long long& d, unsigned long long a,
                                     unsigned long long b) {
    asm("fma.rn.f32x2 %0, %1, %2, %0;" : "+l"(d) : "l"(a), "l"(b));
}
__device__ __forceinline__ float sigm(float a) { return 1.f / (1.f + expf(-a)); }

// ---------------- transposes ----------------
__global__ void trans2_k(const float* __restrict__ Wa, float* __restrict__ WTa,
                         const float* __restrict__ Wb, float* __restrict__ WTb,
                         int Nout) {
    __shared__ float t[32][33];
    const float* W  = blockIdx.z ? Wb  : Wa;
    float*       WT = blockIdx.z ? WTb : WTa;
    const int kb = blockIdx.x * 32, nb = blockIdx.y * 32;
    const int tx = threadIdx.x, ty = threadIdx.y;   // 32 x 8
#pragma unroll
    for (int i = 0; i < 32; i += 8)
        t[ty + i][tx] = W[(size_t)(nb + ty + i) * KBIG + kb + tx];
    __syncthreads();
#pragma unroll
    for (int i = 0; i < 32; i += 8)
        WT[(size_t)(kb + ty + i) * Nout + nb + tx] = t[tx][ty + i];
}

__global__ void trans_pad_k(const float* __restrict__ W, float* __restrict__ WT,
                            int Nout) {
    __shared__ float t[32][33];
    const int kb = blockIdx.x * 32, nb = blockIdx.y * 32;
    const int tx = threadIdx.x, ty = threadIdx.y;
#pragma unroll
    for (int i = 0; i < 32; i += 8) {
        int k = kb + tx;
        t[ty + i][tx] = (k < K0) ? W[(size_t)(nb + ty + i) * K0 + k] : 0.f;
    }
    __syncthreads();
#pragma unroll
    for (int i = 0; i < 32; i += 8) {
        int k = kb + ty + i;
        if (k < K0PAD) WT[(size_t)k * Nout + nb + tx] = t[tx][ty + i];
    }
}

// ================= gemmT core =================
__device__ __forceinline__ void gemmT_core(
    float* sa, const float* __restrict__ act, const float* __restrict__ WT,
    float* __restrict__ part, int Nout, int KS, int ks, int bx, int Kpad)
{
    const int tid = threadIdx.x;
    const int n0raw = bx * 512 + tid * 2;
    const bool act_n = n0raw < Nout;
    const int n0 = act_n ? n0raw : (Nout - 2);
    const int slabs = Kpad >> 7;
    const int s0 = slabs * ks / KS, s1 = slabs * (ks + 1) / KS;
    const int ns = s1 - s0;
    const int kn = ns * 128;

    {
        const float4* src = (const float4*)act + (size_t)s0 * 512;
        for (int f = tid; f < ns * 512; f += 256) {
            float4 v = src[f];
            *(float4*)(&sa[(f >> 2) * 16 + (f & 3) * 4]) = v;
        }
    }

    unsigned long long acc[2][8];
#pragma unroll
    for (int n = 0; n < 2; n++)
#pragma unroll
        for (int p = 0; p < 8; p++) acc[n][p] = 0ull;

    const float* wp = WT + (size_t)(s0 * 128) * Nout + n0;
    float2 wb[2][8];
#pragma unroll
    for (int u = 0; u < 8; u++)
        wb[0][u] = *(const float2*)(wp + (size_t)u * Nout);

    __syncthreads();

    for (int k0 = 0; k0 < kn; k0 += 8) {
        const int cur = (k0 >> 3) & 1;
        const float* wpn = wp + (size_t)8 * Nout;
        if (k0 + 8 < kn) {
#pragma unroll
            for (int u = 0; u < 8; u++)
                wb[cur ^ 1][u] = *(const float2*)(wpn + (size_t)u * Nout);
        }
#pragma unroll
        for (int u = 0; u < 8; u++) {
            const ulonglong2* ap = (const ulonglong2*)(sa + (k0 + u) * 16);
            ulonglong2 u0 = ap[0], u1 = ap[1], u2 = ap[2], u3 = ap[3];
            unsigned long long av[8] = {u0.x, u0.y, u1.x, u1.y,
                                        u2.x, u2.y, u3.x, u3.y};
            unsigned long long w0 = pack2(wb[cur][u].x);
            unsigned long long w1 = pack2(wb[cur][u].y);
#pragma unroll
            for (int p = 0; p < 8; p++) fma2(acc[0][p], w0, av[p]);
#pragma unroll
            for (int p = 0; p < 8; p++) fma2(acc[1][p], w1, av[p]);
        }
        wp = wpn;
    }
    if (act_n) {
        float* op = part + (size_t)ks * 16 * Nout + n0;
#pragma unroll
        for (int b = 0; b < 16; b++) {
            unsigned long long v0 = acc[0][b >> 1], v1 = acc[1][b >> 1];
            float f0 = (b & 1) ? __uint_as_float((unsigned)(v0 >> 32))
                               : __uint_as_float((unsigned)v0);
            float f1 = (b & 1) ? __uint_as_float((unsigned)(v1 >> 32))
                               : __uint_as_float((unsigned)v1);
            op[(size_t)b * Nout + 0] = f0;
            op[(size_t)b * Nout + 1] = f1;
        }
    }
}

__global__ void __launch_bounds__(256) gemmT_k(
    const float* __restrict__ act, const float* __restrict__ WT,
    float* __restrict__ part, int Nout, int KS, int Kpad)
{
    __shared__ float sa[3 * 128 * 16];
    gemmT_core(sa, act, WT, part, Nout, KS, blockIdx.y, blockIdx.x, Kpad);
}

__global__ void __launch_bounds__(256) gemmT2_k(
    const float* __restrict__ actA, const float* __restrict__ WTA,
    float* __restrict__ partA, int NoutA, int KSA, int KpadA,
    const float* __restrict__ actB, const float* __restrict__ WTB,
    float* __restrict__ partB, int NoutB, int KSB, int KpadB)
{
    __shared__ float sa[3 * 128 * 16];
    const int y = blockIdx.y, bx = blockIdx.x;
    if (y < KSA) {
        if (bx * 512 >= NoutA) return;
        gemmT_core(sa, actA, WTA, partA, NoutA, KSA, y, bx, KpadA);
    } else {
        if (bx * 512 >= NoutB) return;
        gemmT_core(sa, actB, WTB, partB, NoutB, KSB, y - KSA, bx, KpadB);
    }
}

// all 8 bu0 GEMMs in one launch: y = t*KS_B0 + ks
__global__ void __launch_bounds__(256) gemmB0all_k(
    const float* __restrict__ xT, const float* __restrict__ WT,
    float* __restrict__ partAll)
{
    __shared__ float sa[3 * 128 * 16];
    const int y = blockIdx.y;
    const int t = y / KS_B0, ks = y - t * KS_B0;
    gemmT_core(sa, xT + (size_t)t * K0PAD * 16, WT,
               partAll + (size_t)t * KS_B0 * 16 * NBU,
               NBU, KS_B0, ks, blockIdx.x, K0PAD);
}

// ---------------- reduces ----------------
__device__ __forceinline__ void red_one(const float* __restrict__ p,
                                        const float* __restrict__ bias,
                                        float* __restrict__ o, int N, int KS,
                                        int i) {
    int n = i % N;
    float a = bias[n];
    for (int ks = 0; ks < KS; ks++) a += p[(size_t)ks * 16 * N + i];
    o[i] = a;
}
__global__ void reduceN_k(const float* __restrict__ part,
                          const float* __restrict__ bias,
                          float* __restrict__ out, int Nout, int KS) {
    int i = blockIdx.x * 256 + threadIdx.x;
    if (i >= 16 * Nout) return;
    red_one(part, bias, out, Nout, KS, i);
}
__global__ void reduce2_k(const float* __restrict__ pA,
                          const float* __restrict__ bA, float* __restrict__ oA,
                          int NA, int KSA,
                          const float* __restrict__ pB,
                          const float* __restrict__ bB, float* __restrict__ oB,
                          int NB, int KSB) {
    int i = blockIdx.x * 256 + threadIdx.x;
    if (i < 16 * NA) { red_one(pA, bA, oA, NA, KSA, i); return; }
    int j = i - 16 * NA;
    if (j < 16 * NB) red_one(pB, bB, oB, NB, KSB, j);
}
__global__ void reduceB0all_k(const float* __restrict__ partAll,
                              const float* __restrict__ bias,
                              float* __restrict__ outAll) {
    int i = blockIdx.x * 256 + threadIdx.x;
    if (i >= TT * 16 * NBU) return;
    int t = i / (16 * NBU), j = i - t * 16 * NBU;
    red_one(partAll + (size_t)t * KS_B0 * 16 * NBU, bias,
            outAll + (size_t)t * 16 * NBU, NBU, KS_B0, j);
}

// ================= conv bodies (ic-split x4) =================
__device__ __forceinline__ void gate_body(
    float* sc, float* sw,
    const float* __restrict__ bu, const float* __restrict__ h,
    const float* __restrict__ td, const float* __restrict__ Wg,
    float* __restrict__ gp, int has_td, int b, int grp, int qtr)
{
    const int ic0 = qtr * 12;
    const int tid = threadIdx.x;
    for (int i = tid; i < 12 * 256; i += 224) sc[i] = 0.f;
    for (int i = tid; i < 12 * 36; i += 224) {
        int lic = i / 36, rem = i - lic * 36, q = rem >> 2, o = rem & 3;
        sw[i] = Wg[(grp * 4 + o) * 432 + (ic0 + lic) * 9 + q];
    }
    __syncthreads();
    for (int i = tid; i < 12 * 196; i += 224) {
        int lic = i / 196, p = i - lic * 196, y = p / 14, x = p - y * 14;
        int ic = ic0 + lic;
        float v = (ic < IND) ? bu[((size_t)b * IND + ic) * 196 + p]
                             : h[((size_t)b * HID + (ic - IND)) * 196 + p];
        if (has_td) v += td[((size_t)b * 48 + ic) * 196 + p];
        sc[lic * 256 + (y + 1) * 16 + (x + 1)] = v;
    }
    __syncthreads();
    if (tid < 196) {
        const int p = tid, y = p / 14, x = p - y * 14;
        float4 a = make_float4(0.f, 0.f, 0.f, 0.f);
        const float* cbase = sc + y * 16 + x;
        for (int lic = 0; lic < 12; ++lic) {
            float v[9];
            const float* cb = cbase + lic * 256;
#pragma unroll
            for (int dy = 0; dy < 3; dy++)
#pragma unroll
                for (int dx = 0; dx < 3; dx++) v[dy * 3 + dx] = cb[dy * 16 + dx];
            const float4* wq = (const float4*)(sw + lic * 36);
#pragma unroll
            for (int q = 0; q < 9; q++) {
                float4 w = wq[q];
                a.x += w.x * v[q]; a.y += w.y * v[q];
                a.z += w.z * v[q]; a.w += w.w * v[q];
            }
        }
        float* o = gp + (size_t)qtr * GSEG + ((size_t)b * 64 + grp * 4) * 196 + p;
        o[0] = a.x; o[196] = a.y; o[392] = a.z; o[588] = a.w;
    }
}

__device__ __forceinline__ void cand_body(
    float* sc, float* sw,
    const float* __restrict__ bu, const float* __restrict__ h,
    const float* __restrict__ gp, const float* __restrict__ bg,
    const float* __restrict__ Wc, float* __restrict__ cp,
    int b, int grp, int qtr)
{
    const int ic0 = qtr * 12;
    const int tid = threadIdx.x;
    for (int i = tid; i < 12 * 256; i += 224) sc[i] = 0.f;
    for (int i = tid; i < 12 * 36; i += 224) {
        int lic = i / 36, rem = i - lic * 36, q = rem >> 2, o = rem & 3;
        sw[i] = Wc[(grp * 4 + o) * 432 + (ic0 + lic) * 9 + q];
    }
    __syncthreads();
    for (int i = tid; i < 12 * 196; i += 224) {
        int lic = i / 196, p = i - lic * 196, y = p / 14, x = p - y * 14;
        int ic = ic0 + lic;
        float v;
        if (ic < IND) {
            v = bu[((size_t)b * IND + ic) * 196 + p];
        } else {
            int c = ic - IND;
            size_t gi = ((size_t)b * 64 + c) * 196 + p;
            float r = sigm(gp[gi] + gp[gi + GSEG] + gp[gi + 2 * (size_t)GSEG] +
                           gp[gi + 3 * (size_t)GSEG] + bg[c]);
            v = r * h[((size_t)b * HID + c) * 196 + p];
        }
        sc[lic * 256 + (y + 1) * 16 + (x + 1)] = v;
    }
    __syncthreads();
    if (tid < 196) {
        const int p = tid, y = p / 14, x = p - y * 14;
        float4 a = make_float4(0.f, 0.f, 0.f, 0.f);
        const float* cbase = sc + y * 16 + x;
        for (int lic = 0; lic < 12; ++lic) {
            float v[9];
            const float* cb = cbase + lic * 256;
#pragma unroll
            for (int dy = 0; dy < 3; dy++)
#pragma unroll
                for (int dx = 0; dx < 3; dx++) v[dy * 3 + dx] = cb[dy * 16 + dx];
            const float4* wq = (const float4*)(sw + lic * 36);
#pragma unroll
            for (int q = 0; q < 9; q++) {
                float4 w = wq[q];
                a.x += w.x * v[q]; a.y += w.y * v[q];
                a.z += w.z * v[q]; a.w += w.w * v[q];
            }
        }
        float* o = cp + (size_t)qtr * CSEG + ((size_t)b * 32 + grp * 4) * 196 + p;
        o[0] = a.x; o[196] = a.y; o[392] = a.z; o[588] = a.w;
    }
}

// single-node conv kernels
__global__ void __launch_bounds__(224) gate_part_k(
    const float* __restrict__ bu, const float* __restrict__ h,
    const float* __restrict__ td, const float* __restrict__ Wg,
    float* __restrict__ gp, int has_td)
{
    __shared__ float sc[12 * 256];
    __shared__ float sw[12 * 36];
    gate_body(sc, sw, bu, h, td, Wg, gp, has_td,
              blockIdx.x, blockIdx.y, blockIdx.z);
}
__global__ void __launch_bounds__(224) cand_part_k(
    const float* __restrict__ bu, const float* __restrict__ h,
    const float* __restrict__ gp, const float* __restrict__ bg,
    const float* __restrict__ Wc, float* __restrict__ cp)
{
    __shared__ float sc[12 * 256];
    __shared__ float sw[12 * 36];
    cand_body(sc, sw, bu, h, gp, bg, Wc, cp, blockIdx.x, blockIdx.y, blockIdx.z);
}

// merged two-node conv kernels (PAIR: A=node2 no-td, B=node0 with td)
__global__ void __launch_bounds__(224) gate_part2_k(
    const float* __restrict__ buA, const float* __restrict__ hA,
    const float* __restrict__ WgA, float* __restrict__ gpA,
    const float* __restrict__ buB, const float* __restrict__ hB,
    const float* __restrict__ tdB, const float* __restrict__ WgB,
    float* __restrict__ gpB)
{
    __shared__ float sc[12 * 256];
    __shared__ float sw[12 * 36];
    const int z = blockIdx.z;
    if (z < 4)
        gate_body(sc, sw, buA, hA, tdB, WgA, gpA, 0, blockIdx.x, blockIdx.y, z);
    else
        gate_body(sc, sw, buB, hB, tdB, WgB, gpB, 1, blockIdx.x, blockIdx.y, z - 4);
}
__global__ void __launch_bounds__(224) cand_part2_k(
    const float* __restrict__ buA, const float* __restrict__ hA,
    const float* __restrict__ gpA, const float* __restrict__ bgA,
    const float* __restrict__ WcA, float* __restrict__ cpA,
    const float* __restrict__ buB, const float* __restrict__ hB,
    const float* __restrict__ gpB, const float* __restrict__ bgB,
    const float* __restrict__ WcB, float* __restrict__ cpB)
{
    __shared__ float sc[12 * 256];
    __shared__ float sw[12 * 36];
    const int z = blockIdx.z;
    if (z < 4)
        cand_body(sc, sw, buA, hA, gpA, bgA, WcA, cpA, blockIdx.x, blockIdx.y, z);
    else
        cand_body(sc, sw, buB, hB, gpB, bgB, WcB, cpB, blockIdx.x, blockIdx.y, z - 4);
}

// ================= fused GRU-update + maxpool(3x3,s1,p1) + transpose =================
// block = one (b, oc) 14x14 plane; 224 threads (196 active).
__device__ __forceinline__ void finpool_body(
    const float* __restrict__ cp, const float* __restrict__ bc,
    const float* __restrict__ gp, const float* __restrict__ bg,
    const float* __restrict__ h, float* __restrict__ hnew,
    float* __restrict__ poolT, int blk)
{
    __shared__ float sp[256];
    const int b = blk >> 5, oc = blk & 31;
    const int tid = threadIdx.x;
    for (int i = tid; i < 256; i += 224) sp[i] = -3.4e38f;
    __syncthreads();
    float hn = 0.f;
    if (tid < 196) {
        const int p = tid, y = p / 14, x = p - y * 14;
        size_t i = ((size_t)b * 32 + oc) * 196 + p;
        float a = cp[i] + cp[i + (size_t)CSEG] + cp[i + 2 * (size_t)CSEG] +
                  cp[i + 3 * (size_t)CSEG] + bc[oc];
        size_t gi = ((size_t)b * 64 + 32 + oc) * 196 + p;
        float z = sigm(gp[gi] + gp[gi + (size_t)GSEG] +
                       gp[gi + 2 * (size_t)GSEG] + gp[gi + 3 * (size_t)GSEG] +
                       bg[32 + oc]);
        hn = (1.f - z) * h[i] + z * tanhf(a);
        hnew[i] = hn;
        sp[(y + 1) * 16 + (x + 1)] = hn;
    }
    __syncthreads();
    if (tid < 196) {
        const int p = tid, y = p / 14, x = p - y * 14;
        const float* c = sp + y * 16 + x;
        float m = c[0];
        m = fmaxf(m, c[1]);  m = fmaxf(m, c[2]);
        m = fmaxf(m, c[16]); m = fmaxf(m, c[17]); m = fmaxf(m, c[18]);
        m = fmaxf(m, c[32]); m = fmaxf(m, c[33]); m = fmaxf(m, c[34]);
        poolT[((size_t)oc * 196 + p) * 16 + b] = m;
    }
}

__global__ void __launch_bounds__(224) cand_finpool_k(
    const float* __restrict__ cp, const float* __restrict__ bc,
    const float* __restrict__ gp, const float* __restrict__ bg,
    const float* __restrict__ h, float* __restrict__ hnew,
    float* __restrict__ poolT)
{
    finpool_body(cp, bc, gp, bg, h, hnew, poolT, blockIdx.x);
}

__global__ void __launch_bounds__(224) cand_finpool2_k(
    const float* __restrict__ cpA, const float* __restrict__ bcA,
    const float* __restrict__ gpA, const float* __restrict__ bgA,
    const float* __restrict__ hA, float* __restrict__ hnA,
    float* __restrict__ poolA,
    const float* __restrict__ cpB, const float* __restrict__ bcB,
    const float* __restrict__ gpB, const float* __restrict__ bgB,
    const float* __restrict__ hB, float* __restrict__ hnB,
    float* __restrict__ poolB)
{
    if (blockIdx.y == 0)
        finpool_body(cpA, bcA, gpA, bgA, hA, hnA, poolA, blockIdx.x);
    else
        finpool_body(cpB, bcB, gpB, bgB, hB, hnB, poolB, blockIdx.x);
}

// ---------------- misc ----------------
__global__ void xT_k(const float* __restrict__ x, float* __restrict__ xT) {
    int idx = blockIdx.x * 256 + threadIdx.x;
    if (idx >= TT * K0PAD * BB) return;
    int b = idx & 15;
    int r = idx >> 4;
    int k = r % K0PAD, t = r / K0PAD;
    float v = 0.f;
    if (k < K0) v = x[((size_t)b * TT + t) * K0 + k];
    xT[idx] = v;
}

__global__ void zero_k(float* p, int n) {
    int i = blockIdx.x * 256 + threadIdx.x;
    if (i < n) p[i] = 0.f;
}

// ---------------- fc tail ----------------
__global__ void __launch_bounds__(256) fc1_k(const float* __restrict__ h2,
                                             const float* __restrict__ w,
                                             const float* __restrict__ bias,
                                             float* __restrict__ out1) {
    __shared__ float red[256];
    int j = blockIdx.x, tid = threadIdx.x;
    float acc[16];
#pragma unroll
    for (int b = 0; b < 16; b++) acc[b] = 0.f;
    for (int k = tid; k < KBIG; k += 256) {
        float wv = w[(size_t)j * KBIG + k];
#pragma unroll
        for (int b = 0; b < 16; b++)
            acc[b] += wv * fmaxf(h2[(size_t)b * KBIG + k], 0.f);
    }
    for (int b = 0; b < 16; b++) {
        red[tid] = acc[b];
        __syncthreads();
        for (int sft = 128; sft; sft >>= 1) {
            if (tid < sft) red[tid] += red[tid + sft];
            __syncthreads();
        }
        if (tid == 0) out1[b * 100 + j] = fmaxf(red[0] + bias[j], 0.f);
        __syncthreads();
    }
}

__global__ void fc2_k(const float* __restrict__ p, const float* __restrict__ w,
                      const float* __restrict__ bias, float* __restrict__ out) {
    int t = threadIdx.x;
    if (t < 160) {
        int b = t / 10, j = t - b * 10;
        float a = bias[j];
        for (int k = 0; k < 100; k++) a += p[b * 100 + k] * w[j * 100 + k];
        out[b * 10 + j] = a;
    }
}

// ---------------- host orchestration ----------------
extern "C" void kernel_launch(void* const* d_in, const int* in_sizes, int n_in,
                              void* d_out, int out_size) {
    const float* x     = (const float*)d_in[0];
    const float* Wg    = (const float*)d_in[1];
    const float* bg    = (const float*)d_in[2];
    const float* Wc    = (const float*)d_in[3];
    const float* bc    = (const float*)d_in[4];
    const float* bu_w0 = (const float*)d_in[5];
    const float* bu_b0 = (const float*)d_in[6];
    const float* bu_w1 = (const float*)d_in[7];
    const float* bu_b1 = (const float*)d_in[8];
    const float* bu_w2 = (const float*)d_in[9];
    const float* bu_b2 = (const float*)d_in[10];
    const float* td_w0 = (const float*)d_in[11];
    const float* td_b0 = (const float*)d_in[12];
    const float* td_w1 = (const float*)d_in[13];
    const float* td_b1 = (const float*)d_in[14];
    const float* fc1_w = (const float*)d_in[15];
    const float* fc1_b = (const float*)d_in[16];
    const float* fc2_w = (const float*)d_in[17];
    const float* fc2_b = (const float*)d_in[18];
    float* out = (float*)d_out;

    float *hbuf, *xT, *pH0, *pH1, *pH2, *bu, *bu0all, *td;
    float *part, *partB, *partB0, *gp, *cp, *gp0, *cp0, *fc1o;
    float *tdw0T, *tdw1T, *buw1T, *buw2T, *buw0T;
    cudaGetSymbolAddress((void**)&hbuf,   g_h);
    cudaGetSymbolAddress((void**)&xT,     g_xT);
    cudaGetSymbolAddress((void**)&pH0,    g_pH0);
    cudaGetSymbolAddress((void**)&pH1,    g_pH1);
    cudaGetSymbolAddress((void**)&pH2,    g_pH2);
    cudaGetSymbolAddress((void**)&bu,     g_bu);
    cudaGetSymbolAddress((void**)&bu0all, g_bu0all);
    cudaGetSymbolAddress((void**)&td,     g_td);
    cudaGetSymbolAddress((void**)&part,   g_part);
    cudaGetSymbolAddress((void**)&partB,  g_partB);
    cudaGetSymbolAddress((void**)&partB0, g_partB0);
    cudaGetSymbolAddress((void**)&gp,     g_gp);
    cudaGetSymbolAddress((void**)&cp,     g_cp);
    cudaGetSymbolAddress((void**)&gp0,    g_gp0);
    cudaGetSymbolAddress((void**)&cp0,    g_cp0);
    cudaGetSymbolAddress((void**)&fc1o,   g_fc1o);
    cudaGetSymbolAddress((void**)&tdw0T,  g_tdw0T);
    cudaGetSymbolAddress((void**)&tdw1T,  g_tdw1T);
    cudaGetSymbolAddress((void**)&buw1T,  g_buw1T);
    cudaGetSymbolAddress((void**)&buw2T,  g_buw2T);
    cudaGetSymbolAddress((void**)&buw0T,  g_buw0T);

    const int hTot = 3 * 2 * BB * HID * HW;
    zero_k<<<(hTot + 255) / 256, 256>>>(hbuf, hTot);
    xT_k<<<(TT * K0PAD * BB + 255) / 256, 256>>>(x, xT);

    const int tdGx = (NTD + 511) / 512, buGx = (NBU + 511) / 512;
    {
        dim3 tb(32, 8);
        trans2_k<<<dim3(KBIG / 32, NTD / 32, 2), tb>>>(td_w0, tdw0T,
                                                       td_w1, tdw1T, NTD);
        trans2_k<<<dim3(KBIG / 32, NBU / 32, 2), tb>>>(bu_w1, buw1T,
                                                       bu_w2, buw2T, NBU);
        trans_pad_k<<<dim3(K0PAD / 32, NBU / 32), tb>>>(bu_w0, buw0T, NBU);
    }
    // precompute ALL node0 bu projections (depend only on x)
    gemmB0all_k<<<dim3(buGx, TT * KS_B0), 256>>>(xT, buw0T, partB0);
    reduceB0all_k<<<(TT * 16 * NBU + 255) / 256, 256>>>(partB0, bu_b0, bu0all);

    int cur[3] = {0, 0, 0};
    const size_t HSZ = (size_t)BB * HID * HW;
    const size_t B0SZ = (size_t)16 * NBU;
    const float* WgN[3] = {Wg, Wg + 27648, Wg + 2 * 27648};
    const float* bgN[3] = {bg, bg + 64, bg + 128};
    const float* WcN[3] = {Wc, Wc + 13824, Wc + 2 * 13824};
    const float* bcN[3] = {bc, bc + 32, bc + 64};

    dim3 gateGrid(16, 16, 4), candGrid(16, 8, 4);
    dim3 gate2Grid(16, 16, 8), cand2Grid(16, 8, 8);
    dim3 fpGrid(512), fp2Grid(512, 2);
    const int buRed = (16 * NBU + 255) / 256;
    const int r2B = (16 * (NBU + NTD) + 255) / 256;
#define HPTR(n, p) (hbuf + ((size_t)(n) * 2 + (p)) * HSZ)

#define NODE0_NOTD(tt)                                                         \
    do {                                                                       \
        const float* b0 = bu0all + (size_t)(tt) * B0SZ;                        \
        gate_part_k<<<gateGrid, 224>>>(b0, HPTR(0, cur[0]), td, WgN[0],        \
                                       gp0, 0);                                \
        cand_part_k<<<candGrid, 224>>>(b0, HPTR(0, cur[0]), gp0, bgN[0],       \
                                       WcN[0], cp0);                           \
        cand_finpool_k<<<fpGrid, 224>>>(cp0, bcN[0], gp0, bgN[0],              \
                                        HPTR(0, cur[0]), HPTR(0, 1 - cur[0]),  \
                                        pH0);                                  \
        cur[0] ^= 1;                                                           \
    } while (0)

#define NODE1(tt)                                                              \
    do {                                                                       \
        int hastd = ((tt) >= 2);                                               \
        if (hastd) {                                                           \
            gemmT2_k<<<dim3(tdGx, KS_BU + KS_TD), 256>>>(                      \
                pH0, buw1T, partB, NBU, KS_BU, KBIG,                           \
                pH2, tdw1T, part, NTD, KS_TD, KBIG);                           \
            reduce2_k<<<r2B, 256>>>(partB, bu_b1, bu, NBU, KS_BU,              \
                                    part, td_b1, td, NTD, KS_TD);              \
        } else {                                                               \
            gemmT_k<<<dim3(buGx, KS_BU), 256>>>(pH0, buw1T, partB,             \
                                                NBU, KS_BU, KBIG);             \
            reduceN_k<<<buRed, 256>>>(partB, bu_b1, bu, NBU, KS_BU);           \
        }                                                                      \
        gate_part_k<<<gateGrid, 224>>>(bu, HPTR(1, cur[1]), td, WgN[1],        \
                                       gp, hastd);                             \
        cand_part_k<<<candGrid, 224>>>(bu, HPTR(1, cur[1]), gp, bgN[1],        \
                                       WcN[1], cp);                            \
        cand_finpool_k<<<fpGrid, 224>>>(cp, bcN[1], gp, bgN[1],                \
                                        HPTR(1, cur[1]), HPTR(1, 1 - cur[1]),  \
                                        pH1);                                  \
        cur[1] ^= 1;                                                           \
    } while (0)

#define NODE2()                                                                \
    do {                                                                       \
        gemmT_k<<<dim3(buGx, KS_BU), 256>>>(pH1, buw2T, partB,                 \
                                            NBU, KS_BU, KBIG);                 \
        reduceN_k<<<buRed, 256>>>(partB, bu_b2, bu, NBU, KS_BU);               \
        gate_part_k<<<gateGrid, 224>>>(bu, HPTR(2, cur[2]), td, WgN[2],        \
                                       gp, 0);                                 \
        cand_part_k<<<candGrid, 224>>>(bu, HPTR(2, cur[2]), gp, bgN[2],        \
                                       WcN[2], cp);                            \
        cand_finpool_k<<<fpGrid, 224>>>(cp, bcN[2], gp, bgN[2],                \
                                        HPTR(2, cur[2]), HPTR(2, 1 - cur[2]),  \
                                        pH2);                                  \
        cur[2] ^= 1;                                                           \
    } while (0)

    // ---- prologue: node0(0), node0(1), node1(1) ----
    NODE0_NOTD(0);
    NODE0_NOTD(1);
    NODE1(1);

    // ---- main loop: PAIR{node2(t), node0(t+1)} ; node1(t+1)  for t=1..6 ----
    for (int t = 1; t <= 6; t++) {
        // pH1 = pool(h1(t)) from NODE1's fused finpool serves bu2 AND td0
        gemmT2_k<<<dim3(tdGx, KS_BU + KS_TD), 256>>>(
            pH1, buw2T, partB, NBU, KS_BU, KBIG,     // node2 bu
            pH1, tdw0T, part, NTD, KS_TD, KBIG);     // node0 td
        reduce2_k<<<r2B, 256>>>(partB, bu_b2, bu, NBU, KS_BU,
                                part, td_b0, td, NTD, KS_TD);
        const float* b0 = bu0all + (size_t)(t + 1) * B0SZ;
        gate_part2_k<<<gate2Grid, 224>>>(bu, HPTR(2, cur[2]), WgN[2], gp,
                                         b0, HPTR(0, cur[0]), td, WgN[0], gp0);
        cand_part2_k<<<cand2Grid, 224>>>(bu, HPTR(2, cur[2]), gp, bgN[2],
                                         WcN[2], cp,
                                         b0, HPTR(0, cur[0]), gp0, bgN[0],
                                         WcN[0], cp0);
        cand_finpool2_k<<<fp2Grid, 224>>>(
            cp, bcN[2], gp, bgN[2], HPTR(2, cur[2]), HPTR(2, 1 - cur[2]), pH2,
            cp0, bcN[0], gp0, bgN[0], HPTR(0, cur[0]), HPTR(0, 1 - cur[0]), pH0);
        cur[2] ^= 1;
        cur[0] ^= 1;
        NODE1(t + 1);
    }

    // ---- epilogue: node2(7), node1(8), node2(8), node1(9), node2(9) ----
    NODE2();
    NODE1(8);
    NODE2();
    NODE1(9);
    NODE2();

    fc1_k<<<100, 256>>>(HPTR(2, cur[2]), fc1_w, fc1_b, fc1o);
    fc2_k<<<1, 192>>>(fc1o, fc2_w, fc2_b, out);
#undef NODE0_NOTD
#undef NODE1
#undef NODE2
#undef HPTR
}

// round 16
// speedup vs baseline: 2.4587x; 1.0400x over previous
#include <cuda_runtime.h>
#include <math.h>

// ---------------- problem constants ----------------
#define BB 16
#define TT 8
#define HW 196
#define HID 32
#define IND 16
#define KBIG 6272       // HID*HW
#define K0 588          // CIN*HW
#define K0PAD 640
#define NBU 3136        // IND*HW
#define NTD 9408        // (IND+HID)*HW
#define KS_TD 24
#define KS_BU 49
#define KS_B0 5
#define GSEG (16 * 64 * 196)
#define CSEG (16 * 32 * 196)

// ---------------- device scratch (no allocs allowed) ----------------
__device__ float g_h[3 * 2 * BB * HID * HW];   // hidden, double buffered
__device__ float g_xT[TT * K0PAD * BB];        // transposed+padded input slices
__device__ float g_pH0[KBIG * BB];
__device__ float g_pH1[KBIG * BB];
__device__ float g_pH2[KBIG * BB];
__device__ float g_bu[BB * NBU];
__device__ float g_bu1e[BB * NBU];             // epilogue shared bu1
__device__ float g_bu0all[TT * BB * NBU];
__device__ float g_td[BB * NTD];
__device__ float g_part[KS_TD * BB * NTD];
__device__ float g_partB[KS_BU * BB * NBU];
__device__ float g_partBe[KS_BU * BB * NBU];
__device__ float g_partB0[TT * KS_B0 * BB * NBU];
__device__ float g_gp[8 * GSEG];               // gate partials (8 ic-slices)
__device__ float g_cp[8 * CSEG];
__device__ float g_gp0[8 * GSEG];
__device__ float g_cp0[8 * CSEG];
__device__ float g_fc1o[BB * 100];
__device__ float g_tdw0T[(size_t)KBIG * NTD];
__device__ float g_tdw1T[(size_t)KBIG * NTD];
__device__ float g_buw1T[(size_t)KBIG * NBU];
__device__ float g_buw2T[(size_t)KBIG * NBU];
__device__ float g_buw0T[(size_t)K0PAD * NBU];

// ---------------- f32x2 helpers ----------------
__device__ __forceinline__ unsigned long long pack2(float v) {
    unsigned long long r;
    asm("mov.b64 %0, {%1, %1};" : "=l"(r) : "f"(v));
    return r;
}
__device__ __forceinline__ void fma2(unsigned long long& d, unsigned long long a,
                                     unsigned long long b) {
    asm("fma.rn.f32x2 %0, %1, %2, %0;" : "+l"(d) : "l"(a), "l"(b));
}
__device__ __forceinline__ float sigm(float a) { return 1.f / (1.f + expf(-a)); }

// ---------------- float4 transposes ----------------
__global__ void trans2_k(const float* __restrict__ Wa, float* __restrict__ WTa,
                         const float* __restrict__ Wb, float* __restrict__ WTb,
                         int Nout) {
    __shared__ float t[32][33];
    const float* W  = blockIdx.z ? Wb  : Wa;
    float*       WT = blockIdx.z ? WTb : WTa;
    const int kb = blockIdx.x * 32, nb = blockIdx.y * 32;
    const int tid = threadIdx.x;                   // 256
    {
        int n = tid >> 3, q = tid & 7;
        float4 v = *(const float4*)(W + (size_t)(nb + n) * KBIG + kb + q * 4);
        t[q * 4 + 0][n] = v.x; t[q * 4 + 1][n] = v.y;
        t[q * 4 + 2][n] = v.z; t[q * 4 + 3][n] = v.w;
    }
    __syncthreads();
    {
        int k = tid >> 3, q = tid & 7;
        float4 v = make_float4(t[k][q * 4], t[k][q * 4 + 1],
                               t[k][q * 4 + 2], t[k][q * 4 + 3]);
        *(float4*)(WT + (size_t)(kb + k) * Nout + nb + q * 4) = v;
    }
}

// padded: W (Nout x K0) -> WT (K0PAD x Nout); rows >= K0 zero. K0 = 4*147.
__global__ void trans_pad_k(const float* __restrict__ W, float* __restrict__ WT,
                            int Nout) {
    __shared__ float t[32][33];
    const int kb = blockIdx.x * 32, nb = blockIdx.y * 32;
    const int tid = threadIdx.x;
    {
        int n = tid >> 3, q = tid & 7;
        float4 v = make_float4(0.f, 0.f, 0.f, 0.f);
        if ((kb >> 2) + q < 147)
            v = *(const float4*)(W + (size_t)(nb + n) * K0 + kb + q * 4);
        t[q * 4 + 0][n] = v.x; t[q * 4 + 1][n] = v.y;
        t[q * 4 + 2][n] = v.z; t[q * 4 + 3][n] = v.w;
    }
    __syncthreads();
    {
        int k = tid >> 3, q = tid & 7;
        float4 v = make_float4(t[k][q * 4], t[k][q * 4 + 1],
                               t[k][q * 4 + 2], t[k][q * 4 + 3]);
        *(float4*)(WT + (size_t)(kb + k) * Nout + nb + q * 4) = v;
    }
}

// ================= gemmT core =================
__device__ __forceinline__ void gemmT_core(
    float* sa, const float* __restrict__ act, const float* __restrict__ WT,
    float* __restrict__ part, int Nout, int KS, int ks, int bx, int Kpad)
{
    const int tid = threadIdx.x;
    const int n0raw = bx * 512 + tid * 2;
    const bool act_n = n0raw < Nout;
    const int n0 = act_n ? n0raw : (Nout - 2);
    const int slabs = Kpad >> 7;
    const int s0 = slabs * ks / KS, s1 = slabs * (ks + 1) / KS;
    const int ns = s1 - s0;
    const int kn = ns * 128;

    {
        const float4* src = (const float4*)act + (size_t)s0 * 512;
        for (int f = tid; f < ns * 512; f += 256) {
            float4 v = src[f];
            *(float4*)(&sa[(f >> 2) * 16 + (f & 3) * 4]) = v;
        }
    }

    unsigned long long acc[2][8];
#pragma unroll
    for (int n = 0; n < 2; n++)
#pragma unroll
        for (int p = 0; p < 8; p++) acc[n][p] = 0ull;

    const float* wp = WT + (size_t)(s0 * 128) * Nout + n0;
    float2 wb[2][8];
#pragma unroll
    for (int u = 0; u < 8; u++)
        wb[0][u] = *(const float2*)(wp + (size_t)u * Nout);

    __syncthreads();

    for (int k0 = 0; k0 < kn; k0 += 8) {
        const int cur = (k0 >> 3) & 1;
        const float* wpn = wp + (size_t)8 * Nout;
        if (k0 + 8 < kn) {
#pragma unroll
            for (int u = 0; u < 8; u++)
                wb[cur ^ 1][u] = *(const float2*)(wpn + (size_t)u * Nout);
        }
#pragma unroll
        for (int u = 0; u < 8; u++) {
            const ulonglong2* ap = (const ulonglong2*)(sa + (k0 + u) * 16);
            ulonglong2 u0 = ap[0], u1 = ap[1], u2 = ap[2], u3 = ap[3];
            unsigned long long av[8] = {u0.x, u0.y, u1.x, u1.y,
                                        u2.x, u2.y, u3.x, u3.y};
            unsigned long long w0 = pack2(wb[cur][u].x);
            unsigned long long w1 = pack2(wb[cur][u].y);
#pragma unroll
            for (int p = 0; p < 8; p++) fma2(acc[0][p], w0, av[p]);
#pragma unroll
            for (int p = 0; p < 8; p++) fma2(acc[1][p], w1, av[p]);
        }
        wp = wpn;
    }
    if (act_n) {
        float* op = part + (size_t)ks * 16 * Nout + n0;
#pragma unroll
        for (int b = 0; b < 16; b++) {
            unsigned long long v0 = acc[0][b >> 1], v1 = acc[1][b >> 1];
            float f0 = (b & 1) ? __uint_as_float((unsigned)(v0 >> 32))
                               : __uint_as_float((unsigned)v0);
            float f1 = (b & 1) ? __uint_as_float((unsigned)(v1 >> 32))
                               : __uint_as_float((unsigned)v1);
            op[(size_t)b * Nout + 0] = f0;
            op[(size_t)b * Nout + 1] = f1;
        }
    }
}

__global__ void __launch_bounds__(256) gemmT_k(
    const float* __restrict__ act, const float* __restrict__ WT,
    float* __restrict__ part, int Nout, int KS, int Kpad)
{
    __shared__ float sa[3 * 128 * 16];
    gemmT_core(sa, act, WT, part, Nout, KS, blockIdx.y, blockIdx.x, Kpad);
}

__global__ void __launch_bounds__(256) gemmT2_k(
    const float* __restrict__ actA, const float* __restrict__ WTA,
    float* __restrict__ partA, int NoutA, int KSA, int KpadA,
    const float* __restrict__ actB, const float* __restrict__ WTB,
    float* __restrict__ partB, int NoutB, int KSB, int KpadB)
{
    __shared__ float sa[3 * 128 * 16];
    const int y = blockIdx.y, bx = blockIdx.x;
    if (y < KSA) {
        if (bx * 512 >= NoutA) return;
        gemmT_core(sa, actA, WTA, partA, NoutA, KSA, y, bx, KpadA);
    } else {
        if (bx * 512 >= NoutB) return;
        gemmT_core(sa, actB, WTB, partB, NoutB, KSB, y - KSA, bx, KpadB);
    }
}

__global__ void __launch_bounds__(256) gemmB0all_k(
    const float* __restrict__ xT, const float* __restrict__ WT,
    float* __restrict__ partAll)
{
    __shared__ float sa[3 * 128 * 16];
    const int y = blockIdx.y;
    const int t = y / KS_B0, ks = y - t * KS_B0;
    gemmT_core(sa, xT + (size_t)t * K0PAD * 16, WT,
               partAll + (size_t)t * KS_B0 * 16 * NBU,
               NBU, KS_B0, ks, blockIdx.x, K0PAD);
}

// ---------------- reduces ----------------
__device__ __forceinline__ void red_one(const float* __restrict__ p,
                                        const float* __restrict__ bias,
                                        float* __restrict__ o, int N, int KS,
                                        int i) {
    int n = i % N;
    float a = bias[n];
    for (int ks = 0; ks < KS; ks++) a += p[(size_t)ks * 16 * N + i];
    o[i] = a;
}
__global__ void reduceN_k(const float* __restrict__ part,
                          const float* __restrict__ bias,
                          float* __restrict__ out, int Nout, int KS) {
    int i = blockIdx.x * 256 + threadIdx.x;
    if (i >= 16 * Nout) return;
    red_one(part, bias, out, Nout, KS, i);
}
__global__ void reduce2_k(const float* __restrict__ pA,
                          const float* __restrict__ bA, float* __restrict__ oA,
                          int NA, int KSA,
                          const float* __restrict__ pB,
                          const float* __restrict__ bB, float* __restrict__ oB,
                          int NB, int KSB) {
    int i = blockIdx.x * 256 + threadIdx.x;
    if (i < 16 * NA) { red_one(pA, bA, oA, NA, KSA, i); return; }
    int j = i - 16 * NA;
    if (j < 16 * NB) red_one(pB, bB, oB, NB, KSB, j);
}
__global__ void reduceB0all_k(const float* __restrict__ partAll,
                              const float* __restrict__ bias,
                              float* __restrict__ outAll) {
    int i = blockIdx.x * 256 + threadIdx.x;
    if (i >= TT * 16 * NBU) return;
    int t = i / (16 * NBU), j = i - t * 16 * NBU;
    red_one(partAll + (size_t)t * KS_B0 * 16 * NBU, bias,
            outAll + (size_t)t * 16 * NBU, NBU, KS_B0, j);
}

// ================= conv bodies: 2 pixels/thread, 6 ics/block (oct 0..7) ====
__device__ __forceinline__ void gate_body(
    float* sc, float* sw,
    const float* __restrict__ bu, const float* __restrict__ h,
    const float* __restrict__ td, const float* __restrict__ Wg,
    float* __restrict__ gp, int has_td, int b, int grp, int oct)
{
    const int ic0 = oct * 6;
    const int tid = threadIdx.x;                    // 128
    for (int i = tid; i < 6 * 256; i += 128) sc[i] = 0.f;
    for (int i = tid; i < 6 * 36; i += 128) {
        int lic = i / 36, rem = i - lic * 36, q = rem >> 2, o = rem & 3;
        sw[i] = Wg[(grp * 4 + o) * 432 + (ic0 + lic) * 9 + q];
    }
    __syncthreads();
    for (int i = tid; i < 6 * 196; i += 128) {
        int lic = i / 196, p = i - lic * 196, y = p / 14, x = p - y * 14;
        int ic = ic0 + lic;
        float v = (ic < IND) ? bu[((size_t)b * IND + ic) * 196 + p]
                             : h[((size_t)b * HID + (ic - IND)) * 196 + p];
        if (has_td) v += td[((size_t)b * 48 + ic) * 196 + p];
        sc[lic * 256 + (y + 1) * 16 + (x + 1)] = v;
    }
    __syncthreads();
    if (tid < 98) {
        const int y = tid / 7, xp = tid - y * 7, x0 = 2 * xp;
        float4 aA = make_float4(0.f, 0.f, 0.f, 0.f);
        float4 aB = make_float4(0.f, 0.f, 0.f, 0.f);
        const float* cbase = sc + y * 16 + x0;
        for (int lic = 0; lic < 6; ++lic) {
            const float* cb = cbase + lic * 256;
            float v[3][4];
#pragma unroll
            for (int dy = 0; dy < 3; dy++)
#pragma unroll
                for (int dx = 0; dx < 4; dx++) v[dy][dx] = cb[dy * 16 + dx];
            const float4* wq = (const float4*)(sw + lic * 36);
#pragma unroll
            for (int dy = 0; dy < 3; dy++)
#pragma unroll
                for (int dx = 0; dx < 3; dx++) {
                    float4 w = wq[dy * 3 + dx];
                    float vA = v[dy][dx], vB = v[dy][dx + 1];
                    aA.x += w.x * vA; aA.y += w.y * vA;
                    aA.z += w.z * vA; aA.w += w.w * vA;
                    aB.x += w.x * vB; aB.y += w.y * vB;
                    aB.z += w.z * vB; aB.w += w.w * vB;
                }
        }
        int pA = y * 14 + x0;
        float* o = gp + (size_t)oct * GSEG + ((size_t)b * 64 + grp * 4) * 196 + pA;
        o[0]   = aA.x; o[196] = aA.y; o[392] = aA.z; o[588] = aA.w;
        o[1]   = aB.x; o[197] = aB.y; o[393] = aB.z; o[589] = aB.w;
    }
}

__device__ __forceinline__ void cand_body(
    float* sc, float* sw,
    const float* __restrict__ bu, const float* __restrict__ h,
    const float* __restrict__ gp, const float* __restrict__ bg,
    const float* __restrict__ Wc, float* __restrict__ cp,
    int b, int grp, int oct)
{
    const int ic0 = oct * 6;
    const int tid = threadIdx.x;
    for (int i = tid; i < 6 * 256; i += 128) sc[i] = 0.f;
    for (int i = tid; i < 6 * 36; i += 128) {
        int lic = i / 36, rem = i - lic * 36, q = rem >> 2, o = rem & 3;
        sw[i] = Wc[(grp * 4 + o) * 432 + (ic0 + lic) * 9 + q];
    }
    __syncthreads();
    for (int i = tid; i < 6 * 196; i += 128) {
        int lic = i / 196, p = i - lic * 196, y = p / 14, x = p - y * 14;
        int ic = ic0 + lic;
        float v;
        if (ic < IND) {
            v = bu[((size_t)b * IND + ic) * 196 + p];
        } else {
            int c = ic - IND;
            size_t gi = ((size_t)b * 64 + c) * 196 + p;
            float s = bg[c];
#pragma unroll
            for (int q = 0; q < 8; q++) s += gp[gi + (size_t)q * GSEG];
            v = sigm(s) * h[((size_t)b * HID + c) * 196 + p];
        }
        sc[lic * 256 + (y + 1) * 16 + (x + 1)] = v;
    }
    __syncthreads();
    if (tid < 98) {
        const int y = tid / 7, xp = tid - y * 7, x0 = 2 * xp;
        float4 aA = make_float4(0.f, 0.f, 0.f, 0.f);
        float4 aB = make_float4(0.f, 0.f, 0.f, 0.f);
        const float* cbase = sc + y * 16 + x0;
        for (int lic = 0; lic < 6; ++lic) {
            const float* cb = cbase + lic * 256;
            float v[3][4];
#pragma unroll
            for (int dy = 0; dy < 3; dy++)
#pragma unroll
                for (int dx = 0; dx < 4; dx++) v[dy][dx] = cb[dy * 16 + dx];
            const float4* wq = (const float4*)(sw + lic * 36);
#pragma unroll
            for (int dy = 0; dy < 3; dy++)
#pragma unroll
                for (int dx = 0; dx < 3; dx++) {
                    float4 w = wq[dy * 3 + dx];
                    float vA = v[dy][dx], vB = v[dy][dx + 1];
                    aA.x += w.x * vA; aA.y += w.y * vA;
                    aA.z += w.z * vA; aA.w += w.w * vA;
                    aB.x += w.x * vB; aB.y += w.y * vB;
                    aB.z += w.z * vB; aB.w += w.w * vB;
                }
        }
        int pA = y * 14 + x0;
        float* o = cp + (size_t)oct * CSEG + ((size_t)b * 32 + grp * 4) * 196 + pA;
        o[0]   = aA.x; o[196] = aA.y; o[392] = aA.z; o[588] = aA.w;
        o[1]   = aB.x; o[197] = aB.y; o[393] = aB.z; o[589] = aB.w;
    }
}

// single-node conv kernels (128 threads)
__global__ void __launch_bounds__(128) gate_part_k(
    const float* __restrict__ bu, const float* __restrict__ h,
    const float* __restrict__ td, const float* __restrict__ Wg,
    float* __restrict__ gp, int has_td)
{
    __shared__ float sc[6 * 256];
    __shared__ float sw[6 * 36];
    gate_body(sc, sw, bu, h, td, Wg, gp, has_td,
              blockIdx.x, blockIdx.y, blockIdx.z);
}
__global__ void __launch_bounds__(128) cand_part_k(
    const float* __restrict__ bu, const float* __restrict__ h,
    const float* __restrict__ gp, const float* __restrict__ bg,
    const float* __restrict__ Wc, float* __restrict__ cp)
{
    __shared__ float sc[6 * 256];
    __shared__ float sw[6 * 36];
    cand_body(sc, sw, bu, h, gp, bg, Wc, cp, blockIdx.x, blockIdx.y, blockIdx.z);
}

// merged two-node conv kernels (PAIR: A=node2 no-td, B=node0 with td)
__global__ void __launch_bounds__(128) gate_part2_k(
    const float* __restrict__ buA, const float* __restrict__ hA,
    const float* __restrict__ WgA, float* __restrict__ gpA,
    const float* __restrict__ buB, const float* __restrict__ hB,
    const float* __restrict__ tdB, const float* __restrict__ WgB,
    float* __restrict__ gpB)
{
    __shared__ float sc[6 * 256];
    __shared__ float sw[6 * 36];
    const int z = blockIdx.z;
    if (z < 8)
        gate_body(sc, sw, buA, hA, tdB, WgA, gpA, 0, blockIdx.x, blockIdx.y, z);
    else
        gate_body(sc, sw, buB, hB, tdB, WgB, gpB, 1, blockIdx.x, blockIdx.y, z - 8);
}
__global__ void __launch_bounds__(128) cand_part2_k(
    const float* __restrict__ buA, const float* __restrict__ hA,
    const float* __restrict__ gpA, const float* __restrict__ bgA,
    const float* __restrict__ WcA, float* __restrict__ cpA,
    const float* __restrict__ buB, const float* __restrict__ hB,
    const float* __restrict__ gpB, const float* __restrict__ bgB,
    const float* __restrict__ WcB, float* __restrict__ cpB)
{
    __shared__ float sc[6 * 256];
    __shared__ float sw[6 * 36];
    const int z = blockIdx.z;
    if (z < 8)
        cand_body(sc, sw, buA, hA, gpA, bgA, WcA, cpA, blockIdx.x, blockIdx.y, z);
    else
        cand_body(sc, sw, buB, hB, gpB, bgB, WcB, cpB, blockIdx.x, blockIdx.y, z - 8);
}

// ================= fused GRU-update + maxpool + transpose =================
__device__ __forceinline__ void finpool_body(
    const float* __restrict__ cp, const float* __restrict__ bc,
    const float* __restrict__ gp, const float* __restrict__ bg,
    const float* __restrict__ h, float* __restrict__ hnew,
    float* __restrict__ poolT, int blk)
{
    __shared__ float sp[256];
    const int b = blk >> 5, oc = blk & 31;
    const int tid = threadIdx.x;
    for (int i = tid; i < 256; i += 224) sp[i] = -3.4e38f;
    __syncthreads();
    if (tid < 196) {
        const int p = tid, y = p / 14, x = p - y * 14;
        size_t i = ((size_t)b * 32 + oc) * 196 + p;
        float a = bc[oc];
#pragma unroll
        for (int q = 0; q < 8; q++) a += cp[i + (size_t)q * CSEG];
        size_t gi = ((size_t)b * 64 + 32 + oc) * 196 + p;
        float zs = bg[32 + oc];
#pragma unroll
        for (int q = 0; q < 8; q++) zs += gp[gi + (size_t)q * GSEG];
        float z = sigm(zs);
        float hn = (1.f - z) * h[i] + z * tanhf(a);
        hnew[i] = hn;
        sp[(y + 1) * 16 + (x + 1)] = hn;
    }
    __syncthreads();
    if (tid < 196) {
        const int p = tid, y = p / 14, x = p - y * 14;
        const float* c = sp + y * 16 + x;
        float m = c[0];
        m = fmaxf(m, c[1]);  m = fmaxf(m, c[2]);
        m = fmaxf(m, c[16]); m = fmaxf(m, c[17]); m = fmaxf(m, c[18]);
        m = fmaxf(m, c[32]); m = fmaxf(m, c[33]); m = fmaxf(m, c[34]);
        poolT[((size_t)oc * 196 + p) * 16 + b] = m;
    }
}

__global__ void __launch_bounds__(224) cand_finpool_k(
    const float* __restrict__ cp, const float* __restrict__ bc,
    const float* __restrict__ gp, const float* __restrict__ bg,
    const float* __restrict__ h, float* __restrict__ hnew,
    float* __restrict__ poolT)
{
    finpool_body(cp, bc, gp, bg, h, hnew, poolT, blockIdx.x);
}

__global__ void __launch_bounds__(224) cand_finpool2_k(
    const float* __restrict__ cpA, const float* __restrict__ bcA,
    const float* __restrict__ gpA, const float* __restrict__ bgA,
    const float* __restrict__ hA, float* __restrict__ hnA,
    float* __restrict__ poolA,
    const float* __restrict__ cpB, const float* __restrict__ bcB,
    const float* __restrict__ gpB, const float* __restrict__ bgB,
    const float* __restrict__ hB, float* __restrict__ hnB,
    float* __restrict__ poolB)
{
    if (blockIdx.y == 0)
        finpool_body(cpA, bcA, gpA, bgA, hA, hnA, poolA, blockIdx.x);
    else
        finpool_body(cpB, bcB, gpB, bgB, hB, hnB, poolB, blockIdx.x);
}

// ---------------- misc ----------------
__global__ void xT_k(const float* __restrict__ x, float* __restrict__ xT) {
    int idx = blockIdx.x * 256 + threadIdx.x;
    if (idx >= TT * K0PAD * BB) return;
    int b = idx & 15;
    int r = idx >> 4;
    int k = r % K0PAD, t = r / K0PAD;
    float v = 0.f;
    if (k < K0) v = x[((size_t)b * TT + t) * K0 + k];
    xT[idx] = v;
}

__global__ void zero_k(float* p, int n) {
    int i = blockIdx.x * 256 + threadIdx.x;
    if (i < n) p[i] = 0.f;
}

// ---------------- fc tail ----------------
__global__ void __launch_bounds__(256) fc1_k(const float* __restrict__ h2,
                                             const float* __restrict__ w,
                                             const float* __restrict__ bias,
                                             float* __restrict__ out1) {
    __shared__ float red[256];
    int j = blockIdx.x, tid = threadIdx.x;
    float acc[16];
#pragma unroll
    for (int b = 0; b < 16; b++) acc[b] = 0.f;
    for (int k = tid; k < KBIG; k += 256) {
        float wv = w[(size_t)j * KBIG + k];
#pragma unroll
        for (int b = 0; b < 16; b++)
            acc[b] += wv * fmaxf(h2[(size_t)b * KBIG + k], 0.f);
    }
    for (int b = 0; b < 16; b++) {
        red[tid] = acc[b];
        __syncthreads();
        for (int sft = 128; sft; sft >>= 1) {
            if (tid < sft) red[tid] += red[tid + sft];
            __syncthreads();
        }
        if (tid == 0) out1[b * 100 + j] = fmaxf(red[0] + bias[j], 0.f);
        __syncthreads();
    }
}

__global__ void fc2_k(const float* __restrict__ p, const float* __restrict__ w,
                      const float* __restrict__ bias, float* __restrict__ out) {
    int t = threadIdx.x;
    if (t < 160) {
        int b = t / 10, j = t - b * 10;
        float a = bias[j];
        for (int k = 0; k < 100; k++) a += p[b * 100 + k] * w[j * 100 + k];
        out[b * 10 + j] = a;
    }
}

// ---------------- host orchestration ----------------
extern "C" void kernel_launch(void* const* d_in, const int* in_sizes, int n_in,
                              void* d_out, int out_size) {
    const float* x     = (const float*)d_in[0];
    const float* Wg    = (const float*)d_in[1];
    const float* bg    = (const float*)d_in[2];
    const float* Wc    = (const float*)d_in[3];
    const float* bc    = (const float*)d_in[4];
    const float* bu_w0 = (const float*)d_in[5];
    const float* bu_b0 = (const float*)d_in[6];
    const float* bu_w1 = (const float*)d_in[7];
    const float* bu_b1 = (const float*)d_in[8];
    const float* bu_w2 = (const float*)d_in[9];
    const float* bu_b2 = (const float*)d_in[10];
    const float* td_w0 = (const float*)d_in[11];
    const float* td_b0 = (const float*)d_in[12];
    const float* td_w1 = (const float*)d_in[13];
    const float* td_b1 = (const float*)d_in[14];
    const float* fc1_w = (const float*)d_in[15];
    const float* fc1_b = (const float*)d_in[16];
    const float* fc2_w = (const float*)d_in[17];
    const float* fc2_b = (const float*)d_in[18];
    float* out = (float*)d_out;

    float *hbuf, *xT, *pH0, *pH1, *pH2, *bu, *bu1e, *bu0all, *td;
    float *part, *partB, *partBe, *partB0, *gp, *cp, *gp0, *cp0, *fc1o;
    float *tdw0T, *tdw1T, *buw1T, *buw2T, *buw0T;
    cudaGetSymbolAddress((void**)&hbuf,   g_h);
    cudaGetSymbolAddress((void**)&xT,     g_xT);
    cudaGetSymbolAddress((void**)&pH0,    g_pH0);
    cudaGetSymbolAddress((void**)&pH1,    g_pH1);
    cudaGetSymbolAddress((void**)&pH2,    g_pH2);
    cudaGetSymbolAddress((void**)&bu,     g_bu);
    cudaGetSymbolAddress((void**)&bu1e,   g_bu1e);
    cudaGetSymbolAddress((void**)&bu0all, g_bu0all);
    cudaGetSymbolAddress((void**)&td,     g_td);
    cudaGetSymbolAddress((void**)&part,   g_part);
    cudaGetSymbolAddress((void**)&partB,  g_partB);
    cudaGetSymbolAddress((void**)&partBe, g_partBe);
    cudaGetSymbolAddress((void**)&partB0, g_partB0);
    cudaGetSymbolAddress((void**)&gp,     g_gp);
    cudaGetSymbolAddress((void**)&cp,     g_cp);
    cudaGetSymbolAddress((void**)&gp0,    g_gp0);
    cudaGetSymbolAddress((void**)&cp0,    g_cp0);
    cudaGetSymbolAddress((void**)&fc1o,   g_fc1o);
    cudaGetSymbolAddress((void**)&tdw0T,  g_tdw0T);
    cudaGetSymbolAddress((void**)&tdw1T,  g_tdw1T);
    cudaGetSymbolAddress((void**)&buw1T,  g_buw1T);
    cudaGetSymbolAddress((void**)&buw2T,  g_buw2T);
    cudaGetSymbolAddress((void**)&buw0T,  g_buw0T);

    const int hTot = 3 * 2 * BB * HID * HW;
    zero_k<<<(hTot + 255) / 256, 256>>>(hbuf, hTot);
    xT_k<<<(TT * K0PAD * BB + 255) / 256, 256>>>(x, xT);

    const int tdGx = (NTD + 511) / 512, buGx = (NBU + 511) / 512;
    {
        trans2_k<<<dim3(KBIG / 32, NTD / 32, 2), 256>>>(td_w0, tdw0T,
                                                        td_w1, tdw1T, NTD);
        trans2_k<<<dim3(KBIG / 32, NBU / 32, 2), 256>>>(bu_w1, buw1T,
                                                        bu_w2, buw2T, NBU);
        trans_pad_k<<<dim3(K0PAD / 32, NBU / 32), 256>>>(bu_w0, buw0T, NBU);
    }
    gemmB0all_k<<<dim3(buGx, TT * KS_B0), 256>>>(xT, buw0T, partB0);
    reduceB0all_k<<<(TT * 16 * NBU + 255) / 256, 256>>>(partB0, bu_b0, bu0all);

    int cur[3] = {0, 0, 0};
    const size_t HSZ = (size_t)BB * HID * HW;
    const size_t B0SZ = (size_t)16 * NBU;
    const float* WgN[3] = {Wg, Wg + 27648, Wg + 2 * 27648};
    const float* bgN[3] = {bg, bg + 64, bg + 128};
    const float* WcN[3] = {Wc, Wc + 13824, Wc + 2 * 13824};
    const float* bcN[3] = {bc, bc + 32, bc + 64};

    dim3 gateGrid(16, 16, 8), candGrid(16, 8, 8);
    dim3 gate2Grid(16, 16, 16), cand2Grid(16, 8, 16);
    dim3 fpGrid(512), fp2Grid(512, 2);
    const int buRed = (16 * NBU + 255) / 256;
    const int tdRed = (16 * NTD + 255) / 256;
    const int r2B = (16 * (NBU + NTD) + 255) / 256;
    const int r2BB = (16 * (NBU + NBU) + 255) / 256;
#define HPTR(n, p) (hbuf + ((size_t)(n) * 2 + (p)) * HSZ)

#define NODE0_NOTD(tt)                                                         \
    do {                                                                       \
        const float* b0 = bu0all + (size_t)(tt) * B0SZ;                        \
        gate_part_k<<<gateGrid, 128>>>(b0, HPTR(0, cur[0]), td, WgN[0],        \
                                       gp0, 0);                                \
        cand_part_k<<<candGrid, 128>>>(b0, HPTR(0, cur[0]), gp0, bgN[0],       \
                                       WcN[0], cp0);                           \
        cand_finpool_k<<<fpGrid, 224>>>(cp0, bcN[0], gp0, bgN[0],              \
                                        HPTR(0, cur[0]), HPTR(0, 1 - cur[0]),  \
                                        pH0);                                  \
        cur[0] ^= 1;                                                           \
    } while (0)

#define NODE1(tt)                                                              \
    do {                                                                       \
        int hastd = ((tt) >= 2);                                               \
        if (hastd) {                                                           \
            gemmT2_k<<<dim3(tdGx, KS_BU + KS_TD), 256>>>(                      \
                pH0, buw1T, partB, NBU, KS_BU, KBIG,                           \
                pH2, tdw1T, part, NTD, KS_TD, KBIG);                           \
            reduce2_k<<<r2B, 256>>>(partB, bu_b1, bu, NBU, KS_BU,              \
                                    part, td_b1, td, NTD, KS_TD);              \
        } else {                                                               \
            gemmT_k<<<dim3(buGx, KS_BU), 256>>>(pH0, buw1T, partB,             \
                                                NBU, KS_BU, KBIG);             \
            reduceN_k<<<buRed, 256>>>(partB, bu_b1, bu, NBU, KS_BU);           \
        }                                                                      \
        gate_part_k<<<gateGrid, 128>>>(bu, HPTR(1, cur[1]), td, WgN[1],        \
                                       gp, hastd);                             \
        cand_part_k<<<candGrid, 128>>>(bu, HPTR(1, cur[1]), gp, bgN[1],        \
                                       WcN[1], cp);                            \
        cand_finpool_k<<<fpGrid, 224>>>(cp, bcN[1], gp, bgN[1],                \
                                        HPTR(1, cur[1]), HPTR(1, 1 - cur[1]),  \
                                        pH1);                                  \
        cur[1] ^= 1;                                                           \
    } while (0)

#define NODE2_CONV()                                                           \
    do {                                                                       \
        gate_part_k<<<gateGrid, 128>>>(bu, HPTR(2, cur[2]), td, WgN[2],        \
                                       gp, 0);                                 \
        cand_part_k<<<candGrid, 128>>>(bu, HPTR(2, cur[2]), gp, bgN[2],        \
                                       WcN[2], cp);                            \
        cand_finpool_k<<<fpGrid, 224>>>(cp, bcN[2], gp, bgN[2],                \
                                        HPTR(2, cur[2]), HPTR(2, 1 - cur[2]),  \
                                        pH2);                                  \
        cur[2] ^= 1;                                                           \
    } while (0)

#define NODE1_EPI_CONV()                                                       \
    do {                                                                       \
        gate_part_k<<<gateGrid, 128>>>(bu1e, HPTR(1, cur[1]), td, WgN[1],      \
                                       gp, 1);                                 \
        cand_part_k<<<candGrid, 128>>>(bu1e, HPTR(1, cur[1]), gp, bgN[1],      \
                                       WcN[1], cp);                            \
        cand_finpool_k<<<fpGrid, 224>>>(cp, bcN[1], gp, bgN[1],                \
                                        HPTR(1, cur[1]), HPTR(1, 1 - cur[1]),  \
                                        pH1);                                  \
        cur[1] ^= 1;                                                           \
    } while (0)

    // ---- prologue: node0(0), node0(1), node1(1) ----
    NODE0_NOTD(0);
    NODE0_NOTD(1);
    NODE1(1);

    // ---- main loop: PAIR{node2(t), node0(t+1)} ; node1(t+1)  for t=1..6 ----
    for (int t = 1; t <= 6; t++) {
        gemmT2_k<<<dim3(tdGx, KS_BU + KS_TD), 256>>>(
            pH1, buw2T, partB, NBU, KS_BU, KBIG,     // node2 bu
            pH1, tdw0T, part, NTD, KS_TD, KBIG);     // node0 td
        reduce2_k<<<r2B, 256>>>(partB, bu_b2, bu, NBU, KS_BU,
                                part, td_b0, td, NTD, KS_TD);
        const float* b0 = bu0all + (size_t)(t + 1) * B0SZ;
        gate_part2_k<<<gate2Grid, 128>>>(bu, HPTR(2, cur[2]), WgN[2], gp,
                                         b0, HPTR(0, cur[0]), td, WgN[0], gp0);
        cand_part2_k<<<cand2Grid, 128>>>(bu, HPTR(2, cur[2]), gp, bgN[2],
                                         WcN[2], cp,
                                         b0, HPTR(0, cur[0]), gp0, bgN[0],
                                         WcN[0], cp0);
        cand_finpool2_k<<<fp2Grid, 224>>>(
            cp, bcN[2], gp, bgN[2], HPTR(2, cur[2]), HPTR(2, 1 - cur[2]), pH2,
            cp0, bcN[0], gp0, bgN[0], HPTR(0, cur[0]), HPTR(0, 1 - cur[0]), pH0);
        cur[2] ^= 1;
        cur[0] ^= 1;
        NODE1(t + 1);
    }

    // ---- epilogue ----
    // E1: node2(7) bu + shared bu1e (h0 frozen after t=7) in one launch
    gemmT2_k<<<dim3(buGx, KS_BU + KS_BU), 256>>>(
        pH1, buw2T, partB, NBU, KS_BU, KBIG,
        pH0, buw1T, partBe, NBU, KS_BU, KBIG);
    reduce2_k<<<r2BB, 256>>>(partB, bu_b2, bu, NBU, KS_BU,
                             partBe, bu_b1, bu1e, NBU, KS_BU);
    NODE2_CONV();                                     // node2(7) -> pH2
    // E2: node1(8): td only
    gemmT_k<<<dim3(tdGx, KS_TD), 256>>>(pH2, tdw1T, part, NTD, KS_TD, KBIG);
    reduceN_k<<<tdRed, 256>>>(part, td_b1, td, NTD, KS_TD);
    NODE1_EPI_CONV();                                 // node1(8) -> pH1
    // E3: node2(8)
    gemmT_k<<<dim3(buGx, KS_BU), 256>>>(pH1, buw2T, partB, NBU, KS_BU, KBIG);
    reduceN_k<<<buRed, 256>>>(partB, bu_b2, bu, NBU, KS_BU);
    NODE2_CONV();                                     // node2(8) -> pH2
    // E4: node1(9): td only (bu1e reused)
    gemmT_k<<<dim3(tdGx, KS_TD), 256>>>(pH2, tdw1T, part, NTD, KS_TD, KBIG);
    reduceN_k<<<tdRed, 256>>>(part, td_b1, td, NTD, KS_TD);
    NODE1_EPI_CONV();                                 // node1(9) -> pH1
    // E5: node2(9)
    gemmT_k<<<dim3(buGx, KS_BU), 256>>>(pH1, buw2T, partB, NBU, KS_BU, KBIG);
    reduceN_k<<<buRed, 256>>>(partB, bu_b2, bu, NBU, KS_BU);
    NODE2_CONV();

    fc1_k<<<100, 256>>>(HPTR(2, cur[2]), fc1_w, fc1_b, fc1o);
    fc2_k<<<1, 192>>>(fc1o, fc2_w, fc2_b, out);
#undef NODE0_NOTD
#undef NODE1
#undef NODE2_CONV
#undef NODE1_EPI_CONV
#undef HPTR
}